// round 7
// baseline (speedup 1.0000x reference)
#include <cuda_runtime.h>
#include <cuda_bf16.h>
#include <cfloat>

#define NB    2
#define DIN   1024
#define DD    512
#define NPAD  10240
#define PADF  239
#define QKVD  1536
#define MLAND 256
#define BH    16

#define FB    1
#define FR    2
#define FACC  4
#define FAT   8
#define FTRB  16

// ----------------- device scratch -----------------
__device__ float g_h  [(size_t)NB*NPAD*DD];
__device__ float g_ln [(size_t)NB*NPAD*DD];
__device__ float g_qkv[(size_t)NB*NPAD*QKVD];
__device__ float g_ql [BH*MLAND*64];
__device__ float g_kl [BH*MLAND*64];
__device__ float g_s1 [(size_t)BH*NPAD*MLAND];
__device__ float g_s3 [(size_t)BH*MLAND*NPAD];
__device__ float g_a2 [BH*MLAND*MLAND];
__device__ float g_xz [BH*MLAND*MLAND];
__device__ float g_wb [BH*MLAND*MLAND];
__device__ float g_tb [BH*MLAND*MLAND];
__device__ float g_z0 [BH*MLAND*MLAND];
__device__ float g_z1 [BH*MLAND*MLAND];
__device__ float g_a3v[BH*MLAND*64];
__device__ float g_pz [BH*MLAND*64];
__device__ float g_mg [(size_t)NB*NPAD*DD];
__device__ float g_mx [2];

// ----------------- block reductions -----------------
__device__ __forceinline__ float bsum(float v, float* sh){
    int lane = threadIdx.x & 31, wid = threadIdx.x >> 5;
    #pragma unroll
    for (int o=16;o;o>>=1) v += __shfl_xor_sync(0xffffffffu, v, o);
    if (lane==0) sh[wid]=v;
    __syncthreads();
    if (wid==0){
        int nw = blockDim.x >> 5;
        float r = (lane<nw) ? sh[lane] : 0.f;
        #pragma unroll
        for (int o=16;o;o>>=1) r += __shfl_xor_sync(0xffffffffu, r, o);
        if (lane==0) sh[0]=r;
    }
    __syncthreads();
    float out = sh[0];
    __syncthreads();
    return out;
}
__device__ __forceinline__ float bmax(float v, float* sh){
    int lane = threadIdx.x & 31, wid = threadIdx.x >> 5;
    #pragma unroll
    for (int o=16;o;o>>=1) v = fmaxf(v, __shfl_xor_sync(0xffffffffu, v, o));
    if (lane==0) sh[wid]=v;
    __syncthreads();
    if (wid==0){
        int nw = blockDim.x >> 5;
        float r = (lane<nw) ? sh[lane] : -FLT_MAX;
        #pragma unroll
        for (int o=16;o;o>>=1) r = fmaxf(r, __shfl_xor_sync(0xffffffffu, r, o));
        if (lane==0) sh[0]=r;
    }
    __syncthreads();
    float out = sh[0];
    __syncthreads();
    return out;
}

// ----------------- generic batched GEMM -----------------
// C = alpha*A@op(B) with runtime flags; batch offset = (bz/nh)*s1 + (bz%nh)*s2
// optional dual output C2 = dval*I - alpha*acc (global indices on the diagonal)
template<int BM,int BN,int BK,int TM,int TN>
__global__ void __launch_bounds__((BM/TM)*(BN/TN))
gemm_k(const float* __restrict__ A, const float* __restrict__ Bp,
       float* C, float* C2, const float* __restrict__ bias,
       int M,int N,int K,int lda,int ldb,int ldc,
       long sA1,long sA2,long sB1,long sB2,long sC1,long sC2,
       int nh,float alpha,float dval,int nTN,int kSplit,int flags)
{
    constexpr int THREADS=(BM/TM)*(BN/TN);
    __shared__ float As[BK][BM];
    __shared__ float Bs[BK][BN+1];
    int bz=blockIdx.z;
    A  += (long)(bz/nh)*sA1 + (long)(bz%nh)*sA2;
    Bp += (long)(bz/nh)*sB1 + (long)(bz%nh)*sB2;
    long offC = (long)(bz/nh)*sC1 + (long)(bz%nh)*sC2;
    int kIdx=blockIdx.x/nTN;
    int col0=(blockIdx.x%nTN)*BN;
    int row0=blockIdx.y*BM;
    int kChunk=(K+kSplit-1)/kSplit;
    int k0=kIdx*kChunk, k1=min(K,k0+kChunk);
    int tid=threadIdx.x;
    int tm=tid/(BN/TN), tn=tid%(BN/TN);
    bool trb = (flags & FTRB) != 0;
    float acc[TM][TN] = {};
    for (int kk=k0; kk<k1; kk+=BK){
        #pragma unroll
        for (int it=0; it<BM*BK/THREADS; it++){
            int i=tid+it*THREADS;
            int m=i/BK, k=i%BK;
            int gm=row0+m, gk=kk+k;
            As[k][m] = (gm<M && gk<k1) ? A[(long)gm*lda+gk] : 0.f;
        }
        #pragma unroll
        for (int it=0; it<BK*BN/THREADS; it++){
            int i=tid+it*THREADS;
            int k,n;
            if (trb){ n=i/BK; k=i%BK; } else { k=i/BN; n=i%BN; }
            int gk=kk+k, gn=col0+n;
            float v=0.f;
            if (gk<k1 && gn<N) v = trb ? Bp[(long)gn*ldb+gk] : Bp[(long)gk*ldb+gn];
            Bs[k][n]=v;
        }
        __syncthreads();
        #pragma unroll
        for (int k=0;k<BK;k++){
            float ra[TM], rb[TN];
            #pragma unroll
            for (int i=0;i<TM;i++) ra[i]=As[k][tm*TM+i];
            #pragma unroll
            for (int j=0;j<TN;j++) rb[j]=Bs[k][tn*TN+j];
            #pragma unroll
            for (int i=0;i<TM;i++)
                #pragma unroll
                for (int j=0;j<TN;j++) acc[i][j] += ra[i]*rb[j];
        }
        __syncthreads();
    }
    #pragma unroll
    for (int i=0;i<TM;i++){
        int gm=row0+tm*TM+i; if (gm>=M) continue;
        #pragma unroll
        for (int j=0;j<TN;j++){
            int gn=col0+tn*TN+j; if (gn>=N) continue;
            float v = acc[i][j]*alpha;
            if (flags&FB) v += bias[gn];
            long idx = offC + (long)gm*ldc + gn;
            if (C2) C2[idx] = ((gm==gn)?dval:0.f) - v;
            if (C){
                if (flags&FAT) atomicAdd(&C[idx], v);
                else {
                    float o = v;
                    if (flags&FACC) o += C[idx];
                    if (flags&FR)   o = fmaxf(o, 0.f);
                    C[idx] = o;
                }
            }
        }
    }
}

static void gemm128(const float*A,const float*B,float*C,float*C2,const float*bias,
    int M,int N,int K,int lda,int ldb,int ldc,
    long a1,long a2,long b1,long b2,long c1,long c2,int nh,int batch,
    float alpha,float dval,int kSplit,int flags)
{
    int nTN=(N+127)/128, nTM=(M+127)/128;
    dim3 g(nTN*kSplit, nTM, batch);
    gemm_k<128,128,8,8,8><<<g,256>>>(A,B,C,C2,bias,M,N,K,lda,ldb,ldc,
        a1,a2,b1,b2,c1,c2,nh,alpha,dval,nTN,kSplit,flags);
}
static void gemm64(const float*A,const float*B,float*C,float*C2,const float*bias,
    int M,int N,int K,int lda,int ldb,int ldc,
    long a1,long a2,long b1,long b2,long c1,long c2,int nh,int batch,
    float alpha,float dval,int kSplit,int flags)
{
    int nTN=(N+63)/64, nTM=(M+63)/64;
    dim3 g(nTN*kSplit, nTM, batch);
    gemm_k<64,64,16,4,4><<<g,256>>>(A,B,C,C2,bias,M,N,K,lda,ldb,ldc,
        a1,a2,b1,b2,c1,c2,nh,alpha,dval,nTN,kSplit,flags);
}

// ----------------- elementwise / reduction kernels -----------------
__global__ void set_cls(float* h, const float* __restrict__ cls){
    h[((size_t)blockIdx.x*NPAD + PADF)*DD + threadIdx.x] = cls[threadIdx.x];
}

__global__ void ln_k(const float* __restrict__ h, float* __restrict__ o,
                     const float* __restrict__ g, const float* __restrict__ b){
    __shared__ float sh[32];
    size_t row = blockIdx.x;
    int t = (int)(row % NPAD);
    float* op = o + row*(size_t)DD;
    int tx = threadIdx.x;
    if (t < PADF){ op[tx]=0.f; op[tx+256]=0.f; return; }
    const float* p = h + row*(size_t)DD;
    float x0=p[tx], x1=p[tx+256];
    float mu  = bsum(x0+x1, sh) * (1.f/512.f);
    float d0=x0-mu, d1=x1-mu;
    float var = bsum(d0*d0+d1*d1, sh) * (1.f/512.f);
    float rs = rsqrtf(var + 1e-5f);
    op[tx]     = d0*rs*g[tx]     + b[tx];
    op[tx+256] = d1*rs*g[tx+256] + b[tx+256];
}

__global__ void lnf_k(const float* __restrict__ h, float* __restrict__ o,
                      const float* __restrict__ g, const float* __restrict__ b){
    __shared__ float sh[32];
    const float* p = h + ((size_t)blockIdx.x*NPAD + PADF)*DD;
    int tx = threadIdx.x;
    float x0=p[tx], x1=p[tx+256];
    float mu  = bsum(x0+x1, sh) * (1.f/512.f);
    float d0=x0-mu, d1=x1-mu;
    float var = bsum(d0*d0+d1*d1, sh) * (1.f/512.f);
    float rs = rsqrtf(var + 1e-5f);
    o[blockIdx.x*DD+tx]     = d0*rs*g[tx]     + b[tx];
    o[blockIdx.x*DD+tx+256] = d1*rs*g[tx+256] + b[tx+256];
}

__global__ void landmarks_k(const float* __restrict__ qkv,
                            float* __restrict__ ql, float* __restrict__ kl){
    int bz=blockIdx.x, m=blockIdx.y, d=threadIdx.x;
    int b=bz>>3, hh=bz&7;
    const float* base = qkv + ((size_t)b*NPAD + (size_t)m*40)*QKVD + hh*64 + d;
    float sq=0.f, sk=0.f;
    #pragma unroll 8
    for (int j=0;j<40;j++){ sq += base[(size_t)j*QKVD]; sk += base[(size_t)j*QKVD+512]; }
    ql[((size_t)bz*MLAND+m)*64+d] = sq*0.003125f;  // (1/40)*DH^-0.5
    kl[((size_t)bz*MLAND+m)*64+d] = sk*0.025f;     // 1/40
}

__global__ void softmax256(float* __restrict__ X){
    __shared__ float sh[32];
    float* p = X + (size_t)blockIdx.x*256;
    float v = p[threadIdx.x];
    float m = bmax(v, sh);
    float e = __expf(v - m);
    float s = bsum(e, sh);
    p[threadIdx.x] = e / s;
}

__global__ void softmaxN(float* __restrict__ X){
    __shared__ float sh[32];
    float* p = X + (size_t)blockIdx.x*NPAD;
    float m = -FLT_MAX;
    for (int i=threadIdx.x;i<NPAD;i+=256) m = fmaxf(m, p[i]);
    m = bmax(m, sh);
    float s = 0.f;
    for (int i=threadIdx.x;i<NPAD;i+=256) s += __expf(p[i]-m);
    s = bsum(s, sh);
    float inv = 1.f/s;
    for (int i=threadIdx.x;i<NPAD;i+=256) p[i] = __expf(p[i]-m)*inv;
}

__global__ void zerok(float* p, int n){
    int i = blockIdx.x*256 + threadIdx.x;
    if (i<n) p[i]=0.f;
}

__global__ void crmax_k(const float* __restrict__ a2, float* mx){
    __shared__ float sh[32];
    const float* p = a2 + (size_t)blockIdx.x*65536;
    int t = threadIdx.x;
    float cs=0.f, rs=0.f;
    for (int m=0;m<256;m++){ cs += p[m*256+t]; rs += p[t*256+m]; }
    float mc = bmax(cs, sh);
    float mr = bmax(rs, sh);
    if (t==0){
        atomicMax((int*)&mx[0], __float_as_int(mc));
        atomicMax((int*)&mx[1], __float_as_int(mr));
    }
}

__global__ void ztrans_k(const float* __restrict__ a2, float* __restrict__ z,
                         const float* __restrict__ mx){
    __shared__ float tile[32][33];
    int bz=blockIdx.x;
    const float* p = a2 + (size_t)bz*65536;
    float* q = z + (size_t)bz*65536;
    int i0=blockIdx.y*32, j0=blockIdx.z*32;
    tile[threadIdx.y][threadIdx.x] = p[(j0+threadIdx.y)*256 + i0+threadIdx.x];
    __syncthreads();
    float inv = 1.f/(mx[0]*mx[1]);
    q[(i0+threadIdx.y)*256 + j0+threadIdx.x] = tile[threadIdx.x][threadIdx.y]*inv;
}

__global__ void resconv_k(const float* __restrict__ qkv, const float* __restrict__ rw,
                          float* __restrict__ mg){
    __shared__ float w[33];
    int bz=blockIdx.y; int b=bz>>3, hh=bz&7;
    if (threadIdx.y==0 && threadIdx.x<33) w[threadIdx.x]=rw[hh*33+threadIdx.x];
    __syncthreads();
    int d=threadIdx.x;
    int t=blockIdx.x*8+threadIdx.y;
    const float* vb = qkv + (size_t)b*NPAD*QKVD + 1024 + hh*64 + d;
    float acc=0.f;
    #pragma unroll
    for (int j=0;j<33;j++){
        int ts=t+j-16;
        if (ts>=0 && ts<NPAD) acc += vb[(size_t)ts*QKVD]*w[j];
    }
    mg[((size_t)b*NPAD+t)*DD + hh*64 + d] += acc;
}

// token layout -> planar (B,512,100,100)
__global__ void t2p_k(const float* __restrict__ h, float* __restrict__ pl){
    __shared__ float tile[32][33];
    int b=blockIdx.x, t0=blockIdx.y*32, c0=blockIdx.z*32;
    int t=t0+threadIdx.y, c=c0+threadIdx.x;
    if (t<10000) tile[threadIdx.y][threadIdx.x] = h[((size_t)b*NPAD+PADF+1+t)*DD + c];
    __syncthreads();
    int ch=c0+threadIdx.y, tt=t0+threadIdx.x;
    if (tt<10000) pl[((size_t)b*DD+ch)*10000 + tt] = tile[threadIdx.x][threadIdx.y];
}
__global__ void p2h_k(const float* __restrict__ pl, float* __restrict__ h){
    __shared__ float tile[32][33];
    int b=blockIdx.x, t0=blockIdx.y*32, c0=blockIdx.z*32;
    int ch=c0+threadIdx.y, tt=t0+threadIdx.x;
    if (tt<10000) tile[threadIdx.y][threadIdx.x] = pl[((size_t)b*DD+ch)*10000 + tt];
    __syncthreads();
    int t=t0+threadIdx.y, c=c0+threadIdx.x;
    if (t<10000) h[((size_t)b*NPAD+PADF+1+t)*DD + c] = tile[threadIdx.x][threadIdx.y];
}

__global__ void ppeg_conv_k(const float* __restrict__ pl, float* __restrict__ po,
    const float* __restrict__ w7, const float* __restrict__ b7,
    const float* __restrict__ w5, const float* __restrict__ b5,
    const float* __restrict__ w3, const float* __restrict__ b3){
    __shared__ float sw[86];
    int plane=blockIdx.x; int ch=plane&511;
    int tx=threadIdx.x;
    if      (tx<49) sw[tx]=w7[ch*49+tx];
    else if (tx<74) sw[tx]=w5[ch*25+tx-49];
    else if (tx<83) sw[tx]=w3[ch*9+tx-74];
    else if (tx==83) sw[83]=b7[ch];
    else if (tx==84) sw[84]=b5[ch];
    else if (tx==85) sw[85]=b3[ch];
    __syncthreads();
    int px=blockIdx.y*256+tx;
    if (px>=10000) return;
    int r=px/100, c=px%100;
    const float* in = pl + (size_t)plane*10000;
    float acc = in[px] + sw[83] + sw[84] + sw[85];
    #pragma unroll
    for (int kr=0;kr<7;kr++){
        int rr=r+kr-3; if (rr<0||rr>=100) continue;
        #pragma unroll
        for (int kc=0;kc<7;kc++){
            int cc=c+kc-3; if (cc<0||cc>=100) continue;
            acc += in[rr*100+cc]*sw[kr*7+kc];
        }
    }
    #pragma unroll
    for (int kr=0;kr<5;kr++){
        int rr=r+kr-2; if (rr<0||rr>=100) continue;
        #pragma unroll
        for (int kc=0;kc<5;kc++){
            int cc=c+kc-2; if (cc<0||cc>=100) continue;
            acc += in[rr*100+cc]*sw[49+kr*5+kc];
        }
    }
    #pragma unroll
    for (int kr=0;kr<3;kr++){
        int rr=r+kr-1; if (rr<0||rr>=100) continue;
        #pragma unroll
        for (int kc=0;kc<3;kc++){
            int cc=c+kc-1; if (cc<0||cc>=100) continue;
            acc += in[rr*100+cc]*sw[74+kr*3+kc];
        }
    }
    po[(size_t)plane*10000+px]=acc;
}

__global__ void head_k(const float* __restrict__ cls, const float* __restrict__ w2,
                       const float* __restrict__ b2, float* out, int osz){
    __shared__ float sh[64];
    int b=blockIdx.x;
    float a0=0.f, a1=0.f;
    for (int d=threadIdx.x; d<512; d+=256){
        float x = cls[b*512+d];
        a0 += x*w2[d*2+0]; a1 += x*w2[d*2+1];
    }
    #pragma unroll
    for (int o=16;o;o>>=1){
        a0 += __shfl_xor_sync(0xffffffffu,a0,o);
        a1 += __shfl_xor_sync(0xffffffffu,a1,o);
    }
    int lane=threadIdx.x&31, wid=threadIdx.x>>5;
    if (lane==0){ sh[wid]=a0; sh[wid+32]=a1; }
    __syncthreads();
    if (threadIdx.x==0){
        float l0=b2[0], l1=b2[1];
        for (int w=0;w<8;w++){ l0+=sh[w]; l1+=sh[w+32]; }
        float m=fmaxf(l0,l1);
        float e0=expf(l0-m), e1=expf(l1-m), s=e0+e1;
        if (b*2+1   < osz){ out[b*2]=l0;      out[b*2+1]=l1; }
        if (4+b*2+1 < osz){ out[4+b*2]=e0/s;  out[4+b*2+1]=e1/s; }
        if (8+b     < osz){ out[8+b] = (l1>l0)?1.f:0.f; }
    }
}

// ----------------- driver -----------------
extern "C" void kernel_launch(void* const* d_in, const int* in_sizes, int n_in,
                              void* d_out, int out_size){
    const float* x    =(const float*)d_in[0];
    const float* wfc1 =(const float*)d_in[1];
    const float* bfc1 =(const float*)d_in[2];
    const float* clst =(const float*)d_in[3];
    const float* lng[2]={(const float*)d_in[4],(const float*)d_in[10]};
    const float* lnb[2]={(const float*)d_in[5],(const float*)d_in[11]};
    const float* qkvw[2]={(const float*)d_in[6],(const float*)d_in[12]};
    const float* outw[2]={(const float*)d_in[7],(const float*)d_in[13]};
    const float* outb[2]={(const float*)d_in[8],(const float*)d_in[14]};
    const float* resw[2]={(const float*)d_in[9],(const float*)d_in[15]};
    const float* pw7=(const float*)d_in[16]; const float* pb7=(const float*)d_in[17];
    const float* pw5=(const float*)d_in[18]; const float* pb5=(const float*)d_in[19];
    const float* pw3=(const float*)d_in[20]; const float* pb3=(const float*)d_in[21];
    const float* lnfg=(const float*)d_in[22]; const float* lnfb=(const float*)d_in[23];
    const float* wfc2=(const float*)d_in[24]; const float* bfc2=(const float*)d_in[25];

    float *h,*ln,*qkv,*ql,*kl,*s1,*s3,*a2,*xz,*wb,*tb,*z0,*z1,*a3v,*pz,*mg,*mx;
    cudaGetSymbolAddress((void**)&h,  g_h);
    cudaGetSymbolAddress((void**)&ln, g_ln);
    cudaGetSymbolAddress((void**)&qkv,g_qkv);
    cudaGetSymbolAddress((void**)&ql, g_ql);
    cudaGetSymbolAddress((void**)&kl, g_kl);
    cudaGetSymbolAddress((void**)&s1, g_s1);
    cudaGetSymbolAddress((void**)&s3, g_s3);
    cudaGetSymbolAddress((void**)&a2, g_a2);
    cudaGetSymbolAddress((void**)&xz, g_xz);
    cudaGetSymbolAddress((void**)&wb, g_wb);
    cudaGetSymbolAddress((void**)&tb, g_tb);
    cudaGetSymbolAddress((void**)&z0, g_z0);
    cudaGetSymbolAddress((void**)&z1, g_z1);
    cudaGetSymbolAddress((void**)&a3v,g_a3v);
    cudaGetSymbolAddress((void**)&pz, g_pz);
    cudaGetSymbolAddress((void**)&mg, g_mg);
    cudaGetSymbolAddress((void**)&mx, g_mx);

    // fc1: h[b, PADF+1+t, :] = relu(x @ w_fc1 + b_fc1)
    gemm128(x, wfc1, h+(size_t)(PADF+1)*DD, nullptr, bfc1,
            10000, 512, 1024, 1024, 512, 512,
            (long)10000*1024, 0, 0, 0, (long)NPAD*DD, 0,
            1, NB, 1.f, 0.f, 1, FB|FR);
    set_cls<<<NB,512>>>(h, clst);

    for (int L=0; L<2; L++){
        ln_k<<<NB*NPAD,256>>>(h, ln, lng[L], lnb[L]);
        // qkv: (2*10240, 512) @ (512, 1536)
        gemm128(ln, qkvw[L], qkv, nullptr, nullptr,
                NB*NPAD, QKVD, 512, 512, QKVD, QKVD,
                0,0, 0,0, 0,0, 1, 1, 1.f, 0.f, 1, 0);
        landmarks_k<<<dim3(BH,MLAND),64>>>(qkv, ql, kl);
        // s2 = ql @ kl^T -> a2 (batched 16, 256x256x64)
        gemm64(ql, kl, a2, nullptr, nullptr,
               256, 256, 64, 64, 64, 256,
               (long)256*64, 0, (long)256*64, 0, (long)65536, 0,
               1, BH, 1.f, 0.f, 1, FTRB);
        softmax256<<<BH*256,256>>>(a2);
        // s1 = q @ kl^T (alpha = DH^-0.5)
        gemm64(qkv, kl, s1, nullptr, nullptr,
               NPAD, 256, 64, QKVD, 64, 256,
               (long)NPAD*QKVD, 64, 8L*256*64, (long)256*64,
               8L*NPAD*256, (long)NPAD*256,
               8, BH, 0.125f, 0.f, 1, FTRB);
        softmax256<<<BH*NPAD,256>>>(s1);
        // s3 = ql @ k^T
        gemm64(ql, qkv+512, s3, nullptr, nullptr,
               256, NPAD, 64, 64, QKVD, NPAD,
               8L*256*64, (long)256*64, (long)NPAD*QKVD, 64,
               8L*256*NPAD, (long)256*NPAD,
               8, BH, 1.f, 0.f, 1, FTRB);
        softmaxN<<<BH*256,256>>>(s3);
        // Moore-Penrose pinv of a2
        zerok<<<1,256>>>(mx, 2);
        crmax_k<<<BH,256>>>(a2, mx);
        ztrans_k<<<dim3(BH,8,8),dim3(32,32)>>>(a2, z0, mx);
        float* cur=z0; float* nxt=z1;
        for (int it=0; it<6; it++){
            gemm64(a2, cur, xz, wb, nullptr, 256,256,256, 256,256,256,
                   65536,0, 65536,0, 65536,0, 1, BH, 1.f, 7.f, 1, 0);
            gemm64(xz, wb, nullptr, tb, nullptr, 256,256,256, 256,256,256,
                   65536,0, 65536,0, 65536,0, 1, BH, 1.f, 15.f, 1, 0);
            gemm64(xz, tb, nullptr, wb, nullptr, 256,256,256, 256,256,256,
                   65536,0, 65536,0, 65536,0, 1, BH, 1.f, 13.f, 1, 0);
            gemm64(cur, wb, nxt, nullptr, nullptr, 256,256,256, 256,256,256,
                   65536,0, 65536,0, 65536,0, 1, BH, 0.25f, 0.f, 1, 0);
            float* t=cur; cur=nxt; nxt=t;
        }
        // a3v = a3 @ v (split-K=16, atomic)
        zerok<<<(BH*256*64+255)/256,256>>>(a3v, BH*256*64);
        gemm64(s3, qkv+1024, a3v, nullptr, nullptr,
               256, 64, NPAD, NPAD, QKVD, 64,
               8L*256*NPAD, (long)256*NPAD, (long)NPAD*QKVD, 64,
               8L*16384, 16384L,
               8, BH, 1.f, 0.f, 16, FAT);
        // pz = pinv(a2) @ a3v
        gemm64(cur, a3v, pz, nullptr, nullptr,
               256, 64, 256, 256, 64, 64,
               65536,0, 16384,0, 16384,0, 1, BH, 1.f, 0.f, 1, 0);
        // out = a1 @ pz -> mg in (B, NPAD, 512) head-concat layout
        gemm64(s1, pz, mg, nullptr, nullptr,
               NPAD, 64, 256, 256, 64, 512,
               8L*NPAD*256, (long)NPAD*256, 8L*16384, 16384L,
               (long)NPAD*DD, 64,
               8, BH, 1.f, 0.f, 1, 0);
        // += depthwise 33-tap residual conv on v
        resconv_k<<<dim3(NPAD/8,BH),dim3(64,8)>>>(qkv, resw[L], mg);
        // h[rows PADF..] += mg @ w_out + b_out
        gemm128(mg+(size_t)PADF*DD, outw[L], h+(size_t)PADF*DD, nullptr, outb[L],
                10001, 512, 512, 512, 512, 512,
                (long)NPAD*DD, 0, 0, 0, (long)NPAD*DD, 0,
                1, NB, 1.f, 0.f, 1, FB|FACC);
        if (L==0){
            t2p_k<<<dim3(NB,313,16),dim3(32,32)>>>(h, s1);
            ppeg_conv_k<<<dim3(NB*512,40),256>>>(s1, s3, pw7,pb7, pw5,pb5, pw3,pb3);
            p2h_k<<<dim3(NB,313,16),dim3(32,32)>>>(s3, h);
        }
    }
    // final LN on cls rows, then 2-class head (logits, probs, argmax)
    lnf_k<<<NB,256>>>(h, a2, lnfg, lnfb);
    head_k<<<NB,256>>>(a2, wfc2, bfc2, (float*)d_out, out_size);
}

// round 8
// speedup vs baseline: 1.1707x; 1.1707x over previous
#include <cuda_runtime.h>
#include <cuda_bf16.h>
#include <cfloat>

#define NB    2
#define DIN   1024
#define DD    512
#define NPAD  10240
#define PADF  239
#define QKVD  1536
#define MLAND 256
#define BH    16

#define FB    1
#define FR    2
#define FACC  4
#define FAT   8
#define FTRB  16

// ----------------- device scratch -----------------
__device__ float g_h  [(size_t)NB*NPAD*DD];
__device__ float g_ln [(size_t)NB*NPAD*DD];
__device__ float g_qkv[(size_t)NB*NPAD*QKVD];
__device__ float g_ql [BH*MLAND*64];
__device__ float g_kl [BH*MLAND*64];
__device__ float g_s1 [(size_t)BH*NPAD*MLAND];   // reused: F2 partials, PPEG planar
__device__ float g_s3 [(size_t)BH*MLAND*NPAD];   // reused: PPEG planar
__device__ float g_a2 [BH*MLAND*MLAND];
__device__ float g_xz [BH*MLAND*MLAND];
__device__ float g_wb [BH*MLAND*MLAND];
__device__ float g_tb [BH*MLAND*MLAND];
__device__ float g_z0 [BH*MLAND*MLAND];
__device__ float g_z1 [BH*MLAND*MLAND];
__device__ float g_a3v[BH*MLAND*64];
__device__ float g_pz [BH*MLAND*64];
__device__ float g_mg [(size_t)NB*NPAD*DD];
__device__ float g_mx [2];
__device__ float g_pm [BH*4*MLAND];
__device__ float g_ps [BH*4*MLAND];

// ----------------- fast exp2 (FFMA-only, rel err ~8e-6) -----------------
__device__ __forceinline__ float fexp2(float y){
    y = fmaxf(y, -120.f);
    float fl = floorf(y);
    float f = y - fl;
    float p = 1.54036e-4f;
    p = fmaf(p, f, 1.33336e-3f);
    p = fmaf(p, f, 9.61813e-3f);
    p = fmaf(p, f, 5.55041e-2f);
    p = fmaf(p, f, 2.40227e-1f);
    p = fmaf(p, f, 6.93147e-1f);
    p = fmaf(p, f, 1.0f);
    return p * __int_as_float(((int)fl + 127) << 23);
}

// ----------------- block reductions -----------------
__device__ __forceinline__ float bsum(float v, float* sh){
    int lane = threadIdx.x & 31, wid = threadIdx.x >> 5;
    #pragma unroll
    for (int o=16;o;o>>=1) v += __shfl_xor_sync(0xffffffffu, v, o);
    if (lane==0) sh[wid]=v;
    __syncthreads();
    if (wid==0){
        int nw = blockDim.x >> 5;
        float r = (lane<nw) ? sh[lane] : 0.f;
        #pragma unroll
        for (int o=16;o;o>>=1) r += __shfl_xor_sync(0xffffffffu, r, o);
        if (lane==0) sh[0]=r;
    }
    __syncthreads();
    float out = sh[0];
    __syncthreads();
    return out;
}
__device__ __forceinline__ float bmax(float v, float* sh){
    int lane = threadIdx.x & 31, wid = threadIdx.x >> 5;
    #pragma unroll
    for (int o=16;o;o>>=1) v = fmaxf(v, __shfl_xor_sync(0xffffffffu, v, o));
    if (lane==0) sh[wid]=v;
    __syncthreads();
    if (wid==0){
        int nw = blockDim.x >> 5;
        float r = (lane<nw) ? sh[lane] : -FLT_MAX;
        #pragma unroll
        for (int o=16;o;o>>=1) r = fmaxf(r, __shfl_xor_sync(0xffffffffu, r, o));
        if (lane==0) sh[0]=r;
    }
    __syncthreads();
    float out = sh[0];
    __syncthreads();
    return out;
}

// ----------------- double-buffered batched GEMM -----------------
template<int BM,int BN,int BK,int TM,int TN,int MAXB>
__global__ void __launch_bounds__((BM/TM)*(BN/TN), MAXB)
gemm_k(const float* __restrict__ A, const float* __restrict__ Bp,
       float* C, float* C2, const float* __restrict__ bias,
       int M,int N,int K,int lda,int ldb,int ldc,
       long sA1,long sA2,long sB1,long sB2,long sC1,long sC2,
       int nh,float alpha,float dval,int nTN,int kSplit,int flags)
{
    constexpr int THREADS=(BM/TM)*(BN/TN);
    constexpr int LA = BM*BK/THREADS;
    constexpr int LB = BK*BN/THREADS;
    __shared__ float As[2][BK][BM];
    __shared__ float Bs[2][BK][BN+1];
    int bz=blockIdx.z;
    A  += (long)(bz/nh)*sA1 + (long)(bz%nh)*sA2;
    Bp += (long)(bz/nh)*sB1 + (long)(bz%nh)*sB2;
    long offC = (long)(bz/nh)*sC1 + (long)(bz%nh)*sC2;
    int kIdx=blockIdx.x/nTN;
    int col0=(blockIdx.x%nTN)*BN;
    int row0=blockIdx.y*BM;
    int kChunk=(K+kSplit-1)/kSplit;
    int k0=kIdx*kChunk, k1=min(K,k0+kChunk);
    int tid=threadIdx.x;
    int tm=tid/(BN/TN), tn=tid%(BN/TN);
    bool trb = (flags & FTRB) != 0;
    float acc[TM][TN] = {};
    float pa[LA], pb[LB];

    auto loadT = [&](int kk){
        #pragma unroll
        for (int it=0; it<LA; it++){
            int i=tid+it*THREADS;
            int m=i/BK, k=i%BK;
            int gm=row0+m, gk=kk+k;
            pa[it] = (gm<M && gk<k1) ? A[(long)gm*lda+gk] : 0.f;
        }
        #pragma unroll
        for (int it=0; it<LB; it++){
            int i=tid+it*THREADS;
            int k,n;
            if (trb){ n=i/BK; k=i%BK; } else { k=i/BN; n=i%BN; }
            int gk=kk+k, gn=col0+n;
            pb[it] = (gk<k1 && gn<N) ? (trb ? Bp[(long)gn*ldb+gk] : Bp[(long)gk*ldb+gn]) : 0.f;
        }
    };
    auto storeT = [&](int b){
        #pragma unroll
        for (int it=0; it<LA; it++){
            int i=tid+it*THREADS;
            int m=i/BK, k=i%BK;
            As[b][k][m]=pa[it];
        }
        #pragma unroll
        for (int it=0; it<LB; it++){
            int i=tid+it*THREADS;
            int k,n;
            if (trb){ n=i/BK; k=i%BK; } else { k=i/BN; n=i%BN; }
            Bs[b][k][n]=pb[it];
        }
    };

    loadT(k0);
    storeT(0);
    __syncthreads();
    int buf=0;
    for (int kk=k0; kk<k1; kk+=BK){
        bool hn = (kk+BK) < k1;
        if (hn) loadT(kk+BK);
        #pragma unroll
        for (int k=0;k<BK;k++){
            float ra[TM], rb[TN];
            #pragma unroll
            for (int i=0;i<TM;i++) ra[i]=As[buf][k][tm*TM+i];
            #pragma unroll
            for (int j=0;j<TN;j++) rb[j]=Bs[buf][k][tn*TN+j];
            #pragma unroll
            for (int i=0;i<TM;i++)
                #pragma unroll
                for (int j=0;j<TN;j++) acc[i][j] += ra[i]*rb[j];
        }
        if (hn) storeT(buf^1);
        __syncthreads();
        buf^=1;
    }
    #pragma unroll
    for (int i=0;i<TM;i++){
        int gm=row0+tm*TM+i; if (gm>=M) continue;
        #pragma unroll
        for (int j=0;j<TN;j++){
            int gn=col0+tn*TN+j; if (gn>=N) continue;
            float v = acc[i][j]*alpha;
            if (flags&FB) v += bias[gn];
            long idx = offC + (long)gm*ldc + gn;
            if (C2) C2[idx] = ((gm==gn)?dval:0.f) - v;
            if (C){
                if (flags&FAT) atomicAdd(&C[idx], v);
                else {
                    float o = v;
                    if (flags&FACC) o += C[idx];
                    if (flags&FR)   o = fmaxf(o, 0.f);
                    C[idx] = o;
                }
            }
        }
    }
}

static void gemm128(const float*A,const float*B,float*C,float*C2,const float*bias,
    int M,int N,int K,int lda,int ldb,int ldc,
    long a1,long a2,long b1,long b2,long c1,long c2,int nh,int batch,
    float alpha,float dval,int kSplit,int flags)
{
    int nTN=(N+127)/128, nTM=(M+127)/128;
    dim3 g(nTN*kSplit, nTM, batch);
    gemm_k<128,128,8,8,8,2><<<g,256>>>(A,B,C,C2,bias,M,N,K,lda,ldb,ldc,
        a1,a2,b1,b2,c1,c2,nh,alpha,dval,nTN,kSplit,flags);
}
static void gemm64(const float*A,const float*B,float*C,float*C2,const float*bias,
    int M,int N,int K,int lda,int ldb,int ldc,
    long a1,long a2,long b1,long b2,long c1,long c2,int nh,int batch,
    float alpha,float dval,int kSplit,int flags)
{
    int nTN=(N+63)/64, nTM=(M+63)/64;
    dim3 g(nTN*kSplit, nTM, batch);
    gemm_k<64,64,16,4,4,2><<<g,256>>>(A,B,C,C2,bias,M,N,K,lda,ldb,ldc,
        a1,a2,b1,b2,c1,c2,nh,alpha,dval,nTN,kSplit,flags);
}

// ----------------- F1: fused s1 = q@kl^T -> softmax -> @pz -> mg -----------------
// grid (160, 16), block 256. dyn smem: sq[64][68] + skl[64][260](∪ spz[256][64]) + sa[256][68]
#define F1_SMEM ((64*68 + 64*260 + 256*68)*4)
__global__ void __launch_bounds__(256,1)
f1_k(const float* __restrict__ qkv, const float* __restrict__ kl,
     const float* __restrict__ pz, float* __restrict__ mg)
{
    extern __shared__ float sm[];
    float* sq  = sm;                 // [64][68]  k-major q tile
    float* skl = sm + 64*68;         // [64][260] k-major kl ; later reused as spz[256][64]
    float* sa  = skl + 64*260;       // [256][68] a^T
    int bh = blockIdx.y, b = bh>>3, h = bh&7;
    int row0 = blockIdx.x*64;
    int tid = threadIdx.x;

    for (int i=tid;i<4096;i+=256){
        int m=i>>6, k=i&63;
        sq[k*68+m] = qkv[((size_t)b*NPAD + row0+m)*QKVD + h*64 + k];
    }
    const float* klb = kl + (size_t)bh*16384;
    for (int i=tid;i<16384;i+=256){
        int j=i>>6, k=i&63;
        skl[k*260+j] = klb[i];
    }
    __syncthreads();

    int tm=tid>>4, tn=tid&15;
    float acc[4][16] = {};
    #pragma unroll 4
    for (int k=0;k<64;k++){
        float ra[4], rb[16];
        #pragma unroll
        for (int x=0;x<4;x++)  ra[x]=sq[k*68+tm*4+x];
        #pragma unroll
        for (int x=0;x<16;x++) rb[x]=skl[k*260+tn*16+x];
        #pragma unroll
        for (int i=0;i<4;i++)
            #pragma unroll
            for (int j=0;j<16;j++) acc[i][j] += ra[i]*rb[j];
    }
    // softmax per row (0.125 scale folded into exp2 arg)
    const float C1 = 0.125f*1.44269504f;
    #pragma unroll
    for (int mi=0;mi<4;mi++){
        float mx = acc[mi][0];
        #pragma unroll
        for (int j=1;j<16;j++) mx = fmaxf(mx, acc[mi][j]);
        #pragma unroll
        for (int o=8;o;o>>=1) mx = fmaxf(mx, __shfl_xor_sync(0xffffffffu, mx, o));
        float p[16], s=0.f;
        #pragma unroll
        for (int j=0;j<16;j++){ p[j] = fexp2((acc[mi][j]-mx)*C1); s += p[j]; }
        #pragma unroll
        for (int o=8;o;o>>=1) s += __shfl_xor_sync(0xffffffffu, s, o);
        float inv = 1.f/s;
        #pragma unroll
        for (int j=0;j<16;j++) sa[(tn*16+j)*68 + tm*4+mi] = p[j]*inv;
    }
    __syncthreads();
    // load pz into the kl buffer (natural [j][d])
    const float* pzb = pz + (size_t)bh*16384;
    for (int i=tid;i<16384;i+=256) skl[i] = pzb[i];
    __syncthreads();
    // phase 2: out[64x64] = a @ pz
    float o2[4][4] = {};
    #pragma unroll 8
    for (int j=0;j<256;j++){
        float ra[4], rb[4];
        #pragma unroll
        for (int x=0;x<4;x++) ra[x]=sa[j*68+tm*4+x];
        #pragma unroll
        for (int x=0;x<4;x++) rb[x]=skl[j*64+tn*4+x];
        #pragma unroll
        for (int i=0;i<4;i++)
            #pragma unroll
            for (int d=0;d<4;d++) o2[i][d] += ra[i]*rb[d];
    }
    #pragma unroll
    for (int i=0;i<4;i++){
        size_t base = ((size_t)b*NPAD + row0 + tm*4+i)*DD + h*64 + tn*4;
        #pragma unroll
        for (int d=0;d<4;d++) mg[base+d] = o2[i][d];
    }
}

// ----------------- F2: split flash  out_part = softmax(ql@k^T) @ v -----------------
// grid (split=4, rowtile=4, bh=16), block 256.
// dyn smem: sql[64][68] + sk[64][68] + sv[64][64] + sp[64][68]
#define F2_SMEM ((64*68 + 64*68 + 64*64 + 64*68)*4)
__global__ void __launch_bounds__(256,1)
f2_k(const float* __restrict__ qkv, const float* __restrict__ ql,
     float* __restrict__ pout, float* __restrict__ pm, float* __restrict__ ps)
{
    extern __shared__ float sm[];
    float* sql = sm;               // [64][68]
    float* sk  = sm + 64*68;       // [64][68]
    float* sv  = sk + 64*68;       // [64][64]
    float* sp  = sv + 64*64;       // [64][68]  P^T
    int split = blockIdx.x, rt = blockIdx.y, bh = blockIdx.z;
    int b = bh>>3, h = bh&7;
    int row0 = rt*64;
    int tid = threadIdx.x;
    int tm = tid>>4, tn = tid&15;

    const float* qlb = ql + (size_t)bh*16384;
    for (int i=tid;i<4096;i+=256){
        int m=i>>6, k=i&63;
        sql[k*68+m] = qlb[(row0+m)*64 + k];
    }
    const float* kp = qkv + (size_t)b*NPAD*QKVD + 512  + h*64;
    const float* vp = qkv + (size_t)b*NPAD*QKVD + 1024 + h*64;

    float out[4][4] = {};
    float m_run[4] = {-1e30f,-1e30f,-1e30f,-1e30f};
    float s_run[4] = {};
    const float LOG2E = 1.44269504f;
    int t0 = split*2560;

    for (int c=0;c<40;c++){
        int tc = t0 + c*64;
        __syncthreads();
        for (int i=tid;i<4096;i+=256){
            int t=i>>6, k=i&63;
            sk[k*68+t] = kp[(size_t)(tc+t)*QKVD + k];
            sv[t*64+k] = vp[(size_t)(tc+t)*QKVD + k];
        }
        __syncthreads();
        float s[4][4] = {};
        #pragma unroll 8
        for (int k=0;k<64;k++){
            float ra[4], rb[4];
            #pragma unroll
            for (int x=0;x<4;x++) ra[x]=sql[k*68+tm*4+x];
            #pragma unroll
            for (int x=0;x<4;x++) rb[x]=sk[k*68+tn*4+x];
            #pragma unroll
            for (int i=0;i<4;i++)
                #pragma unroll
                for (int j=0;j<4;j++) s[i][j] += ra[i]*rb[j];
        }
        #pragma unroll
        for (int mi=0;mi<4;mi++){
            float cm = fmaxf(fmaxf(s[mi][0],s[mi][1]), fmaxf(s[mi][2],s[mi][3]));
            #pragma unroll
            for (int o=8;o;o>>=1) cm = fmaxf(cm, __shfl_xor_sync(0xffffffffu, cm, o));
            float nm = fmaxf(m_run[mi], cm);
            float fac = fexp2((m_run[mi]-nm)*LOG2E);
            m_run[mi] = nm;
            s_run[mi] *= fac;
            #pragma unroll
            for (int d=0;d<4;d++) out[mi][d] *= fac;
            float ls = 0.f;
            #pragma unroll
            for (int ti=0;ti<4;ti++){
                float p = fexp2((s[mi][ti]-nm)*LOG2E);
                sp[(tn*4+ti)*68 + tm*4+mi] = p;
                ls += p;
            }
            #pragma unroll
            for (int o=8;o;o>>=1) ls += __shfl_xor_sync(0xffffffffu, ls, o);
            s_run[mi] += ls;
        }
        __syncthreads();
        #pragma unroll 8
        for (int t=0;t<64;t++){
            float ra[4], rb[4];
            #pragma unroll
            for (int x=0;x<4;x++) ra[x]=sp[t*68+tm*4+x];
            #pragma unroll
            for (int x=0;x<4;x++) rb[x]=sv[t*64+tn*4+x];
            #pragma unroll
            for (int i=0;i<4;i++)
                #pragma unroll
                for (int d=0;d<4;d++) out[i][d] += ra[i]*rb[d];
        }
    }
    // write partials
    #pragma unroll
    for (int mi=0;mi<4;mi++){
        int gr = row0 + tm*4+mi;
        size_t base = (((size_t)bh*4 + split)*256 + gr)*64 + tn*4;
        #pragma unroll
        for (int d=0;d<4;d++) pout[base+d] = out[mi][d];
        if (tn==0){
            pm[(bh*4+split)*256+gr] = m_run[mi];
            ps[(bh*4+split)*256+gr] = s_run[mi];
        }
    }
}

__global__ void f2comb_k(const float* __restrict__ pout, const float* __restrict__ pm,
                         const float* __restrict__ ps, float* __restrict__ a3v)
{
    int bh = blockIdx.x>>8, r = blockIdx.x&255, d = threadIdx.x;
    float M = -1e30f;
    #pragma unroll
    for (int s=0;s<4;s++) M = fmaxf(M, pm[(bh*4+s)*256+r]);
    float S = 0.f, o = 0.f;
    #pragma unroll
    for (int s=0;s<4;s++){
        float w = __expf(pm[(bh*4+s)*256+r] - M);
        S += ps[(bh*4+s)*256+r]*w;
        o += pout[(((size_t)bh*4+s)*256 + r)*64 + d]*w;
    }
    a3v[((size_t)bh*256+r)*64+d] = o/S;
}

// ----------------- elementwise / reduction kernels -----------------
__global__ void set_cls(float* h, const float* __restrict__ cls){
    h[((size_t)blockIdx.x*NPAD + PADF)*DD + threadIdx.x] = cls[threadIdx.x];
}

__global__ void ln_k(const float* __restrict__ h, float* __restrict__ o,
                     const float* __restrict__ g, const float* __restrict__ b){
    __shared__ float sh[32];
    size_t row = blockIdx.x;
    int t = (int)(row % NPAD);
    float* op = o + row*(size_t)DD;
    int tx = threadIdx.x;
    if (t < PADF){ op[tx]=0.f; op[tx+256]=0.f; return; }
    const float* p = h + row*(size_t)DD;
    float x0=p[tx], x1=p[tx+256];
    float mu  = bsum(x0+x1, sh) * (1.f/512.f);
    float d0=x0-mu, d1=x1-mu;
    float var = bsum(d0*d0+d1*d1, sh) * (1.f/512.f);
    float rs = rsqrtf(var + 1e-5f);
    op[tx]     = d0*rs*g[tx]     + b[tx];
    op[tx+256] = d1*rs*g[tx+256] + b[tx+256];
}

__global__ void lnf_k(const float* __restrict__ h, float* __restrict__ o,
                      const float* __restrict__ g, const float* __restrict__ b){
    __shared__ float sh[32];
    const float* p = h + ((size_t)blockIdx.x*NPAD + PADF)*DD;
    int tx = threadIdx.x;
    float x0=p[tx], x1=p[tx+256];
    float mu  = bsum(x0+x1, sh) * (1.f/512.f);
    float d0=x0-mu, d1=x1-mu;
    float var = bsum(d0*d0+d1*d1, sh) * (1.f/512.f);
    float rs = rsqrtf(var + 1e-5f);
    o[blockIdx.x*DD+tx]     = d0*rs*g[tx]     + b[tx];
    o[blockIdx.x*DD+tx+256] = d1*rs*g[tx+256] + b[tx+256];
}

__global__ void landmarks_k(const float* __restrict__ qkv,
                            float* __restrict__ ql, float* __restrict__ kl){
    int bz=blockIdx.x, m=blockIdx.y, d=threadIdx.x;
    int b=bz>>3, hh=bz&7;
    const float* base = qkv + ((size_t)b*NPAD + (size_t)m*40)*QKVD + hh*64 + d;
    float sq=0.f, sk=0.f;
    #pragma unroll 8
    for (int j=0;j<40;j++){ sq += base[(size_t)j*QKVD]; sk += base[(size_t)j*QKVD+512]; }
    ql[((size_t)bz*MLAND+m)*64+d] = sq*0.003125f;  // (1/40)*DH^-0.5
    kl[((size_t)bz*MLAND+m)*64+d] = sk*0.025f;     // 1/40
}

__global__ void softmax256(float* __restrict__ X){
    __shared__ float sh[32];
    float* p = X + (size_t)blockIdx.x*256;
    float v = p[threadIdx.x];
    float m = bmax(v, sh);
    float e = __expf(v - m);
    float s = bsum(e, sh);
    p[threadIdx.x] = e / s;
}

__global__ void zerok(float* p, int n){
    int i = blockIdx.x*256 + threadIdx.x;
    if (i<n) p[i]=0.f;
}

__global__ void crmax_k(const float* __restrict__ a2, float* mx){
    __shared__ float sh[32];
    const float* p = a2 + (size_t)blockIdx.x*65536;
    int t = threadIdx.x;
    float cs=0.f, rs=0.f;
    for (int m=0;m<256;m++){ cs += p[m*256+t]; rs += p[t*256+m]; }
    float mc = bmax(cs, sh);
    float mr = bmax(rs, sh);
    if (t==0){
        atomicMax((int*)&mx[0], __float_as_int(mc));
        atomicMax((int*)&mx[1], __float_as_int(mr));
    }
}

__global__ void ztrans_k(const float* __restrict__ a2, float* __restrict__ z,
                         const float* __restrict__ mx){
    __shared__ float tile[32][33];
    int bz=blockIdx.x;
    const float* p = a2 + (size_t)bz*65536;
    float* q = z + (size_t)bz*65536;
    int i0=blockIdx.y*32, j0=blockIdx.z*32;
    tile[threadIdx.y][threadIdx.x] = p[(j0+threadIdx.y)*256 + i0+threadIdx.x];
    __syncthreads();
    float inv = 1.f/(mx[0]*mx[1]);
    q[(i0+threadIdx.y)*256 + j0+threadIdx.x] = tile[threadIdx.x][threadIdx.y]*inv;
}

__global__ void resconv_k(const float* __restrict__ qkv, const float* __restrict__ rw,
                          float* __restrict__ mg){
    __shared__ float w[33];
    int bz=blockIdx.y; int b=bz>>3, hh=bz&7;
    if (threadIdx.y==0 && threadIdx.x<33) w[threadIdx.x]=rw[hh*33+threadIdx.x];
    __syncthreads();
    int d=threadIdx.x;
    int t=blockIdx.x*8+threadIdx.y;
    const float* vb = qkv + (size_t)b*NPAD*QKVD + 1024 + hh*64 + d;
    float acc=0.f;
    #pragma unroll
    for (int j=0;j<33;j++){
        int ts=t+j-16;
        if (ts>=0 && ts<NPAD) acc += vb[(size_t)ts*QKVD]*w[j];
    }
    mg[((size_t)b*NPAD+t)*DD + hh*64 + d] += acc;
}

__global__ void t2p_k(const float* __restrict__ h, float* __restrict__ pl){
    __shared__ float tile[32][33];
    int b=blockIdx.x, t0=blockIdx.y*32, c0=blockIdx.z*32;
    int t=t0+threadIdx.y, c=c0+threadIdx.x;
    if (t<10000) tile[threadIdx.y][threadIdx.x] = h[((size_t)b*NPAD+PADF+1+t)*DD + c];
    __syncthreads();
    int ch=c0+threadIdx.y, tt=t0+threadIdx.x;
    if (tt<10000) pl[((size_t)b*DD+ch)*10000 + tt] = tile[threadIdx.x][threadIdx.y];
}
__global__ void p2h_k(const float* __restrict__ pl, float* __restrict__ h){
    __shared__ float tile[32][33];
    int b=blockIdx.x, t0=blockIdx.y*32, c0=blockIdx.z*32;
    int ch=c0+threadIdx.y, tt=t0+threadIdx.x;
    if (tt<10000) tile[threadIdx.y][threadIdx.x] = pl[((size_t)b*DD+ch)*10000 + tt];
    __syncthreads();
    int t=t0+threadIdx.y, c=c0+threadIdx.x;
    if (t<10000) h[((size_t)b*NPAD+PADF+1+t)*DD + c] = tile[threadIdx.x][threadIdx.y];
}

__global__ void ppeg_conv_k(const float* __restrict__ pl, float* __restrict__ po,
    const float* __restrict__ w7, const float* __restrict__ b7,
    const float* __restrict__ w5, const float* __restrict__ b5,
    const float* __restrict__ w3, const float* __restrict__ b3){
    __shared__ float sw[86];
    int plane=blockIdx.x; int ch=plane&511;
    int tx=threadIdx.x;
    if      (tx<49) sw[tx]=w7[ch*49+tx];
    else if (tx<74) sw[tx]=w5[ch*25+tx-49];
    else if (tx<83) sw[tx]=w3[ch*9+tx-74];
    else if (tx==83) sw[83]=b7[ch];
    else if (tx==84) sw[84]=b5[ch];
    else if (tx==85) sw[85]=b3[ch];
    __syncthreads();
    int px=blockIdx.y*256+tx;
    if (px>=10000) return;
    int r=px/100, c=px%100;
    const float* in = pl + (size_t)plane*10000;
    float acc = in[px] + sw[83] + sw[84] + sw[85];
    #pragma unroll
    for (int kr=0;kr<7;kr++){
        int rr=r+kr-3; if (rr<0||rr>=100) continue;
        #pragma unroll
        for (int kc=0;kc<7;kc++){
            int cc=c+kc-3; if (cc<0||cc>=100) continue;
            acc += in[rr*100+cc]*sw[kr*7+kc];
        }
    }
    #pragma unroll
    for (int kr=0;kr<5;kr++){
        int rr=r+kr-2; if (rr<0||rr>=100) continue;
        #pragma unroll
        for (int kc=0;kc<5;kc++){
            int cc=c+kc-2; if (cc<0||cc>=100) continue;
            acc += in[rr*100+cc]*sw[49+kr*5+kc];
        }
    }
    #pragma unroll
    for (int kr=0;kr<3;kr++){
        int rr=r+kr-1; if (rr<0||rr>=100) continue;
        #pragma unroll
        for (int kc=0;kc<3;kc++){
            int cc=c+kc-1; if (cc<0||cc>=100) continue;
            acc += in[rr*100+cc]*sw[74+kr*3+kc];
        }
    }
    po[(size_t)plane*10000+px]=acc;
}

__global__ void head_k(const float* __restrict__ cls, const float* __restrict__ w2,
                       const float* __restrict__ b2, float* out, int osz){
    __shared__ float sh[64];
    int b=blockIdx.x;
    float a0=0.f, a1=0.f;
    for (int d=threadIdx.x; d<512; d+=256){
        float x = cls[b*512+d];
        a0 += x*w2[d*2+0]; a1 += x*w2[d*2+1];
    }
    #pragma unroll
    for (int o=16;o;o>>=1){
        a0 += __shfl_xor_sync(0xffffffffu,a0,o);
        a1 += __shfl_xor_sync(0xffffffffu,a1,o);
    }
    int lane=threadIdx.x&31, wid=threadIdx.x>>5;
    if (lane==0){ sh[wid]=a0; sh[wid+32]=a1; }
    __syncthreads();
    if (threadIdx.x==0){
        float l0=b2[0], l1=b2[1];
        for (int w=0;w<8;w++){ l0+=sh[w]; l1+=sh[w+32]; }
        float m=fmaxf(l0,l1);
        float e0=expf(l0-m), e1=expf(l1-m), s=e0+e1;
        if (b*2+1   < osz){ out[b*2]=l0;      out[b*2+1]=l1; }
        if (4+b*2+1 < osz){ out[4+b*2]=e0/s;  out[4+b*2+1]=e1/s; }
        if (8+b     < osz){ out[8+b] = (l1>l0)?1.f:0.f; }
    }
}

// ----------------- driver -----------------
extern "C" void kernel_launch(void* const* d_in, const int* in_sizes, int n_in,
                              void* d_out, int out_size){
    const float* x    =(const float*)d_in[0];
    const float* wfc1 =(const float*)d_in[1];
    const float* bfc1 =(const float*)d_in[2];
    const float* clst =(const float*)d_in[3];
    const float* lng[2]={(const float*)d_in[4],(const float*)d_in[10]};
    const float* lnb[2]={(const float*)d_in[5],(const float*)d_in[11]};
    const float* qkvw[2]={(const float*)d_in[6],(const float*)d_in[12]};
    const float* outw[2]={(const float*)d_in[7],(const float*)d_in[13]};
    const float* outb[2]={(const float*)d_in[8],(const float*)d_in[14]};
    const float* resw[2]={(const float*)d_in[9],(const float*)d_in[15]};
    const float* pw7=(const float*)d_in[16]; const float* pb7=(const float*)d_in[17];
    const float* pw5=(const float*)d_in[18]; const float* pb5=(const float*)d_in[19];
    const float* pw3=(const float*)d_in[20]; const float* pb3=(const float*)d_in[21];
    const float* lnfg=(const float*)d_in[22]; const float* lnfb=(const float*)d_in[23];
    const float* wfc2=(const float*)d_in[24]; const float* bfc2=(const float*)d_in[25];

    float *h,*ln,*qkv,*ql,*kl,*s1,*s3,*a2,*xz,*wb,*tb,*z0,*z1,*a3v,*pz,*mg,*mx,*pm,*ps;
    cudaGetSymbolAddress((void**)&h,  g_h);
    cudaGetSymbolAddress((void**)&ln, g_ln);
    cudaGetSymbolAddress((void**)&qkv,g_qkv);
    cudaGetSymbolAddress((void**)&ql, g_ql);
    cudaGetSymbolAddress((void**)&kl, g_kl);
    cudaGetSymbolAddress((void**)&s1, g_s1);
    cudaGetSymbolAddress((void**)&s3, g_s3);
    cudaGetSymbolAddress((void**)&a2, g_a2);
    cudaGetSymbolAddress((void**)&xz, g_xz);
    cudaGetSymbolAddress((void**)&wb, g_wb);
    cudaGetSymbolAddress((void**)&tb, g_tb);
    cudaGetSymbolAddress((void**)&z0, g_z0);
    cudaGetSymbolAddress((void**)&z1, g_z1);
    cudaGetSymbolAddress((void**)&a3v,g_a3v);
    cudaGetSymbolAddress((void**)&pz, g_pz);
    cudaGetSymbolAddress((void**)&mg, g_mg);
    cudaGetSymbolAddress((void**)&mx, g_mx);
    cudaGetSymbolAddress((void**)&pm, g_pm);
    cudaGetSymbolAddress((void**)&ps, g_ps);

    cudaFuncSetAttribute(f1_k, cudaFuncAttributeMaxDynamicSharedMemorySize, F1_SMEM);
    cudaFuncSetAttribute(f2_k, cudaFuncAttributeMaxDynamicSharedMemorySize, F2_SMEM);

    // fc1: h[b, PADF+1+t, :] = relu(x @ w_fc1 + b_fc1)
    gemm128(x, wfc1, h+(size_t)(PADF+1)*DD, nullptr, bfc1,
            10000, 512, 1024, 1024, 512, 512,
            (long)10000*1024, 0, 0, 0, (long)NPAD*DD, 0,
            1, NB, 1.f, 0.f, 1, FB|FR);
    set_cls<<<NB,512>>>(h, clst);

    for (int L=0; L<2; L++){
        ln_k<<<NB*NPAD,256>>>(h, ln, lng[L], lnb[L]);
        gemm128(ln, qkvw[L], qkv, nullptr, nullptr,
                NB*NPAD, QKVD, 512, 512, QKVD, QKVD,
                0,0, 0,0, 0,0, 1, 1, 1.f, 0.f, 1, 0);
        landmarks_k<<<dim3(BH,MLAND),64>>>(qkv, ql, kl);
        // s2 = ql @ kl^T -> a2, softmax
        gemm64(ql, kl, a2, nullptr, nullptr,
               256, 256, 64, 64, 64, 256,
               (long)256*64, 0, (long)256*64, 0, (long)65536, 0,
               1, BH, 1.f, 0.f, 1, FTRB);
        softmax256<<<BH*256,256>>>(a2);
        // fused s3 -> online softmax -> @v  (split flash + combine)
        f2_k<<<dim3(4,4,BH),256,F2_SMEM>>>(qkv, ql, s1, pm, ps);
        f2comb_k<<<BH*256,64>>>(s1, pm, ps, a3v);
        // Moore-Penrose pinv of a2
        zerok<<<1,256>>>(mx, 2);
        crmax_k<<<BH,256>>>(a2, mx);
        ztrans_k<<<dim3(BH,8,8),dim3(32,32)>>>(a2, z0, mx);
        float* cur=z0; float* nxt=z1;
        for (int it=0; it<6; it++){
            gemm64(a2, cur, xz, wb, nullptr, 256,256,256, 256,256,256,
                   65536,0, 65536,0, 65536,0, 1, BH, 1.f, 7.f, 1, 0);
            gemm64(xz, wb, nullptr, tb, nullptr, 256,256,256, 256,256,256,
                   65536,0, 65536,0, 65536,0, 1, BH, 1.f, 15.f, 1, 0);
            gemm64(xz, tb, nullptr, wb, nullptr, 256,256,256, 256,256,256,
                   65536,0, 65536,0, 65536,0, 1, BH, 1.f, 13.f, 1, 0);
            gemm64(cur, wb, nxt, nullptr, nullptr, 256,256,256, 256,256,256,
                   65536,0, 65536,0, 65536,0, 1, BH, 0.25f, 0.f, 1, 0);
            float* t=cur; cur=nxt; nxt=t;
        }
        // pz = pinv(a2) @ a3v
        gemm64(cur, a3v, pz, nullptr, nullptr,
               256, 64, 256, 256, 64, 64,
               65536,0, 16384,0, 16384,0, 1, BH, 1.f, 0.f, 1, 0);
        // fused s1 -> softmax -> @pz -> mg
        f1_k<<<dim3(160,BH),256,F1_SMEM>>>(qkv, kl, pz, mg);
        // += depthwise 33-tap residual conv on v
        resconv_k<<<dim3(NPAD/8,BH),dim3(64,8)>>>(qkv, resw[L], mg);
        // h[rows PADF..] += mg @ w_out + b_out
        gemm128(mg+(size_t)PADF*DD, outw[L], h+(size_t)PADF*DD, nullptr, outb[L],
                10001, 512, 512, 512, 512, 512,
                (long)NPAD*DD, 0, 0, 0, (long)NPAD*DD, 0,
                1, NB, 1.f, 0.f, 1, FB|FACC);
        if (L==0){
            t2p_k<<<dim3(NB,313,16),dim3(32,32)>>>(h, s1);
            ppeg_conv_k<<<dim3(NB*512,40),256>>>(s1, s3, pw7,pb7, pw5,pb5, pw3,pb3);
            p2h_k<<<dim3(NB,313,16),dim3(32,32)>>>(s3, h);
        }
    }
    lnf_k<<<NB,256>>>(h, a2, lnfg, lnfb);
    head_k<<<NB,256>>>(a2, wfc2, bfc2, (float*)d_out, out_size);
}

// round 11
// speedup vs baseline: 1.6093x; 1.3746x over previous
#include <cuda_runtime.h>
#include <cuda_bf16.h>
#include <cfloat>
#include <cstdint>

#define NB    2
#define DIN   1024
#define DD    512
#define NPAD  10240
#define PADF  239
#define QKVD  1536
#define MLAND 256
#define BH    16

#define FB    1
#define FR    2
#define FACC  4
#define FAT   8
#define FTRB  16

// ----------------- device scratch -----------------
__device__ float g_h  [(size_t)NB*NPAD*DD];
__device__ float g_qkv[(size_t)NB*NPAD*QKVD];
__device__ float g_ql [BH*MLAND*64];
__device__ float g_kl [BH*MLAND*64];
__device__ float g_s1 [(size_t)BH*NPAD*MLAND];   // reused: F2 partials, PPEG planar
__device__ float g_s3 [(size_t)BH*MLAND*NPAD];   // reused: PPEG planar
__device__ float g_a2 [BH*MLAND*MLAND];
__device__ float g_xz [BH*MLAND*MLAND];
__device__ float g_wb [BH*MLAND*MLAND];
__device__ float g_tb [BH*MLAND*MLAND];
__device__ float g_z0 [BH*MLAND*MLAND];
__device__ float g_z1 [BH*MLAND*MLAND];
__device__ float g_a3v[BH*MLAND*64];
__device__ float g_pz [BH*MLAND*64];
__device__ float g_mg [(size_t)NB*NPAD*DD];
__device__ float g_mx [2];
__device__ float g_pm [BH*4*MLAND];
__device__ float g_ps [BH*4*MLAND];

// bf16 hi/lo operands for tensor-core GEMMs
__device__ __align__(16) __nv_bfloat16 g_xh [(size_t)NB*10000*DIN];
__device__ __align__(16) __nv_bfloat16 g_xl [(size_t)NB*10000*DIN];
__device__ __align__(16) __nv_bfloat16 g_lnh[(size_t)NB*NPAD*DD];
__device__ __align__(16) __nv_bfloat16 g_lnl[(size_t)NB*NPAD*DD];
__device__ __align__(16) __nv_bfloat16 g_mgh[(size_t)NB*NPAD*DD];
__device__ __align__(16) __nv_bfloat16 g_mgl[(size_t)NB*NPAD*DD];
__device__ __align__(16) __nv_bfloat16 g_wth[786432];
__device__ __align__(16) __nv_bfloat16 g_wtl[786432];

// ----------------- fast exp2 (FFMA-only, rel err ~8e-6) -----------------
__device__ __forceinline__ float fexp2(float y){
    y = fmaxf(y, -120.f);
    float fl = floorf(y);
    float f = y - fl;
    float p = 1.54036e-4f;
    p = fmaf(p, f, 1.33336e-3f);
    p = fmaf(p, f, 9.61813e-3f);
    p = fmaf(p, f, 5.55041e-2f);
    p = fmaf(p, f, 2.40227e-1f);
    p = fmaf(p, f, 6.93147e-1f);
    p = fmaf(p, f, 1.0f);
    return p * __int_as_float(((int)fl + 127) << 23);
}

// ----------------- helpers -----------------
__device__ __forceinline__ uint32_t smem_u32(const void* p){
    uint32_t a;
    asm("{ .reg .u64 t; cvta.to.shared.u64 t, %1; cvt.u32.u64 %0, t; }" : "=r"(a) : "l"(p));
    return a;
}
__device__ __forceinline__ void cpasync16(uint32_t d, const void* s, int sz){
    asm volatile("cp.async.cg.shared.global [%0], [%1], 16, %2;"
        :: "r"(d), "l"(s), "r"(sz) : "memory");
}
__device__ __forceinline__ void ldmx4(uint32_t* r, uint32_t a){
    asm volatile("ldmatrix.sync.aligned.m8n8.x4.shared.b16 {%0,%1,%2,%3},[%4];"
        : "=r"(r[0]), "=r"(r[1]), "=r"(r[2]), "=r"(r[3]) : "r"(a));
}
__device__ __forceinline__ void mma_bf16(float* c, const uint32_t* a, uint32_t b0, uint32_t b1){
    asm volatile("mma.sync.aligned.m16n8k16.row.col.f32.bf16.bf16.f32 "
        "{%0,%1,%2,%3},{%4,%5,%6,%7},{%8,%9},{%0,%1,%2,%3};"
        : "+f"(c[0]), "+f"(c[1]), "+f"(c[2]), "+f"(c[3])
        : "r"(a[0]), "r"(a[1]), "r"(a[2]), "r"(a[3]), "r"(b0), "r"(b1));
}

// ----------------- HMMA GEMM: C = A @ B^T (hi/lo bf16, fp32 acc) -----------------
// A hi/lo: [batch][M][K] bf16 row-major. B hi/lo: [N][K] bf16 row-major (pre-transposed W).
// grid (N/128, ceil(M/128), batch), block 256. dyn smem = 2 buffers * 4 tiles * 128*72 bf16.
#define MMH_TS   (128*72)
#define MMH_BUFB (4*MMH_TS*2)
#define MMH_SMEM (2*MMH_BUFB)
__global__ void __launch_bounds__(256, 1)
mm_hmma(const __nv_bfloat16* __restrict__ Ah, const __nv_bfloat16* __restrict__ Al,
        const __nv_bfloat16* __restrict__ Bh, const __nv_bfloat16* __restrict__ Bl,
        float* __restrict__ C, const float* __restrict__ bias,
        int M, int K, int ldc, long sA, long sC, int flags)
{
    extern __shared__ __nv_bfloat16 smb[];
    uint32_t sbase = smem_u32(smb);
    int tid = threadIdx.x, wid = tid >> 5, lane = tid & 31;
    int col0 = blockIdx.x * 128, row0 = blockIdx.y * 128;
    long bz = blockIdx.z;
    Ah += bz * sA;  Al += bz * sA;
    float* Cb = C + bz * sC;

    int wm = wid & 3, wn = wid >> 2;  // warp tile: rows wm*32, cols wn*64
    float acc[2][8][4] = {};
    const int S = K >> 6;

    auto issue = [&](int s){
        int b = s & 1;
        uint32_t dst = sbase + (uint32_t)b * MMH_BUFB;
        int k0 = s << 6;
        #pragma unroll
        for (int i = 0; i < 4; i++){
            int ch = tid + i*256;
            int r = ch >> 3, c8 = ch & 7;
            uint32_t off = (uint32_t)(r*144 + c8*16);
            int gm = row0 + r;
            const __nv_bfloat16* pah = Ah + (long)gm*K + k0 + c8*8;
            const __nv_bfloat16* pal = Al + (long)gm*K + k0 + c8*8;
            int sz = (gm < M) ? 16 : 0;
            cpasync16(dst + off,              pah, sz);
            cpasync16(dst + MMH_TS*2 + off,   pal, sz);
            long gn = col0 + r;
            cpasync16(dst + 2*MMH_TS*2 + off, Bh + gn*K + k0 + c8*8, 16);
            cpasync16(dst + 3*MMH_TS*2 + off, Bl + gn*K + k0 + c8*8, 16);
        }
        asm volatile("cp.async.commit_group;" ::: "memory");
    };

    issue(0);
    for (int s = 0; s < S; s++){
        if (s + 1 < S){
            issue(s + 1);
            asm volatile("cp.async.wait_group 1;" ::: "memory");
        } else {
            asm volatile("cp.async.wait_group 0;" ::: "memory");
        }
        __syncthreads();
        uint32_t buf = sbase + (uint32_t)(s & 1) * MMH_BUFB;
        uint32_t aH = buf, aL = buf + MMH_TS*2;
        uint32_t bHb = buf + 2*MMH_TS*2, bLb = buf + 3*MMH_TS*2;
        #pragma unroll
        for (int ks = 0; ks < 4; ks++){
            int kc = ks * 16;
            uint32_t ah[2][4], al[2][4];
            #pragma unroll
            for (int mi = 0; mi < 2; mi++){
                int rowb = wm*32 + mi*16 + (lane & 15);
                uint32_t o = (uint32_t)(rowb*144 + kc*2 + (lane >> 4)*16);
                ldmx4(ah[mi], aH + o);
                ldmx4(al[mi], aL + o);
            }
            #pragma unroll
            for (int nb = 0; nb < 4; nb++){
                int g = lane >> 3;
                int rown = wn*64 + nb*16 + (g >> 1)*8 + (lane & 7);
                uint32_t bo = (uint32_t)(rown*144 + kc*2 + (g & 1)*16);
                uint32_t bh[4], bl[4];
                ldmx4(bh, bHb + bo);
                ldmx4(bl, bLb + bo);
                #pragma unroll
                for (int mi = 0; mi < 2; mi++){
                    #pragma unroll
                    for (int hf = 0; hf < 2; hf++){
                        float* c = acc[mi][nb*2 + hf];
                        mma_bf16(c, ah[mi], bh[hf*2], bh[hf*2+1]);
                        mma_bf16(c, ah[mi], bl[hf*2], bl[hf*2+1]);
                        mma_bf16(c, al[mi], bh[hf*2], bh[hf*2+1]);
                    }
                }
            }
        }
        __syncthreads();
    }

    int gID = lane >> 2, tig = lane & 3;
    #pragma unroll
    for (int mi = 0; mi < 2; mi++){
        #pragma unroll
        for (int nj = 0; nj < 8; nj++){
            int colb = col0 + wn*64 + nj*8 + tig*2;
            #pragma unroll
            for (int rh = 0; rh < 2; rh++){
                int gm = row0 + wm*32 + mi*16 + rh*8 + gID;
                if (gm >= M) continue;
                float v0 = acc[mi][nj][rh*2+0];
                float v1 = acc[mi][nj][rh*2+1];
                float* cp = Cb + (long)gm*ldc + colb;
                if (flags & FB){ v0 += bias[colb]; v1 += bias[colb+1]; }
                if (flags & FACC){ v0 += cp[0]; v1 += cp[1]; }
                if (flags & FR){ v0 = fmaxf(v0, 0.f); v1 = fmaxf(v1, 0.f); }
                cp[0] = v0; cp[1] = v1;
            }
        }
    }
}

// ----------------- hi/lo split conversions -----------------
__global__ void cvt_k(const float* __restrict__ s, __nv_bfloat16* __restrict__ hi,
                      __nv_bfloat16* __restrict__ lo, int n){
    int i = blockIdx.x*256 + threadIdx.x;
    if (i < n){
        float v = s[i];
        __nv_bfloat16 h = __float2bfloat16(v);
        hi[i] = h;
        lo[i] = __float2bfloat16(v - __bfloat162float(h));
    }
}
// W[K][N] -> WT hi/lo [N][K]
__global__ void cvtT_k(const float* __restrict__ W, __nv_bfloat16* __restrict__ th,
                       __nv_bfloat16* __restrict__ tl, int K, int N){
    __shared__ float t[32][33];
    int k0 = blockIdx.x*32, n0 = blockIdx.y*32;
    t[threadIdx.y][threadIdx.x] = W[(k0+threadIdx.y)*N + n0+threadIdx.x];
    __syncthreads();
    int n = n0+threadIdx.y, k = k0+threadIdx.x;
    float v = t[threadIdx.x][threadIdx.y];
    __nv_bfloat16 h = __float2bfloat16(v);
    th[(size_t)n*K+k] = h;
    tl[(size_t)n*K+k] = __float2bfloat16(v - __bfloat162float(h));
}

// ----------------- block reductions -----------------
__device__ __forceinline__ float bsum(float v, float* sh){
    int lane = threadIdx.x & 31, wid = threadIdx.x >> 5;
    #pragma unroll
    for (int o=16;o;o>>=1) v += __shfl_xor_sync(0xffffffffu, v, o);
    if (lane==0) sh[wid]=v;
    __syncthreads();
    if (wid==0){
        int nw = blockDim.x >> 5;
        float r = (lane<nw) ? sh[lane] : 0.f;
        #pragma unroll
        for (int o=16;o;o>>=1) r += __shfl_xor_sync(0xffffffffu, r, o);
        if (lane==0) sh[0]=r;
    }
    __syncthreads();
    float out = sh[0];
    __syncthreads();
    return out;
}
__device__ __forceinline__ float bmax(float v, float* sh){
    int lane = threadIdx.x & 31, wid = threadIdx.x >> 5;
    #pragma unroll
    for (int o=16;o;o>>=1) v = fmaxf(v, __shfl_xor_sync(0xffffffffu, v, o));
    if (lane==0) sh[wid]=v;
    __syncthreads();
    if (wid==0){
        int nw = blockDim.x >> 5;
        float r = (lane<nw) ? sh[lane] : -FLT_MAX;
        #pragma unroll
        for (int o=16;o;o>>=1) r = fmaxf(r, __shfl_xor_sync(0xffffffffu, r, o));
        if (lane==0) sh[0]=r;
    }
    __syncthreads();
    float out = sh[0];
    __syncthreads();
    return out;
}

// ----------------- fp32 batched GEMM (small/batched paths) -----------------
template<int BM,int BN,int BK,int TM,int TN,int MAXB>
__global__ void __launch_bounds__((BM/TM)*(BN/TN), MAXB)
gemm_k(const float* __restrict__ A, const float* __restrict__ Bp,
       float* C, float* C2, const float* __restrict__ bias,
       int M,int N,int K,int lda,int ldb,int ldc,
       long sA1,long sA2,long sB1,long sB2,long sC1,long sC2,
       int nh,float alpha,float dval,int nTN,int kSplit,int flags)
{
    constexpr int THREADS=(BM/TM)*(BN/TN);
    constexpr int LA = BM*BK/THREADS;
    constexpr int LB = BK*BN/THREADS;
    __shared__ float As[2][BK][BM];
    __shared__ float Bs[2][BK][BN+1];
    int bz=blockIdx.z;
    A  += (long)(bz/nh)*sA1 + (long)(bz%nh)*sA2;
    Bp += (long)(bz/nh)*sB1 + (long)(bz%nh)*sB2;
    long offC = (long)(bz/nh)*sC1 + (long)(bz%nh)*sC2;
    int kIdx=blockIdx.x/nTN;
    int col0=(blockIdx.x%nTN)*BN;
    int row0=blockIdx.y*BM;
    int kChunk=(K+kSplit-1)/kSplit;
    int k0=kIdx*kChunk, k1=min(K,k0+kChunk);
    int tid=threadIdx.x;
    int tm=tid/(BN/TN), tn=tid%(BN/TN);
    bool trb = (flags & FTRB) != 0;
    float acc[TM][TN] = {};
    float pa[LA], pb[LB];

    auto loadT = [&](int kk){
        #pragma unroll
        for (int it=0; it<LA; it++){
            int i=tid+it*THREADS;
            int m=i/BK, k=i%BK;
            int gm=row0+m, gk=kk+k;
            pa[it] = (gm<M && gk<k1) ? A[(long)gm*lda+gk] : 0.f;
        }
        #pragma unroll
        for (int it=0; it<LB; it++){
            int i=tid+it*THREADS;
            int k,n;
            if (trb){ n=i/BK; k=i%BK; } else { k=i/BN; n=i%BN; }
            int gk=kk+k, gn=col0+n;
            pb[it] = (gk<k1 && gn<N) ? (trb ? Bp[(long)gn*ldb+gk] : Bp[(long)gk*ldb+gn]) : 0.f;
        }
    };
    auto storeT = [&](int b){
        #pragma unroll
        for (int it=0; it<LA; it++){
            int i=tid+it*THREADS;
            int m=i/BK, k=i%BK;
            As[b][k][m]=pa[it];
        }
        #pragma unroll
        for (int it=0; it<LB; it++){
            int i=tid+it*THREADS;
            int k,n;
            if (trb){ n=i/BK; k=i%BK; } else { k=i/BN; n=i%BN; }
            Bs[b][k][n]=pb[it];
        }
    };

    loadT(k0);
    storeT(0);
    __syncthreads();
    int buf=0;
    for (int kk=k0; kk<k1; kk+=BK){
        bool hn = (kk+BK) < k1;
        if (hn) loadT(kk+BK);
        #pragma unroll
        for (int k=0;k<BK;k++){
            float ra[TM], rb[TN];
            #pragma unroll
            for (int i=0;i<TM;i++) ra[i]=As[buf][k][tm*TM+i];
            #pragma unroll
            for (int j=0;j<TN;j++) rb[j]=Bs[buf][k][tn*TN+j];
            #pragma unroll
            for (int i=0;i<TM;i++)
                #pragma unroll
                for (int j=0;j<TN;j++) acc[i][j] += ra[i]*rb[j];
        }
        if (hn) storeT(buf^1);
        __syncthreads();
        buf^=1;
    }
    #pragma unroll
    for (int i=0;i<TM;i++){
        int gm=row0+tm*TM+i; if (gm>=M) continue;
        #pragma unroll
        for (int j=0;j<TN;j++){
            int gn=col0+tn*TN+j; if (gn>=N) continue;
            float v = acc[i][j]*alpha;
            if (flags&FB) v += bias[gn];
            long idx = offC + (long)gm*ldc + gn;
            if (C2) C2[idx] = ((gm==gn)?dval:0.f) - v;
            if (C){
                if (flags&FAT) atomicAdd(&C[idx], v);
                else {
                    float o = v;
                    if (flags&FACC) o += C[idx];
                    if (flags&FR)   o = fmaxf(o, 0.f);
                    C[idx] = o;
                }
            }
        }
    }
}

static void gemm64(const float*A,const float*B,float*C,float*C2,const float*bias,
    int M,int N,int K,int lda,int ldb,int ldc,
    long a1,long a2,long b1,long b2,long c1,long c2,int nh,int batch,
    float alpha,float dval,int kSplit,int flags)
{
    int nTN=(N+63)/64, nTM=(M+63)/64;
    dim3 g(nTN*kSplit, nTM, batch);
    gemm_k<64,64,16,4,4,2><<<g,256>>>(A,B,C,C2,bias,M,N,K,lda,ldb,ldc,
        a1,a2,b1,b2,c1,c2,nh,alpha,dval,nTN,kSplit,flags);
}

// ----------------- F1: fused s1 = q@kl^T -> softmax -> @pz -> mg -----------------
#define F1_SMEM ((64*68 + 64*260 + 256*68)*4)
__global__ void __launch_bounds__(256,1)
f1_k(const float* __restrict__ qkv, const float* __restrict__ kl,
     const float* __restrict__ pz, float* __restrict__ mg)
{
    extern __shared__ float sm[];
    float* sq  = sm;
    float* skl = sm + 64*68;
    float* sa  = skl + 64*260;
    int bh = blockIdx.y, b = bh>>3, h = bh&7;
    int row0 = blockIdx.x*64;
    int tid = threadIdx.x;

    for (int i=tid;i<4096;i+=256){
        int m=i>>6, k=i&63;
        sq[k*68+m] = qkv[((size_t)b*NPAD + row0+m)*QKVD + h*64 + k];
    }
    const float* klb = kl + (size_t)bh*16384;
    for (int i=tid;i<16384;i+=256){
        int j=i>>6, k=i&63;
        skl[k*260+j] = klb[i];
    }
    __syncthreads();

    int tm=tid>>4, tn=tid&15;
    float acc[4][16] = {};
    #pragma unroll 4
    for (int k=0;k<64;k++){
        float ra[4], rb[16];
        #pragma unroll
        for (int x=0;x<4;x++)  ra[x]=sq[k*68+tm*4+x];
        #pragma unroll
        for (int x=0;x<16;x++) rb[x]=skl[k*260+tn*16+x];
        #pragma unroll
        for (int i=0;i<4;i++)
            #pragma unroll
            for (int j=0;j<16;j++) acc[i][j] += ra[i]*rb[j];
    }
    const float C1 = 0.125f*1.44269504f;
    #pragma unroll
    for (int mi=0;mi<4;mi++){
        float mx = acc[mi][0];
        #pragma unroll
        for (int j=1;j<16;j++) mx = fmaxf(mx, acc[mi][j]);
        #pragma unroll
        for (int o=8;o;o>>=1) mx = fmaxf(mx, __shfl_xor_sync(0xffffffffu, mx, o));
        float p[16], s=0.f;
        #pragma unroll
        for (int j=0;j<16;j++){ p[j] = fexp2((acc[mi][j]-mx)*C1); s += p[j]; }
        #pragma unroll
        for (int o=8;o;o>>=1) s += __shfl_xor_sync(0xffffffffu, s, o);
        float inv = 1.f/s;
        #pragma unroll
        for (int j=0;j<16;j++) sa[(tn*16+j)*68 + tm*4+mi] = p[j]*inv;
    }
    __syncthreads();
    const float* pzb = pz + (size_t)bh*16384;
    for (int i=tid;i<16384;i+=256) skl[i] = pzb[i];
    __syncthreads();
    float o2[4][4] = {};
    #pragma unroll 8
    for (int j=0;j<256;j++){
        float ra[4], rb[4];
        #pragma unroll
        for (int x=0;x<4;x++) ra[x]=sa[j*68+tm*4+x];
        #pragma unroll
        for (int x=0;x<4;x++) rb[x]=skl[j*64+tn*4+x];
        #pragma unroll
        for (int i=0;i<4;i++)
            #pragma unroll
            for (int d=0;d<4;d++) o2[i][d] += ra[i]*rb[d];
    }
    #pragma unroll
    for (int i=0;i<4;i++){
        size_t base = ((size_t)b*NPAD + row0 + tm*4+i)*DD + h*64 + tn*4;
        #pragma unroll
        for (int d=0;d<4;d++) mg[base+d] = o2[i][d];
    }
}

// ----------------- F2: split flash  out_part = softmax(ql@k^T) @ v -----------------
#define F2_SMEM ((64*68 + 64*68 + 64*64 + 64*68)*4)
__global__ void __launch_bounds__(256,1)
f2_k(const float* __restrict__ qkv, const float* __restrict__ ql,
     float* __restrict__ pout, float* __restrict__ pm, float* __restrict__ ps)
{
    extern __shared__ float sm[];
    float* sql = sm;
    float* sk  = sm + 64*68;
    float* sv  = sk + 64*68;
    float* sp  = sv + 64*64;
    int split = blockIdx.x, rt = blockIdx.y, bh = blockIdx.z;
    int b = bh>>3, h = bh&7;
    int row0 = rt*64;
    int tid = threadIdx.x;
    int tm = tid>>4, tn = tid&15;

    const float* qlb = ql + (size_t)bh*16384;
    for (int i=tid;i<4096;i+=256){
        int m=i>>6, k=i&63;
        sql[k*68+m] = qlb[(row0+m)*64 + k];
    }
    const float* kp = qkv + (size_t)b*NPAD*QKVD + 512  + h*64;
    const float* vp = qkv + (size_t)b*NPAD*QKVD + 1024 + h*64;

    float out[4][4] = {};
    float m_run[4] = {-1e30f,-1e30f,-1e30f,-1e30f};
    float s_run[4] = {};
    const float LOG2E = 1.44269504f;
    int t0 = split*2560;

    for (int c=0;c<40;c++){
        int tc = t0 + c*64;
        __syncthreads();
        for (int i=tid;i<4096;i+=256){
            int t=i>>6, k=i&63;
            sk[k*68+t] = kp[(size_t)(tc+t)*QKVD + k];
            sv[t*64+k] = vp[(size_t)(tc+t)*QKVD + k];
        }
        __syncthreads();
        float s[4][4] = {};
        #pragma unroll 8
        for (int k=0;k<64;k++){
            float ra[4], rb[4];
            #pragma unroll
            for (int x=0;x<4;x++) ra[x]=sql[k*68+tm*4+x];
            #pragma unroll
            for (int x=0;x<4;x++) rb[x]=sk[k*68+tn*4+x];
            #pragma unroll
            for (int i=0;i<4;i++)
                #pragma unroll
                for (int j=0;j<4;j++) s[i][j] += ra[i]*rb[j];
        }
        #pragma unroll
        for (int mi=0;mi<4;mi++){
            float cm = fmaxf(fmaxf(s[mi][0],s[mi][1]), fmaxf(s[mi][2],s[mi][3]));
            #pragma unroll
            for (int o=8;o;o>>=1) cm = fmaxf(cm, __shfl_xor_sync(0xffffffffu, cm, o));
            float nm = fmaxf(m_run[mi], cm);
            float fac = fexp2((m_run[mi]-nm)*LOG2E);
            m_run[mi] = nm;
            s_run[mi] *= fac;
            #pragma unroll
            for (int d=0;d<4;d++) out[mi][d] *= fac;
            float ls = 0.f;
            #pragma unroll
            for (int ti=0;ti<4;ti++){
                float p = fexp2((s[mi][ti]-nm)*LOG2E);
                sp[(tn*4+ti)*68 + tm*4+mi] = p;
                ls += p;
            }
            #pragma unroll
            for (int o=8;o;o>>=1) ls += __shfl_xor_sync(0xffffffffu, ls, o);
            s_run[mi] += ls;
        }
        __syncthreads();
        #pragma unroll 8
        for (int t=0;t<64;t++){
            float ra[4], rb[4];
            #pragma unroll
            for (int x=0;x<4;x++) ra[x]=sp[t*68+tm*4+x];
            #pragma unroll
            for (int x=0;x<4;x++) rb[x]=sv[t*64+tn*4+x];
            #pragma unroll
            for (int i=0;i<4;i++)
                #pragma unroll
                for (int d=0;d<4;d++) out[i][d] += ra[i]*rb[d];
        }
    }
    #pragma unroll
    for (int mi=0;mi<4;mi++){
        int gr = row0 + tm*4+mi;
        size_t base = (((size_t)bh*4 + split)*256 + gr)*64 + tn*4;
        #pragma unroll
        for (int d=0;d<4;d++) pout[base+d] = out[mi][d];
        if (tn==0){
            pm[(bh*4+split)*256+gr] = m_run[mi];
            ps[(bh*4+split)*256+gr] = s_run[mi];
        }
    }
}

__global__ void f2comb_k(const float* __restrict__ pout, const float* __restrict__ pm,
                         const float* __restrict__ ps, float* __restrict__ a3v)
{
    int bh = blockIdx.x>>8, r = blockIdx.x&255, d = threadIdx.x;
    float M = -1e30f;
    #pragma unroll
    for (int s=0;s<4;s++) M = fmaxf(M, pm[(bh*4+s)*256+r]);
    float S = 0.f, o = 0.f;
    #pragma unroll
    for (int s=0;s<4;s++){
        float w = __expf(pm[(bh*4+s)*256+r] - M);
        S += ps[(bh*4+s)*256+r]*w;
        o += pout[(((size_t)bh*4+s)*256 + r)*64 + d]*w;
    }
    a3v[((size_t)bh*256+r)*64+d] = o/S;
}

// ----------------- elementwise / reduction kernels -----------------
__global__ void set_cls(float* h, const float* __restrict__ cls){
    h[((size_t)blockIdx.x*NPAD + PADF)*DD + threadIdx.x] = cls[threadIdx.x];
}

// layernorm -> bf16 hi/lo split (zeros for front-pad rows)
__global__ void ln_k(const float* __restrict__ h, __nv_bfloat16* __restrict__ oh,
                     __nv_bfloat16* __restrict__ ol,
                     const float* __restrict__ g, const float* __restrict__ b){
    __shared__ float sh[32];
    size_t row = blockIdx.x;
    int t = (int)(row % NPAD);
    __nv_bfloat16* ph = oh + row*(size_t)DD;
    __nv_bfloat16* pl = ol + row*(size_t)DD;
    int tx = threadIdx.x;
    __nv_bfloat16 z = __float2bfloat16(0.f);
    if (t < PADF){ ph[tx]=z; ph[tx+256]=z; pl[tx]=z; pl[tx+256]=z; return; }
    const float* p = h + row*(size_t)DD;
    float x0=p[tx], x1=p[tx+256];
    float mu  = bsum(x0+x1, sh) * (1.f/512.f);
    float d0=x0-mu, d1=x1-mu;
    float var = bsum(d0*d0+d1*d1, sh) * (1.f/512.f);
    float rs = rsqrtf(var + 1e-5f);
    float y0 = d0*rs*g[tx]     + b[tx];
    float y1 = d1*rs*g[tx+256] + b[tx+256];
    __nv_bfloat16 h0 = __float2bfloat16(y0);
    __nv_bfloat16 h1 = __float2bfloat16(y1);
    ph[tx]     = h0; pl[tx]     = __float2bfloat16(y0 - __bfloat162float(h0));
    ph[tx+256] = h1; pl[tx+256] = __float2bfloat16(y1 - __bfloat162float(h1));
}

__global__ void lnf_k(const float* __restrict__ h, float* __restrict__ o,
                      const float* __restrict__ g, const float* __restrict__ b){
    __shared__ float sh[32];
    const float* p = h + ((size_t)blockIdx.x*NPAD + PADF)*DD;
    int tx = threadIdx.x;
    float x0=p[tx], x1=p[tx+256];
    float mu  = bsum(x0+x1, sh) * (1.f/512.f);
    float d0=x0-mu, d1=x1-mu;
    float var = bsum(d0*d0+d1*d1, sh) * (1.f/512.f);
    float rs = rsqrtf(var + 1e-5f);
    o[blockIdx.x*DD+tx]     = d0*rs*g[tx]     + b[tx];
    o[blockIdx.x*DD+tx+256] = d1*rs*g[tx+256] + b[tx+256];
}

__global__ void landmarks_k(const float* __restrict__ qkv,
                            float* __restrict__ ql, float* __restrict__ kl){
    int bz=blockIdx.x, m=blockIdx.y, d=threadIdx.x;
    int b=bz>>3, hh=bz&7;
    const float* base = qkv + ((size_t)b*NPAD + (size_t)m*40)*QKVD + hh*64 + d;
    float sq=0.f, sk=0.f;
    #pragma unroll 8
    for (int j=0;j<40;j++){ sq += base[(size_t)j*QKVD]; sk += base[(size_t)j*QKVD+512]; }
    ql[((size_t)bz*MLAND+m)*64+d] = sq*0.003125f;
    kl[((size_t)bz*MLAND+m)*64+d] = sk*0.025f;
}

__global__ void softmax256(float* __restrict__ X){
    __shared__ float sh[32];
    float* p = X + (size_t)blockIdx.x*256;
    float v = p[threadIdx.x];
    float m = bmax(v, sh);
    float e = __expf(v - m);
    float s = bsum(e, sh);
    p[threadIdx.x] = e / s;
}

__global__ void zerok(float* p, int n){
    int i = blockIdx.x*256 + threadIdx.x;
    if (i<n) p[i]=0.f;
}

__global__ void crmax_k(const float* __restrict__ a2, float* mx){
    __shared__ float sh[32];
    const float* p = a2 + (size_t)blockIdx.x*65536;
    int t = threadIdx.x;
    float cs=0.f, rs=0.f;
    for (int m=0;m<256;m++){ cs += p[m*256+t]; rs += p[t*256+m]; }
    float mc = bmax(cs, sh);
    float mr = bmax(rs, sh);
    if (t==0){
        atomicMax((int*)&mx[0], __float_as_int(mc));
        atomicMax((int*)&mx[1], __float_as_int(mr));
    }
}

__global__ void ztrans_k(const float* __restrict__ a2, float* __restrict__ z,
                         const float* __restrict__ mx){
    __shared__ float tile[32][33];
    int bz=blockIdx.x;
    const float* p = a2 + (size_t)bz*65536;
    float* q = z + (size_t)bz*65536;
    int i0=blockIdx.y*32, j0=blockIdx.z*32;
    tile[threadIdx.y][threadIdx.x] = p[(j0+threadIdx.y)*256 + i0+threadIdx.x];
    __syncthreads();
    float inv = 1.f/(mx[0]*mx[1]);
    q[(i0+threadIdx.y)*256 + j0+threadIdx.x] = tile[threadIdx.x][threadIdx.y]*inv;
}

__global__ void resconv_k(const float* __restrict__ qkv, const float* __restrict__ rw,
                          float* __restrict__ mg){
    __shared__ float w[33];
    int bz=blockIdx.y; int b=bz>>3, hh=bz&7;
    if (threadIdx.y==0 && threadIdx.x<33) w[threadIdx.x]=rw[hh*33+threadIdx.x];
    __syncthreads();
    int d=threadIdx.x;
    int t=blockIdx.x*8+threadIdx.y;
    const float* vb = qkv + (size_t)b*NPAD*QKVD + 1024 + hh*64 + d;
    float acc=0.f;
    #pragma unroll
    for (int j=0;j<33;j++){
        int ts=t+j-16;
        if (ts>=0 && ts<NPAD) acc += vb[(size_t)ts*QKVD]*w[j];
    }
    mg[((size_t)b*NPAD+t)*DD + hh*64 + d] += acc;
}

__global__ void t2p_k(const float* __restrict__ h, float* __restrict__ pl){
    __shared__ float tile[32][33];
    int b=blockIdx.x, t0=blockIdx.y*32, c0=blockIdx.z*32;
    int t=t0+threadIdx.y, c=c0+threadIdx.x;
    if (t<10000) tile[threadIdx.y][threadIdx.x] = h[((size_t)b*NPAD+PADF+1+t)*DD + c];
    __syncthreads();
    int ch=c0+threadIdx.y, tt=t0+threadIdx.x;
    if (tt<10000) pl[((size_t)b*DD+ch)*10000 + tt] = tile[threadIdx.x][threadIdx.y];
}
__global__ void p2h_k(const float* __restrict__ pl, float* __restrict__ h){
    __shared__ float tile[32][33];
    int b=blockIdx.x, t0=blockIdx.y*32, c0=blockIdx.z*32;
    int ch=c0+threadIdx.y, tt=t0+threadIdx.x;
    if (tt<10000) tile[threadIdx.y][threadIdx.x] = pl[((size_t)b*DD+ch)*10000 + tt];
    __syncthreads();
    int t=t0+threadIdx.y, c=c0+threadIdx.x;
    if (t<10000) h[((size_t)b*NPAD+PADF+1+t)*DD + c] = tile[threadIdx.x][threadIdx.y];
}

__global__ void ppeg_conv_k(const float* __restrict__ pl, float* __restrict__ po,
    const float* __restrict__ w7, const float* __restrict__ b7,
    const float* __restrict__ w5, const float* __restrict__ b5,
    const float* __restrict__ w3, const float* __restrict__ b3){
    __shared__ float sw[86];
    int plane=blockIdx.x; int ch=plane&511;
    int tx=threadIdx.x;
    if      (tx<49) sw[tx]=w7[ch*49+tx];
    else if (tx<74) sw[tx]=w5[ch*25+tx-49];
    else if (tx<83) sw[tx]=w3[ch*9+tx-74];
    else if (tx==83) sw[83]=b7[ch];
    else if (tx==84) sw[84]=b5[ch];
    else if (tx==85) sw[85]=b3[ch];
    __syncthreads();
    int px=blockIdx.y*256+tx;
    if (px>=10000) return;
    int r=px/100, c=px%100;
    const float* in = pl + (size_t)plane*10000;
    float acc = in[px] + sw[83] + sw[84] + sw[85];
    #pragma unroll
    for (int kr=0;kr<7;kr++){
        int rr=r+kr-3; if (rr<0||rr>=100) continue;
        #pragma unroll
        for (int kc=0;kc<7;kc++){
            int cc=c+kc-3; if (cc<0||cc>=100) continue;
            acc += in[rr*100+cc]*sw[kr*7+kc];
        }
    }
    #pragma unroll
    for (int kr=0;kr<5;kr++){
        int rr=r+kr-2; if (rr<0||rr>=100) continue;
        #pragma unroll
        for (int kc=0;kc<5;kc++){
            int cc=c+kc-2; if (cc<0||cc>=100) continue;
            acc += in[rr*100+cc]*sw[49+kr*5+kc];
        }
    }
    #pragma unroll
    for (int kr=0;kr<3;kr++){
        int rr=r+kr-1; if (rr<0||rr>=100) continue;
        #pragma unroll
        for (int kc=0;kc<3;kc++){
            int cc=c+kc-1; if (cc<0||cc>=100) continue;
            acc += in[rr*100+cc]*sw[74+kr*3+kc];
        }
    }
    po[(size_t)plane*10000+px]=acc;
}

__global__ void head_k(const float* __restrict__ cls, const float* __restrict__ w2,
                       const float* __restrict__ b2, float* out, int osz){
    __shared__ float sh[64];
    int b=blockIdx.x;
    float a0=0.f, a1=0.f;
    for (int d=threadIdx.x; d<512; d+=256){
        float x = cls[b*512+d];
        a0 += x*w2[d*2+0]; a1 += x*w2[d*2+1];
    }
    #pragma unroll
    for (int o=16;o;o>>=1){
        a0 += __shfl_xor_sync(0xffffffffu,a0,o);
        a1 += __shfl_xor_sync(0xffffffffu,a1,o);
    }
    int lane=threadIdx.x&31, wid=threadIdx.x>>5;
    if (lane==0){ sh[wid]=a0; sh[wid+32]=a1; }
    __syncthreads();
    if (threadIdx.x==0){
        float l0=b2[0], l1=b2[1];
        for (int w=0;w<8;w++){ l0+=sh[w]; l1+=sh[w+32]; }
        float m=fmaxf(l0,l1);
        float e0=expf(l0-m), e1=expf(l1-m), s=e0+e1;
        if (b*2+1   < osz){ out[b*2]=l0;      out[b*2+1]=l1; }
        if (4+b*2+1 < osz){ out[4+b*2]=e0/s;  out[4+b*2+1]=e1/s; }
        if (8+b     < osz){ out[8+b] = (l1>l0)?1.f:0.f; }
    }
}

// ----------------- driver -----------------
extern "C" void kernel_launch(void* const* d_in, const int* in_sizes, int n_in,
                              void* d_out, int out_size){
    const float* x    =(const float*)d_in[0];
    const float* wfc1 =(const float*)d_in[1];
    const float* bfc1 =(const float*)d_in[2];
    const float* clst =(const float*)d_in[3];
    const float* lng[2]={(const float*)d_in[4],(const float*)d_in[10]};
    const float* lnb[2]={(const float*)d_in[5],(const float*)d_in[11]};
    const float* qkvw[2]={(const float*)d_in[6],(const float*)d_in[12]};
    const float* outw[2]={(const float*)d_in[7],(const float*)d_in[13]};
    const float* outb[2]={(const float*)d_in[8],(const float*)d_in[14]};
    const float* resw[2]={(const float*)d_in[9],(const float*)d_in[15]};
    const float* pw7=(const float*)d_in[16]; const float* pb7=(const float*)d_in[17];
    const float* pw5=(const float*)d_in[18]; const float* pb5=(const float*)d_in[19];
    const float* pw3=(const float*)d_in[20]; const float* pb3=(const float*)d_in[21];
    const float* lnfg=(const float*)d_in[22]; const float* lnfb=(const float*)d_in[23];
    const float* wfc2=(const float*)d_in[24]; const float* bfc2=(const float*)d_in[25];

    float *h,*qkv,*ql,*kl,*s1,*s3,*a2,*xz,*wb,*tb,*z0,*z1,*a3v,*pz,*mg,*mx,*pm,*ps;
    __nv_bfloat16 *xh,*xl,*lnh,*lnl,*mgh,*mgl,*wth,*wtl;
    cudaGetSymbolAddress((void**)&h,  g_h);
    cudaGetSymbolAddress((void**)&qkv,g_qkv);
    cudaGetSymbolAddress((void**)&ql, g_ql);
    cudaGetSymbolAddress((void**)&kl, g_kl);
    cudaGetSymbolAddress((void**)&s1, g_s1);
    cudaGetSymbolAddress((void**)&s3, g_s3);
    cudaGetSymbolAddress((void**)&a2, g_a2);
    cudaGetSymbolAddress((void**)&xz, g_xz);
    cudaGetSymbolAddress((void**)&wb, g_wb);
    cudaGetSymbolAddress((void**)&tb, g_tb);
    cudaGetSymbolAddress((void**)&z0, g_z0);
    cudaGetSymbolAddress((void**)&z1, g_z1);
    cudaGetSymbolAddress((void**)&a3v,g_a3v);
    cudaGetSymbolAddress((void**)&pz, g_pz);
    cudaGetSymbolAddress((void**)&mg, g_mg);
    cudaGetSymbolAddress((void**)&mx, g_mx);
    cudaGetSymbolAddress((void**)&pm, g_pm);
    cudaGetSymbolAddress((void**)&ps, g_ps);
    cudaGetSymbolAddress((void**)&xh, g_xh);
    cudaGetSymbolAddress((void**)&xl, g_xl);
    cudaGetSymbolAddress((void**)&lnh,g_lnh);
    cudaGetSymbolAddress((void**)&lnl,g_lnl);
    cudaGetSymbolAddress((void**)&mgh,g_mgh);
    cudaGetSymbolAddress((void**)&mgl,g_mgl);
    cudaGetSymbolAddress((void**)&wth,g_wth);
    cudaGetSymbolAddress((void**)&wtl,g_wtl);

    cudaFuncSetAttribute(f1_k, cudaFuncAttributeMaxDynamicSharedMemorySize, F1_SMEM);
    cudaFuncSetAttribute(f2_k, cudaFuncAttributeMaxDynamicSharedMemorySize, F2_SMEM);
    cudaFuncSetAttribute(mm_hmma, cudaFuncAttributeMaxDynamicSharedMemorySize, MMH_SMEM);

    // fc1 on tensor cores (HMMA): split x and W, then h = relu(x @ W + b)
    {
        int n = NB*10000*DIN;
        cvt_k<<<(n+255)/256,256>>>(x, xh, xl, n);
        cvtT_k<<<dim3(DIN/32, DD/32), dim3(32,32)>>>(wfc1, wth, wtl, DIN, DD);
        mm_hmma<<<dim3(4,79,NB),256,MMH_SMEM>>>(xh, xl, wth, wtl,
            h+(size_t)(PADF+1)*DD, bfc1, 10000, DIN, DD,
            (long)10000*DIN, (long)NPAD*DD, FB|FR);
    }
    set_cls<<<NB,512>>>(h, clst);

    for (int L=0; L<2; L++){
        ln_k<<<NB*NPAD,256>>>(h, lnh, lnl, lng[L], lnb[L]);
        // qkv on tensor cores
        cvtT_k<<<dim3(DD/32, QKVD/32), dim3(32,32)>>>(qkvw[L], wth, wtl, DD, QKVD);
        mm_hmma<<<dim3(12,160,1),256,MMH_SMEM>>>(lnh, lnl, wth, wtl,
            qkv, bfc1 /*unused*/, NB*NPAD, DD, QKVD, 0L, 0L, 0);
        landmarks_k<<<dim3(BH,MLAND),64>>>(qkv, ql, kl);
        // s2 = ql @ kl^T -> a2, softmax
        gemm64(ql, kl, a2, nullptr, nullptr,
               256, 256, 64, 64, 64, 256,
               (long)256*64, 0, (long)256*64, 0, (long)65536, 0,
               1, BH, 1.f, 0.f, 1, FTRB);
        softmax256<<<BH*256,256>>>(a2);
        // fused s3 -> online softmax -> @v  (split flash + combine)
        f2_k<<<dim3(4,4,BH),256,F2_SMEM>>>(qkv, ql, s1, pm, ps);
        f2comb_k<<<BH*256,64>>>(s1, pm, ps, a3v);
        // Moore-Penrose pinv of a2
        zerok<<<1,256>>>(mx, 2);
        crmax_k<<<BH,256>>>(a2, mx);
        ztrans_k<<<dim3(BH,8,8),dim3(32,32)>>>(a2, z0, mx);
        float* cur=z0; float* nxt=z1;
        for (int it=0; it<6; it++){
            gemm64(a2, cur, xz, wb, nullptr, 256,256,256, 256,256,256,
                   65536,0, 65536,0, 65536,0, 1, BH, 1.f, 7.f, 1, 0);
            gemm64(xz, wb, nullptr, tb, nullptr, 256,256,256, 256,256,256,
                   65536,0, 65536,0, 65536,0, 1, BH, 1.f, 15.f, 1, 0);
            gemm64(xz, tb, nullptr, wb, nullptr, 256,256,256, 256,256,256,
                   65536,0, 65536,0, 65536,0, 1, BH, 1.f, 13.f, 1, 0);
            gemm64(cur, wb, nxt, nullptr, nullptr, 256,256,256, 256,256,256,
                   65536,0, 65536,0, 65536,0, 1, BH, 0.25f, 0.f, 1, 0);
            float* t=cur; cur=nxt; nxt=t;
        }
        // pz = pinv(a2) @ a3v
        gemm64(cur, a3v, pz, nullptr, nullptr,
               256, 64, 256, 256, 64, 64,
               65536,0, 16384,0, 16384,0, 1, BH, 1.f, 0.f, 1, 0);
        // fused s1 -> softmax -> @pz -> mg
        f1_k<<<dim3(160,BH),256,F1_SMEM>>>(qkv, kl, pz, mg);
        resconv_k<<<dim3(NPAD/8,BH),dim3(64,8)>>>(qkv, resw[L], mg);
        // out-proj on tensor cores: h += mg @ w_out + b_out
        {
            int n = NB*NPAD*DD;
            cvt_k<<<(n+255)/256,256>>>(mg, mgh, mgl, n);
            cvtT_k<<<dim3(DD/32, DD/32), dim3(32,32)>>>(outw[L], wth, wtl, DD, DD);
            mm_hmma<<<dim3(4,79,NB),256,MMH_SMEM>>>(
                mgh+(size_t)PADF*DD, mgl+(size_t)PADF*DD, wth, wtl,
                h+(size_t)PADF*DD, outb[L], 10001, DD, DD,
                (long)NPAD*DD, (long)NPAD*DD, FB|FACC);
        }
        if (L==0){
            t2p_k<<<dim3(NB,313,16),dim3(32,32)>>>(h, s1);
            ppeg_conv_k<<<dim3(NB*512,40),256>>>(s1, s3, pw7,pb7, pw5,pb5, pw3,pb3);
            p2h_k<<<dim3(NB,313,16),dim3(32,32)>>>(s3, h);
        }
    }
    lnf_k<<<NB,256>>>(h, a2, lnfg, lnfb);
    head_k<<<NB,256>>>(a2, wfc2, bfc2, (float*)d_out, out_size);
}

// round 13
// speedup vs baseline: 1.7691x; 1.0993x over previous
#include <cuda_runtime.h>
#include <cuda_bf16.h>
#include <cfloat>
#include <cstdint>

#define NB    2
#define DIN   1024
#define DD    512
#define NPAD  10240
#define PADF  239
#define QKVD  1536
#define MLAND 256
#define BH    16

#define FB    1
#define FR    2
#define FACC  4
#define FAT   8
#define FTRB  16

// pinv epilogue flags
#define PF_F  1
#define PF_A  2
#define PF_BV 4
#define PF_BD 8

#define PSZ 65536
#define PT  (16*PSZ)

// ----------------- device scratch -----------------
__device__ float g_h  [(size_t)NB*NPAD*DD];
__device__ float g_qkv[(size_t)NB*NPAD*QKVD];
__device__ float g_ql [BH*MLAND*64];
__device__ float g_kl [BH*MLAND*64];
__device__ float g_s1 [(size_t)BH*NPAD*MLAND];   // reused: F2 partials, PPEG planar
__device__ float g_s3 [(size_t)BH*MLAND*NPAD];   // reused: PPEG planar
__device__ float g_a2 [BH*MLAND*MLAND];
__device__ float g_z0 [BH*MLAND*MLAND];          // fp32 final pinv (zf)
__device__ float g_a3v[BH*MLAND*64];
__device__ float g_pz [BH*MLAND*64];
__device__ float g_mg [(size_t)NB*NPAD*DD];
__device__ float g_mx [2];
__device__ float g_pm [BH*4*MLAND];
__device__ float g_ps [BH*4*MLAND];

// bf16 hi/lo operands for tensor-core GEMMs
__device__ __align__(16) __nv_bfloat16 g_xh [(size_t)NB*10000*DIN];
__device__ __align__(16) __nv_bfloat16 g_xl [(size_t)NB*10000*DIN];
__device__ __align__(16) __nv_bfloat16 g_lnh[(size_t)NB*NPAD*DD];
__device__ __align__(16) __nv_bfloat16 g_lnl[(size_t)NB*NPAD*DD];
__device__ __align__(16) __nv_bfloat16 g_mgh[(size_t)NB*NPAD*DD];
__device__ __align__(16) __nv_bfloat16 g_mgl[(size_t)NB*NPAD*DD];
__device__ __align__(16) __nv_bfloat16 g_wth[786432];
__device__ __align__(16) __nv_bfloat16 g_wtl[786432];

// pinv hi/lo buffers (A-layout = [m][k] row-major; B-layout = [n][k] = transposed)
__device__ __align__(16) __nv_bfloat16 g_pa2h[PT], g_pa2l[PT];
__device__ __align__(16) __nv_bfloat16 g_pxzh[PT], g_pxzl[PT];
__device__ __align__(16) __nv_bfloat16 g_pwbh[PT], g_pwbl[PT];
__device__ __align__(16) __nv_bfloat16 g_ptbh[PT], g_ptbl[PT];
__device__ __align__(16) __nv_bfloat16 g_pzah0[PT], g_pzal0[PT], g_pzbh0[PT], g_pzbl0[PT];
__device__ __align__(16) __nv_bfloat16 g_pzah1[PT], g_pzal1[PT], g_pzbh1[PT], g_pzbl1[PT];

// ----------------- fast exp2 (FFMA-only, rel err ~8e-6) -----------------
__device__ __forceinline__ float fexp2(float y){
    y = fmaxf(y, -120.f);
    float fl = floorf(y);
    float f = y - fl;
    float p = 1.54036e-4f;
    p = fmaf(p, f, 1.33336e-3f);
    p = fmaf(p, f, 9.61813e-3f);
    p = fmaf(p, f, 5.55041e-2f);
    p = fmaf(p, f, 2.40227e-1f);
    p = fmaf(p, f, 6.93147e-1f);
    p = fmaf(p, f, 1.0f);
    return p * __int_as_float(((int)fl + 127) << 23);
}

// ----------------- helpers -----------------
__device__ __forceinline__ uint32_t smem_u32(const void* p){
    uint32_t a;
    asm("{ .reg .u64 t; cvta.to.shared.u64 t, %1; cvt.u32.u64 %0, t; }" : "=r"(a) : "l"(p));
    return a;
}
__device__ __forceinline__ void cpasync16(uint32_t d, const void* s, int sz){
    asm volatile("cp.async.cg.shared.global [%0], [%1], 16, %2;"
        :: "r"(d), "l"(s), "r"(sz) : "memory");
}
__device__ __forceinline__ void ldmx4(uint32_t* r, uint32_t a){
    asm volatile("ldmatrix.sync.aligned.m8n8.x4.shared.b16 {%0,%1,%2,%3},[%4];"
        : "=r"(r[0]), "=r"(r[1]), "=r"(r[2]), "=r"(r[3]) : "r"(a));
}
__device__ __forceinline__ void mma_bf16(float* c, const uint32_t* a, uint32_t b0, uint32_t b1){
    asm volatile("mma.sync.aligned.m16n8k16.row.col.f32.bf16.bf16.f32 "
        "{%0,%1,%2,%3},{%4,%5,%6,%7},{%8,%9},{%0,%1,%2,%3};"
        : "+f"(c[0]), "+f"(c[1]), "+f"(c[2]), "+f"(c[3])
        : "r"(a[0]), "r"(a[1]), "r"(a[2]), "r"(a[3]), "r"(b0), "r"(b1));
}
__device__ __forceinline__ void hilo_st(float v, __nv_bfloat16* H, __nv_bfloat16* L, long i){
    __nv_bfloat16 h = __float2bfloat16(v);
    H[i] = h;
    L[i] = __float2bfloat16(v - __bfloat162float(h));
}

// ----------------- HMMA GEMM: C = A @ B^T (hi/lo bf16, fp32 acc) -----------------
#define MMH_TS   (128*72)
#define MMH_BUFB (4*MMH_TS*2)
#define MMH_SMEM (2*MMH_BUFB)
__global__ void __launch_bounds__(256, 1)
mm_hmma(const __nv_bfloat16* __restrict__ Ah, const __nv_bfloat16* __restrict__ Al,
        const __nv_bfloat16* __restrict__ Bh, const __nv_bfloat16* __restrict__ Bl,
        float* __restrict__ C, const float* __restrict__ bias,
        int M, int K, int ldc, long sA, long sC, int flags)
{
    extern __shared__ __nv_bfloat16 smb[];
    uint32_t sbase = smem_u32(smb);
    int tid = threadIdx.x, wid = tid >> 5, lane = tid & 31;
    int col0 = blockIdx.x * 128, row0 = blockIdx.y * 128;
    long bz = blockIdx.z;
    Ah += bz * sA;  Al += bz * sA;
    float* Cb = C + bz * sC;

    int wm = wid & 3, wn = wid >> 2;
    float acc[2][8][4] = {};
    const int S = K >> 6;

    auto issue = [&](int s){
        int b = s & 1;
        uint32_t dst = sbase + (uint32_t)b * MMH_BUFB;
        int k0 = s << 6;
        #pragma unroll
        for (int i = 0; i < 4; i++){
            int ch = tid + i*256;
            int r = ch >> 3, c8 = ch & 7;
            uint32_t off = (uint32_t)(r*144 + c8*16);
            int gm = row0 + r;
            const __nv_bfloat16* pah = Ah + (long)gm*K + k0 + c8*8;
            const __nv_bfloat16* pal = Al + (long)gm*K + k0 + c8*8;
            int sz = (gm < M) ? 16 : 0;
            cpasync16(dst + off,              pah, sz);
            cpasync16(dst + MMH_TS*2 + off,   pal, sz);
            long gn = col0 + r;
            cpasync16(dst + 2*MMH_TS*2 + off, Bh + gn*K + k0 + c8*8, 16);
            cpasync16(dst + 3*MMH_TS*2 + off, Bl + gn*K + k0 + c8*8, 16);
        }
        asm volatile("cp.async.commit_group;" ::: "memory");
    };

    issue(0);
    for (int s = 0; s < S; s++){
        if (s + 1 < S){
            issue(s + 1);
            asm volatile("cp.async.wait_group 1;" ::: "memory");
        } else {
            asm volatile("cp.async.wait_group 0;" ::: "memory");
        }
        __syncthreads();
        uint32_t buf = sbase + (uint32_t)(s & 1) * MMH_BUFB;
        uint32_t aH = buf, aL = buf + MMH_TS*2;
        uint32_t bHb = buf + 2*MMH_TS*2, bLb = buf + 3*MMH_TS*2;
        #pragma unroll
        for (int ks = 0; ks < 4; ks++){
            int kc = ks * 16;
            uint32_t ah[2][4], al[2][4];
            #pragma unroll
            for (int mi = 0; mi < 2; mi++){
                int rowb = wm*32 + mi*16 + (lane & 15);
                uint32_t o = (uint32_t)(rowb*144 + kc*2 + (lane >> 4)*16);
                ldmx4(ah[mi], aH + o);
                ldmx4(al[mi], aL + o);
            }
            #pragma unroll
            for (int nb = 0; nb < 4; nb++){
                int g = lane >> 3;
                int rown = wn*64 + nb*16 + (g >> 1)*8 + (lane & 7);
                uint32_t bo = (uint32_t)(rown*144 + kc*2 + (g & 1)*16);
                uint32_t bh[4], bl[4];
                ldmx4(bh, bHb + bo);
                ldmx4(bl, bLb + bo);
                #pragma unroll
                for (int mi = 0; mi < 2; mi++){
                    #pragma unroll
                    for (int hf = 0; hf < 2; hf++){
                        float* c = acc[mi][nb*2 + hf];
                        mma_bf16(c, ah[mi], bh[hf*2], bh[hf*2+1]);
                        mma_bf16(c, ah[mi], bl[hf*2], bl[hf*2+1]);
                        mma_bf16(c, al[mi], bh[hf*2], bh[hf*2+1]);
                    }
                }
            }
        }
        __syncthreads();
    }

    int gID = lane >> 2, tig = lane & 3;
    #pragma unroll
    for (int mi = 0; mi < 2; mi++){
        #pragma unroll
        for (int nj = 0; nj < 8; nj++){
            int colb = col0 + wn*64 + nj*8 + tig*2;
            #pragma unroll
            for (int rh = 0; rh < 2; rh++){
                int gm = row0 + wm*32 + mi*16 + rh*8 + gID;
                if (gm >= M) continue;
                float v0 = acc[mi][nj][rh*2+0];
                float v1 = acc[mi][nj][rh*2+1];
                float* cp = Cb + (long)gm*ldc + colb;
                if (flags & FB){ v0 += bias[colb]; v1 += bias[colb+1]; }
                if (flags & FACC){ v0 += cp[0]; v1 += cp[1]; }
                if (flags & FR){ v0 = fmaxf(v0, 0.f); v1 = fmaxf(v1, 0.f); }
                cp[0] = v0; cp[1] = v1;
            }
        }
    }
}

// ----------------- HMMA pinv GEMM: 16 batches of 256x256x256 -----------------
// A hi/lo row-major [m][k]; B hi/lo transposed layout [n][k]. grid (2,2,16).
// Epilogue: v = alpha*acc. Flags: PF_F -> Cf[m][n]=v; PF_A -> X hilo [m][n]=v;
// PF_BV -> Y hilo [n][m]=v; PF_BD -> Y hilo [n][m]=dval*I - v.
__global__ void __launch_bounds__(256, 1)
mm_pinv(const __nv_bfloat16* __restrict__ Ah, const __nv_bfloat16* __restrict__ Al,
        const __nv_bfloat16* __restrict__ Bh, const __nv_bfloat16* __restrict__ Bl,
        float* __restrict__ Cf,
        __nv_bfloat16* __restrict__ Xh, __nv_bfloat16* __restrict__ Xl,
        __nv_bfloat16* __restrict__ Yh, __nv_bfloat16* __restrict__ Yl,
        float alpha, float dval, int flags)
{
    extern __shared__ __nv_bfloat16 smb[];
    uint32_t sbase = smem_u32(smb);
    int tid = threadIdx.x, wid = tid >> 5, lane = tid & 31;
    int col0 = blockIdx.x * 128, row0 = blockIdx.y * 128;
    long off = (long)blockIdx.z * PSZ;
    Ah += off; Al += off; Bh += off; Bl += off;

    int wm = wid & 3, wn = wid >> 2;
    float acc[2][8][4] = {};

    auto issue = [&](int s){
        uint32_t dst = sbase + (uint32_t)(s & 1) * MMH_BUFB;
        int k0 = s << 6;
        #pragma unroll
        for (int i = 0; i < 4; i++){
            int ch = tid + i*256;
            int r = ch >> 3, c8 = ch & 7;
            uint32_t o2 = (uint32_t)(r*144 + c8*16);
            cpasync16(dst + o2,              Ah + (long)(row0+r)*256 + k0 + c8*8, 16);
            cpasync16(dst + MMH_TS*2 + o2,   Al + (long)(row0+r)*256 + k0 + c8*8, 16);
            cpasync16(dst + 2*MMH_TS*2 + o2, Bh + (long)(col0+r)*256 + k0 + c8*8, 16);
            cpasync16(dst + 3*MMH_TS*2 + o2, Bl + (long)(col0+r)*256 + k0 + c8*8, 16);
        }
        asm volatile("cp.async.commit_group;" ::: "memory");
    };

    issue(0);
    for (int s = 0; s < 4; s++){
        if (s + 1 < 4){
            issue(s + 1);
            asm volatile("cp.async.wait_group 1;" ::: "memory");
        } else {
            asm volatile("cp.async.wait_group 0;" ::: "memory");
        }
        __syncthreads();
        uint32_t buf = sbase + (uint32_t)(s & 1) * MMH_BUFB;
        uint32_t aH = buf, aL = buf + MMH_TS*2;
        uint32_t bHb = buf + 2*MMH_TS*2, bLb = buf + 3*MMH_TS*2;
        #pragma unroll
        for (int ks = 0; ks < 4; ks++){
            int kc = ks * 16;
            uint32_t ah[2][4], al[2][4];
            #pragma unroll
            for (int mi = 0; mi < 2; mi++){
                int rowb = wm*32 + mi*16 + (lane & 15);
                uint32_t o = (uint32_t)(rowb*144 + kc*2 + (lane >> 4)*16);
                ldmx4(ah[mi], aH + o);
                ldmx4(al[mi], aL + o);
            }
            #pragma unroll
            for (int nb = 0; nb < 4; nb++){
                int g = lane >> 3;
                int rown = wn*64 + nb*16 + (g >> 1)*8 + (lane & 7);
                uint32_t bo = (uint32_t)(rown*144 + kc*2 + (g & 1)*16);
                uint32_t bh[4], bl[4];
                ldmx4(bh, bHb + bo);
                ldmx4(bl, bLb + bo);
                #pragma unroll
                for (int mi = 0; mi < 2; mi++){
                    #pragma unroll
                    for (int hf = 0; hf < 2; hf++){
                        float* c = acc[mi][nb*2 + hf];
                        mma_bf16(c, ah[mi], bh[hf*2], bh[hf*2+1]);
                        mma_bf16(c, ah[mi], bl[hf*2], bl[hf*2+1]);
                        mma_bf16(c, al[mi], bh[hf*2], bh[hf*2+1]);
                    }
                }
            }
        }
        __syncthreads();
    }

    int gID = lane >> 2, tig = lane & 3;
    #pragma unroll
    for (int mi = 0; mi < 2; mi++){
        #pragma unroll
        for (int nj = 0; nj < 8; nj++){
            int cb = col0 + wn*64 + nj*8 + tig*2;
            #pragma unroll
            for (int rh = 0; rh < 2; rh++){
                int gm = row0 + wm*32 + mi*16 + rh*8 + gID;
                float v0 = acc[mi][nj][rh*2+0]*alpha;
                float v1 = acc[mi][nj][rh*2+1]*alpha;
                long i0 = off + (long)gm*256 + cb;
                if (flags & PF_F){ Cf[i0] = v0; Cf[i0+1] = v1; }
                if (flags & PF_A){
                    hilo_st(v0, Xh, Xl, i0);
                    hilo_st(v1, Xh, Xl, i0+1);
                }
                if (flags & (PF_BV|PF_BD)){
                    float w0 = v0, w1 = v1;
                    if (flags & PF_BD){
                        w0 = ((gm==cb  )?dval:0.f) - v0;
                        w1 = ((gm==cb+1)?dval:0.f) - v1;
                    }
                    long j0 = off + (long)cb*256 + gm;
                    hilo_st(w0, Yh, Yl, j0);
                    hilo_st(w1, Yh, Yl, j0+256);
                }
            }
        }
    }
}

// ----------------- hi/lo split conversions -----------------
__global__ void cvt_k(const float* __restrict__ s, __nv_bfloat16* __restrict__ hi,
                      __nv_bfloat16* __restrict__ lo, int n){
    int i = blockIdx.x*256 + threadIdx.x;
    if (i < n){
        float v = s[i];
        __nv_bfloat16 h = __float2bfloat16(v);
        hi[i] = h;
        lo[i] = __float2bfloat16(v - __bfloat162float(h));
    }
}
// W[K][N] -> WT hi/lo [N][K]
__global__ void cvtT_k(const float* __restrict__ W, __nv_bfloat16* __restrict__ th,
                       __nv_bfloat16* __restrict__ tl, int K, int N){
    __shared__ float t[32][33];
    int k0 = blockIdx.x*32, n0 = blockIdx.y*32;
    t[threadIdx.y][threadIdx.x] = W[(k0+threadIdx.y)*N + n0+threadIdx.x];
    __syncthreads();
    int n = n0+threadIdx.y, k = k0+threadIdx.x;
    float v = t[threadIdx.x][threadIdx.y];
    __nv_bfloat16 h = __float2bfloat16(v);
    th[(size_t)n*K+k] = h;
    tl[(size_t)n*K+k] = __float2bfloat16(v - __bfloat162float(h));
}

// ----------------- block reductions -----------------
__device__ __forceinline__ float bsum(float v, float* sh){
    int lane = threadIdx.x & 31, wid = threadIdx.x >> 5;
    #pragma unroll
    for (int o=16;o;o>>=1) v += __shfl_xor_sync(0xffffffffu, v, o);
    if (lane==0) sh[wid]=v;
    __syncthreads();
    if (wid==0){
        int nw = blockDim.x >> 5;
        float r = (lane<nw) ? sh[lane] : 0.f;
        #pragma unroll
        for (int o=16;o;o>>=1) r += __shfl_xor_sync(0xffffffffu, r, o);
        if (lane==0) sh[0]=r;
    }
    __syncthreads();
    float out = sh[0];
    __syncthreads();
    return out;
}
__device__ __forceinline__ float bmax(float v, float* sh){
    int lane = threadIdx.x & 31, wid = threadIdx.x >> 5;
    #pragma unroll
    for (int o=16;o;o>>=1) v = fmaxf(v, __shfl_xor_sync(0xffffffffu, v, o));
    if (lane==0) sh[wid]=v;
    __syncthreads();
    if (wid==0){
        int nw = blockDim.x >> 5;
        float r = (lane<nw) ? sh[lane] : -FLT_MAX;
        #pragma unroll
        for (int o=16;o;o>>=1) r = fmaxf(r, __shfl_xor_sync(0xffffffffu, r, o));
        if (lane==0) sh[0]=r;
    }
    __syncthreads();
    float out = sh[0];
    __syncthreads();
    return out;
}

// ----------------- fp32 batched GEMM (small paths) -----------------
template<int BM,int BN,int BK,int TM,int TN,int MAXB>
__global__ void __launch_bounds__((BM/TM)*(BN/TN), MAXB)
gemm_k(const float* __restrict__ A, const float* __restrict__ Bp,
       float* C, float* C2, const float* __restrict__ bias,
       int M,int N,int K,int lda,int ldb,int ldc,
       long sA1,long sA2,long sB1,long sB2,long sC1,long sC2,
       int nh,float alpha,float dval,int nTN,int kSplit,int flags)
{
    constexpr int THREADS=(BM/TM)*(BN/TN);
    constexpr int LA = BM*BK/THREADS;
    constexpr int LB = BK*BN/THREADS;
    __shared__ float As[2][BK][BM];
    __shared__ float Bs[2][BK][BN+1];
    int bz=blockIdx.z;
    A  += (long)(bz/nh)*sA1 + (long)(bz%nh)*sA2;
    Bp += (long)(bz/nh)*sB1 + (long)(bz%nh)*sB2;
    long offC = (long)(bz/nh)*sC1 + (long)(bz%nh)*sC2;
    int kIdx=blockIdx.x/nTN;
    int col0=(blockIdx.x%nTN)*BN;
    int row0=blockIdx.y*BM;
    int kChunk=(K+kSplit-1)/kSplit;
    int k0=kIdx*kChunk, k1=min(K,k0+kChunk);
    int tid=threadIdx.x;
    int tm=tid/(BN/TN), tn=tid%(BN/TN);
    bool trb = (flags & FTRB) != 0;
    float acc[TM][TN] = {};
    float pa[LA], pb[LB];

    auto loadT = [&](int kk){
        #pragma unroll
        for (int it=0; it<LA; it++){
            int i=tid+it*THREADS;
            int m=i/BK, k=i%BK;
            int gm=row0+m, gk=kk+k;
            pa[it] = (gm<M && gk<k1) ? A[(long)gm*lda+gk] : 0.f;
        }
        #pragma unroll
        for (int it=0; it<LB; it++){
            int i=tid+it*THREADS;
            int k,n;
            if (trb){ n=i/BK; k=i%BK; } else { k=i/BN; n=i%BN; }
            int gk=kk+k, gn=col0+n;
            pb[it] = (gk<k1 && gn<N) ? (trb ? Bp[(long)gn*ldb+gk] : Bp[(long)gk*ldb+gn]) : 0.f;
        }
    };
    auto storeT = [&](int b){
        #pragma unroll
        for (int it=0; it<LA; it++){
            int i=tid+it*THREADS;
            int m=i/BK, k=i%BK;
            As[b][k][m]=pa[it];
        }
        #pragma unroll
        for (int it=0; it<LB; it++){
            int i=tid+it*THREADS;
            int k,n;
            if (trb){ n=i/BK; k=i%BK; } else { k=i/BN; n=i%BN; }
            Bs[b][k][n]=pb[it];
        }
    };

    loadT(k0);
    storeT(0);
    __syncthreads();
    int buf=0;
    for (int kk=k0; kk<k1; kk+=BK){
        bool hn = (kk+BK) < k1;
        if (hn) loadT(kk+BK);
        #pragma unroll
        for (int k=0;k<BK;k++){
            float ra[TM], rb[TN];
            #pragma unroll
            for (int i=0;i<TM;i++) ra[i]=As[buf][k][tm*TM+i];
            #pragma unroll
            for (int j=0;j<TN;j++) rb[j]=Bs[buf][k][tn*TN+j];
            #pragma unroll
            for (int i=0;i<TM;i++)
                #pragma unroll
                for (int j=0;j<TN;j++) acc[i][j] += ra[i]*rb[j];
        }
        if (hn) storeT(buf^1);
        __syncthreads();
        buf^=1;
    }
    #pragma unroll
    for (int i=0;i<TM;i++){
        int gm=row0+tm*TM+i; if (gm>=M) continue;
        #pragma unroll
        for (int j=0;j<TN;j++){
            int gn=col0+tn*TN+j; if (gn>=N) continue;
            float v = acc[i][j]*alpha;
            if (flags&FB) v += bias[gn];
            long idx = offC + (long)gm*ldc + gn;
            if (C2) C2[idx] = ((gm==gn)?dval:0.f) - v;
            if (C){
                if (flags&FAT) atomicAdd(&C[idx], v);
                else {
                    float o = v;
                    if (flags&FACC) o += C[idx];
                    if (flags&FR)   o = fmaxf(o, 0.f);
                    C[idx] = o;
                }
            }
        }
    }
}

static void gemm64(const float*A,const float*B,float*C,float*C2,const float*bias,
    int M,int N,int K,int lda,int ldb,int ldc,
    long a1,long a2,long b1,long b2,long c1,long c2,int nh,int batch,
    float alpha,float dval,int kSplit,int flags)
{
    int nTN=(N+63)/64, nTM=(M+63)/64;
    dim3 g(nTN*kSplit, nTM, batch);
    gemm_k<64,64,16,4,4,2><<<g,256>>>(A,B,C,C2,bias,M,N,K,lda,ldb,ldc,
        a1,a2,b1,b2,c1,c2,nh,alpha,dval,nTN,kSplit,flags);
}

// ----------------- F1: fused s1 = q@kl^T -> softmax -> @pz -> mg -----------------
#define F1_SMEM ((64*68 + 64*260 + 256*68)*4)
__global__ void __launch_bounds__(256,1)
f1_k(const float* __restrict__ qkv, const float* __restrict__ kl,
     const float* __restrict__ pz, float* __restrict__ mg)
{
    extern __shared__ float sm[];
    float* sq  = sm;
    float* skl = sm + 64*68;
    float* sa  = skl + 64*260;
    int bh = blockIdx.y, b = bh>>3, h = bh&7;
    int row0 = blockIdx.x*64;
    int tid = threadIdx.x;

    for (int i=tid;i<4096;i+=256){
        int m=i>>6, k=i&63;
        sq[k*68+m] = qkv[((size_t)b*NPAD + row0+m)*QKVD + h*64 + k];
    }
    const float* klb = kl + (size_t)bh*16384;
    for (int i=tid;i<16384;i+=256){
        int j=i>>6, k=i&63;
        skl[k*260+j] = klb[i];
    }
    __syncthreads();

    int tm=tid>>4, tn=tid&15;
    float acc[4][16] = {};
    #pragma unroll 4
    for (int k=0;k<64;k++){
        float ra[4], rb[16];
        #pragma unroll
        for (int x=0;x<4;x++)  ra[x]=sq[k*68+tm*4+x];
        #pragma unroll
        for (int x=0;x<16;x++) rb[x]=skl[k*260+tn*16+x];
        #pragma unroll
        for (int i=0;i<4;i++)
            #pragma unroll
            for (int j=0;j<16;j++) acc[i][j] += ra[i]*rb[j];
    }
    const float C1 = 0.125f*1.44269504f;
    #pragma unroll
    for (int mi=0;mi<4;mi++){
        float mx = acc[mi][0];
        #pragma unroll
        for (int j=1;j<16;j++) mx = fmaxf(mx, acc[mi][j]);
        #pragma unroll
        for (int o=8;o;o>>=1) mx = fmaxf(mx, __shfl_xor_sync(0xffffffffu, mx, o));
        float p[16], s=0.f;
        #pragma unroll
        for (int j=0;j<16;j++){ p[j] = fexp2((acc[mi][j]-mx)*C1); s += p[j]; }
        #pragma unroll
        for (int o=8;o;o>>=1) s += __shfl_xor_sync(0xffffffffu, s, o);
        float inv = 1.f/s;
        #pragma unroll
        for (int j=0;j<16;j++) sa[(tn*16+j)*68 + tm*4+mi] = p[j]*inv;
    }
    __syncthreads();
    const float* pzb = pz + (size_t)bh*16384;
    for (int i=tid;i<16384;i+=256) skl[i] = pzb[i];
    __syncthreads();
    float o2[4][4] = {};
    #pragma unroll 8
    for (int j=0;j<256;j++){
        float ra[4], rb[4];
        #pragma unroll
        for (int x=0;x<4;x++) ra[x]=sa[j*68+tm*4+x];
        #pragma unroll
        for (int x=0;x<4;x++) rb[x]=skl[j*64+tn*4+x];
        #pragma unroll
        for (int i=0;i<4;i++)
            #pragma unroll
            for (int d=0;d<4;d++) o2[i][d] += ra[i]*rb[d];
    }
    #pragma unroll
    for (int i=0;i<4;i++){
        size_t base = ((size_t)b*NPAD + row0 + tm*4+i)*DD + h*64 + tn*4;
        #pragma unroll
        for (int d=0;d<4;d++) mg[base+d] = o2[i][d];
    }
}

// ----------------- F2: split flash  out_part = softmax(ql@k^T) @ v -----------------
#define F2_SMEM ((64*68 + 64*68 + 64*64 + 64*68)*4)
__global__ void __launch_bounds__(256,1)
f2_k(const float* __restrict__ qkv, const float* __restrict__ ql,
     float* __restrict__ pout, float* __restrict__ pm, float* __restrict__ ps)
{
    extern __shared__ float sm[];
    float* sql = sm;
    float* sk  = sm + 64*68;
    float* sv  = sk + 64*68;
    float* sp  = sv + 64*64;
    int split = blockIdx.x, rt = blockIdx.y, bh = blockIdx.z;
    int b = bh>>3, h = bh&7;
    int row0 = rt*64;
    int tid = threadIdx.x;
    int tm = tid>>4, tn = tid&15;

    const float* qlb = ql + (size_t)bh*16384;
    for (int i=tid;i<4096;i+=256){
        int m=i>>6, k=i&63;
        sql[k*68+m] = qlb[(row0+m)*64 + k];
    }
    const float* kp = qkv + (size_t)b*NPAD*QKVD + 512  + h*64;
    const float* vp = qkv + (size_t)b*NPAD*QKVD + 1024 + h*64;

    float out[4][4] = {};
    float m_run[4] = {-1e30f,-1e30f,-1e30f,-1e30f};
    float s_run[4] = {};
    const float LOG2E = 1.44269504f;
    int t0 = split*2560;

    for (int c=0;c<40;c++){
        int tc = t0 + c*64;
        __syncthreads();
        for (int i=tid;i<4096;i+=256){
            int t=i>>6, k=i&63;
            sk[k*68+t] = kp[(size_t)(tc+t)*QKVD + k];
            sv[t*64+k] = vp[(size_t)(tc+t)*QKVD + k];
        }
        __syncthreads();
        float s[4][4] = {};
        #pragma unroll 8
        for (int k=0;k<64;k++){
            float ra[4], rb[4];
            #pragma unroll
            for (int x=0;x<4;x++) ra[x]=sql[k*68+tm*4+x];
            #pragma unroll
            for (int x=0;x<4;x++) rb[x]=sk[k*68+tn*4+x];
            #pragma unroll
            for (int i=0;i<4;i++)
                #pragma unroll
                for (int j=0;j<4;j++) s[i][j] += ra[i]*rb[j];
        }
        #pragma unroll
        for (int mi=0;mi<4;mi++){
            float cm = fmaxf(fmaxf(s[mi][0],s[mi][1]), fmaxf(s[mi][2],s[mi][3]));
            #pragma unroll
            for (int o=8;o;o>>=1) cm = fmaxf(cm, __shfl_xor_sync(0xffffffffu, cm, o));
            float nm = fmaxf(m_run[mi], cm);
            float fac = fexp2((m_run[mi]-nm)*LOG2E);
            m_run[mi] = nm;
            s_run[mi] *= fac;
            #pragma unroll
            for (int d=0;d<4;d++) out[mi][d] *= fac;
            float ls = 0.f;
            #pragma unroll
            for (int ti=0;ti<4;ti++){
                float p = fexp2((s[mi][ti]-nm)*LOG2E);
                sp[(tn*4+ti)*68 + tm*4+mi] = p;
                ls += p;
            }
            #pragma unroll
            for (int o=8;o;o>>=1) ls += __shfl_xor_sync(0xffffffffu, ls, o);
            s_run[mi] += ls;
        }
        __syncthreads();
        #pragma unroll 8
        for (int t=0;t<64;t++){
            float ra[4], rb[4];
            #pragma unroll
            for (int x=0;x<4;x++) ra[x]=sp[t*68+tm*4+x];
            #pragma unroll
            for (int x=0;x<4;x++) rb[x]=sv[t*64+tn*4+x];
            #pragma unroll
            for (int i=0;i<4;i++)
                #pragma unroll
                for (int d=0;d<4;d++) out[i][d] += ra[i]*rb[d];
        }
    }
    #pragma unroll
    for (int mi=0;mi<4;mi++){
        int gr = row0 + tm*4+mi;
        size_t base = (((size_t)bh*4 + split)*256 + gr)*64 + tn*4;
        #pragma unroll
        for (int d=0;d<4;d++) pout[base+d] = out[mi][d];
        if (tn==0){
            pm[(bh*4+split)*256+gr] = m_run[mi];
            ps[(bh*4+split)*256+gr] = s_run[mi];
        }
    }
}

__global__ void f2comb_k(const float* __restrict__ pout, const float* __restrict__ pm,
                         const float* __restrict__ ps, float* __restrict__ a3v)
{
    int bh = blockIdx.x>>8, r = blockIdx.x&255, d = threadIdx.x;
    float M = -1e30f;
    #pragma unroll
    for (int s=0;s<4;s++) M = fmaxf(M, pm[(bh*4+s)*256+r]);
    float S = 0.f, o = 0.f;
    #pragma unroll
    for (int s=0;s<4;s++){
        float w = __expf(pm[(bh*4+s)*256+r] - M);
        S += ps[(bh*4+s)*256+r]*w;
        o += pout[(((size_t)bh*4+s)*256 + r)*64 + d]*w;
    }
    a3v[((size_t)bh*256+r)*64+d] = o/S;
}

// ----------------- elementwise / reduction kernels -----------------
__global__ void set_cls(float* h, const float* __restrict__ cls){
    h[((size_t)blockIdx.x*NPAD + PADF)*DD + threadIdx.x] = cls[threadIdx.x];
}

// layernorm -> bf16 hi/lo split (zeros for front-pad rows)
__global__ void ln_k(const float* __restrict__ h, __nv_bfloat16* __restrict__ oh,
                     __nv_bfloat16* __restrict__ ol,
                     const float* __restrict__ g, const float* __restrict__ b){
    __shared__ float sh[32];
    size_t row = blockIdx.x;
    int t = (int)(row % NPAD);
    __nv_bfloat16* ph = oh + row*(size_t)DD;
    __nv_bfloat16* pl = ol + row*(size_t)DD;
    int tx = threadIdx.x;
    __nv_bfloat16 z = __float2bfloat16(0.f);
    if (t < PADF){ ph[tx]=z; ph[tx+256]=z; pl[tx]=z; pl[tx+256]=z; return; }
    const float* p = h + row*(size_t)DD;
    float x0=p[tx], x1=p[tx+256];
    float mu  = bsum(x0+x1, sh) * (1.f/512.f);
    float d0=x0-mu, d1=x1-mu;
    float var = bsum(d0*d0+d1*d1, sh) * (1.f/512.f);
    float rs = rsqrtf(var + 1e-5f);
    float y0 = d0*rs*g[tx]     + b[tx];
    float y1 = d1*rs*g[tx+256] + b[tx+256];
    __nv_bfloat16 h0 = __float2bfloat16(y0);
    __nv_bfloat16 h1 = __float2bfloat16(y1);
    ph[tx]     = h0; pl[tx]     = __float2bfloat16(y0 - __bfloat162float(h0));
    ph[tx+256] = h1; pl[tx+256] = __float2bfloat16(y1 - __bfloat162float(h1));
}

__global__ void lnf_k(const float* __restrict__ h, float* __restrict__ o,
                      const float* __restrict__ g, const float* __restrict__ b){
    __shared__ float sh[32];
    const float* p = h + ((size_t)blockIdx.x*NPAD + PADF)*DD;
    int tx = threadIdx.x;
    float x0=p[tx], x1=p[tx+256];
    float mu  = bsum(x0+x1, sh) * (1.f/512.f);
    float d0=x0-mu, d1=x1-mu;
    float var = bsum(d0*d0+d1*d1, sh) * (1.f/512.f);
    float rs = rsqrtf(var + 1e-5f);
    o[blockIdx.x*DD+tx]     = d0*rs*g[tx]     + b[tx];
    o[blockIdx.x*DD+tx+256] = d1*rs*g[tx+256] + b[tx+256];
}

__global__ void landmarks_k(const float* __restrict__ qkv,
                            float* __restrict__ ql, float* __restrict__ kl){
    int bz=blockIdx.x, m=blockIdx.y, d=threadIdx.x;
    int b=bz>>3, hh=bz&7;
    const float* base = qkv + ((size_t)b*NPAD + (size_t)m*40)*QKVD + hh*64 + d;
    float sq=0.f, sk=0.f;
    #pragma unroll 8
    for (int j=0;j<40;j++){ sq += base[(size_t)j*QKVD]; sk += base[(size_t)j*QKVD+512]; }
    ql[((size_t)bz*MLAND+m)*64+d] = sq*0.003125f;
    kl[((size_t)bz*MLAND+m)*64+d] = sk*0.025f;
}

// softmax over rows of 256; also emit bf16 hi/lo (A-layout) for the pinv chain
__global__ void softmax256(float* __restrict__ X, __nv_bfloat16* __restrict__ Xh,
                           __nv_bfloat16* __restrict__ Xl){
    __shared__ float sh[32];
    float* p = X + (size_t)blockIdx.x*256;
    float v = p[threadIdx.x];
    float m = bmax(v, sh);
    float e = __expf(v - m);
    float s = bsum(e, sh);
    float r = e / s;
    p[threadIdx.x] = r;
    long i = (long)blockIdx.x*256 + threadIdx.x;
    hilo_st(r, Xh, Xl, i);
}

__global__ void zerok(float* p, int n){
    int i = blockIdx.x*256 + threadIdx.x;
    if (i<n) p[i]=0.f;
}

__global__ void crmax_k(const float* __restrict__ a2, float* mx){
    __shared__ float sh[32];
    const float* p = a2 + (size_t)blockIdx.x*65536;
    int t = threadIdx.x;
    float cs=0.f, rs=0.f;
    for (int m=0;m<256;m++){ cs += p[m*256+t]; rs += p[t*256+m]; }
    float mc = bmax(cs, sh);
    float mr = bmax(rs, sh);
    if (t==0){
        atomicMax((int*)&mx[0], __float_as_int(mc));
        atomicMax((int*)&mx[1], __float_as_int(mr));
    }
}

// z0 = a2^T/(mx0*mx1) emitted as hi/lo in both A-layout and B-layout
__global__ void ztrans_k(const float* __restrict__ a2, const float* __restrict__ mx,
                         __nv_bfloat16* __restrict__ zAh, __nv_bfloat16* __restrict__ zAl,
                         __nv_bfloat16* __restrict__ zBh, __nv_bfloat16* __restrict__ zBl){
    __shared__ float tile[32][33];
    int bz=blockIdx.x;
    const float* p = a2 + (size_t)bz*65536;
    int i0=blockIdx.y*32, j0=blockIdx.z*32;
    tile[threadIdx.y][threadIdx.x] = p[(j0+threadIdx.y)*256 + i0+threadIdx.x];
    __syncthreads();
    float inv = 1.f/(mx[0]*mx[1]);
    long off = (long)bz*PSZ;
    // A-layout: z[i0+ty][j0+tx] = a2[j0+tx][i0+ty]*inv
    float za = tile[threadIdx.x][threadIdx.y]*inv;
    hilo_st(za, zAh, zAl, off + (long)(i0+threadIdx.y)*256 + (j0+threadIdx.x));
    // B-layout: zB[n][k] = z[k][n] = a2[n][k]*inv -> at [j0+ty][i0+tx]
    float zb = tile[threadIdx.y][threadIdx.x]*inv;
    hilo_st(zb, zBh, zBl, off + (long)(j0+threadIdx.y)*256 + (i0+threadIdx.x));
}

__global__ void resconv_k(const float* __restrict__ qkv, const float* __restrict__ rw,
                          float* __restrict__ mg){
    __shared__ float w[33];
    int bz=blockIdx.y; int b=bz>>3, hh=bz&7;
    if (threadIdx.y==0 && threadIdx.x<33) w[threadIdx.x]=rw[hh*33+threadIdx.x];
    __syncthreads();
    int d=threadIdx.x;
    int t=blockIdx.x*8+threadIdx.y;
    const float* vb = qkv + (size_t)b*NPAD*QKVD + 1024 + hh*64 + d;
    float acc=0.f;
    #pragma unroll
    for (int j=0;j<33;j++){
        int ts=t+j-16;
        if (ts>=0 && ts<NPAD) acc += vb[(size_t)ts*QKVD]*w[j];
    }
    mg[((size_t)b*NPAD+t)*DD + hh*64 + d] += acc;
}

__global__ void t2p_k(const float* __restrict__ h, float* __restrict__ pl){
    __shared__ float tile[32][33];
    int b=blockIdx.x, t0=blockIdx.y*32, c0=blockIdx.z*32;
    int t=t0+threadIdx.y, c=c0+threadIdx.x;
    if (t<10000) tile[threadIdx.y][threadIdx.x] = h[((size_t)b*NPAD+PADF+1+t)*DD + c];
    __syncthreads();
    int ch=c0+threadIdx.y, tt=t0+threadIdx.x;
    if (tt<10000) pl[((size_t)b*DD+ch)*10000 + tt] = tile[threadIdx.x][threadIdx.y];
}
__global__ void p2h_k(const float* __restrict__ pl, float* __restrict__ h){
    __shared__ float tile[32][33];
    int b=blockIdx.x, t0=blockIdx.y*32, c0=blockIdx.z*32;
    int ch=c0+threadIdx.y, tt=t0+threadIdx.x;
    if (tt<10000) tile[threadIdx.y][threadIdx.x] = pl[((size_t)b*DD+ch)*10000 + tt];
    __syncthreads();
    int t=t0+threadIdx.y, c=c0+threadIdx.x;
    if (t<10000) h[((size_t)b*NPAD+PADF+1+t)*DD + c] = tile[threadIdx.x][threadIdx.y];
}

__global__ void ppeg_conv_k(const float* __restrict__ pl, float* __restrict__ po,
    const float* __restrict__ w7, const float* __restrict__ b7,
    const float* __restrict__ w5, const float* __restrict__ b5,
    const float* __restrict__ w3, const float* __restrict__ b3){
    __shared__ float sw[86];
    int plane=blockIdx.x; int ch=plane&511;
    int tx=threadIdx.x;
    if      (tx<49) sw[tx]=w7[ch*49+tx];
    else if (tx<74) sw[tx]=w5[ch*25+tx-49];
    else if (tx<83) sw[tx]=w3[ch*9+tx-74];
    else if (tx==83) sw[83]=b7[ch];
    else if (tx==84) sw[84]=b5[ch];
    else if (tx==85) sw[85]=b3[ch];
    __syncthreads();
    int px=blockIdx.y*256+tx;
    if (px>=10000) return;
    int r=px/100, c=px%100;
    const float* in = pl + (size_t)plane*10000;
    float acc = in[px] + sw[83] + sw[84] + sw[85];
    #pragma unroll
    for (int kr=0;kr<7;kr++){
        int rr=r+kr-3; if (rr<0||rr>=100) continue;
        #pragma unroll
        for (int kc=0;kc<7;kc++){
            int cc=c+kc-3; if (cc<0||cc>=100) continue;
            acc += in[rr*100+cc]*sw[kr*7+kc];
        }
    }
    #pragma unroll
    for (int kr=0;kr<5;kr++){
        int rr=r+kr-2; if (rr<0||rr>=100) continue;
        #pragma unroll
        for (int kc=0;kc<5;kc++){
            int cc=c+kc-2; if (cc<0||cc>=100) continue;
            acc += in[rr*100+cc]*sw[49+kr*5+kc];
        }
    }
    #pragma unroll
    for (int kr=0;kr<3;kr++){
        int rr=r+kr-1; if (rr<0||rr>=100) continue;
        #pragma unroll
        for (int kc=0;kc<3;kc++){
            int cc=c+kc-1; if (cc<0||cc>=100) continue;
            acc += in[rr*100+cc]*sw[74+kr*3+kc];
        }
    }
    po[(size_t)plane*10000+px]=acc;
}

__global__ void head_k(const float* __restrict__ cls, const float* __restrict__ w2,
                       const float* __restrict__ b2, float* out, int osz){
    __shared__ float sh[64];
    int b=blockIdx.x;
    float a0=0.f, a1=0.f;
    for (int d=threadIdx.x; d<512; d+=256){
        float x = cls[b*512+d];
        a0 += x*w2[d*2+0]; a1 += x*w2[d*2+1];
    }
    #pragma unroll
    for (int o=16;o;o>>=1){
        a0 += __shfl_xor_sync(0xffffffffu,a0,o);
        a1 += __shfl_xor_sync(0xffffffffu,a1,o);
    }
    int lane=threadIdx.x&31, wid=threadIdx.x>>5;
    if (lane==0){ sh[wid]=a0; sh[wid+32]=a1; }
    __syncthreads();
    if (threadIdx.x==0){
        float l0=b2[0], l1=b2[1];
        for (int w=0;w<8;w++){ l0+=sh[w]; l1+=sh[w+32]; }
        float m=fmaxf(l0,l1);
        float e0=expf(l0-m), e1=expf(l1-m), s=e0+e1;
        if (b*2+1   < osz){ out[b*2]=l0;      out[b*2+1]=l1; }
        if (4+b*2+1 < osz){ out[4+b*2]=e0/s;  out[4+b*2+1]=e1/s; }
        if (8+b     < osz){ out[8+b] = (l1>l0)?1.f:0.f; }
    }
}

// ----------------- driver -----------------
extern "C" void kernel_launch(void* const* d_in, const int* in_sizes, int n_in,
                              void* d_out, int out_size){
    const float* x    =(const float*)d_in[0];
    const float* wfc1 =(const float*)d_in[1];
    const float* bfc1 =(const float*)d_in[2];
    const float* clst =(const float*)d_in[3];
    const float* lng[2]={(const float*)d_in[4],(const float*)d_in[10]};
    const float* lnb[2]={(const float*)d_in[5],(const float*)d_in[11]};
    const float* qkvw[2]={(const float*)d_in[6],(const float*)d_in[12]};
    const float* outw[2]={(const float*)d_in[7],(const float*)d_in[13]};
    const float* outb[2]={(const float*)d_in[8],(const float*)d_in[14]};
    const float* resw[2]={(const float*)d_in[9],(const float*)d_in[15]};
    const float* pw7=(const float*)d_in[16]; const float* pb7=(const float*)d_in[17];
    const float* pw5=(const float*)d_in[18]; const float* pb5=(const float*)d_in[19];
    const float* pw3=(const float*)d_in[20]; const float* pb3=(const float*)d_in[21];
    const float* lnfg=(const float*)d_in[22]; const float* lnfb=(const float*)d_in[23];
    const float* wfc2=(const float*)d_in[24]; const float* bfc2=(const float*)d_in[25];

    float *h,*qkv,*ql,*kl,*s1,*s3,*a2,*zf,*a3v,*pz,*mg,*mx,*pm,*ps;
    __nv_bfloat16 *xh,*xl,*lnh,*lnl,*mgh,*mgl,*wth,*wtl;
    __nv_bfloat16 *pa2h,*pa2l,*pxzh,*pxzl,*pwbh,*pwbl,*ptbh,*ptbl;
    __nv_bfloat16 *pzah[2],*pzal[2],*pzbh[2],*pzbl[2];
    cudaGetSymbolAddress((void**)&h,  g_h);
    cudaGetSymbolAddress((void**)&qkv,g_qkv);
    cudaGetSymbolAddress((void**)&ql, g_ql);
    cudaGetSymbolAddress((void**)&kl, g_kl);
    cudaGetSymbolAddress((void**)&s1, g_s1);
    cudaGetSymbolAddress((void**)&s3, g_s3);
    cudaGetSymbolAddress((void**)&a2, g_a2);
    cudaGetSymbolAddress((void**)&zf, g_z0);
    cudaGetSymbolAddress((void**)&a3v,g_a3v);
    cudaGetSymbolAddress((void**)&pz, g_pz);
    cudaGetSymbolAddress((void**)&mg, g_mg);
    cudaGetSymbolAddress((void**)&mx, g_mx);
    cudaGetSymbolAddress((void**)&pm, g_pm);
    cudaGetSymbolAddress((void**)&ps, g_ps);
    cudaGetSymbolAddress((void**)&xh, g_xh);
    cudaGetSymbolAddress((void**)&xl, g_xl);
    cudaGetSymbolAddress((void**)&lnh,g_lnh);
    cudaGetSymbolAddress((void**)&lnl,g_lnl);
    cudaGetSymbolAddress((void**)&mgh,g_mgh);
    cudaGetSymbolAddress((void**)&mgl,g_mgl);
    cudaGetSymbolAddress((void**)&wth,g_wth);
    cudaGetSymbolAddress((void**)&wtl,g_wtl);
    cudaGetSymbolAddress((void**)&pa2h,g_pa2h);  cudaGetSymbolAddress((void**)&pa2l,g_pa2l);
    cudaGetSymbolAddress((void**)&pxzh,g_pxzh);  cudaGetSymbolAddress((void**)&pxzl,g_pxzl);
    cudaGetSymbolAddress((void**)&pwbh,g_pwbh);  cudaGetSymbolAddress((void**)&pwbl,g_pwbl);
    cudaGetSymbolAddress((void**)&ptbh,g_ptbh);  cudaGetSymbolAddress((void**)&ptbl,g_ptbl);
    cudaGetSymbolAddress((void**)&pzah[0],g_pzah0); cudaGetSymbolAddress((void**)&pzal[0],g_pzal0);
    cudaGetSymbolAddress((void**)&pzbh[0],g_pzbh0); cudaGetSymbolAddress((void**)&pzbl[0],g_pzbl0);
    cudaGetSymbolAddress((void**)&pzah[1],g_pzah1); cudaGetSymbolAddress((void**)&pzal[1],g_pzal1);
    cudaGetSymbolAddress((void**)&pzbh[1],g_pzbh1); cudaGetSymbolAddress((void**)&pzbl[1],g_pzbl1);

    cudaFuncSetAttribute(f1_k, cudaFuncAttributeMaxDynamicSharedMemorySize, F1_SMEM);
    cudaFuncSetAttribute(f2_k, cudaFuncAttributeMaxDynamicSharedMemorySize, F2_SMEM);
    cudaFuncSetAttribute(mm_hmma, cudaFuncAttributeMaxDynamicSharedMemorySize, MMH_SMEM);
    cudaFuncSetAttribute(mm_pinv, cudaFuncAttributeMaxDynamicSharedMemorySize, MMH_SMEM);

    // fc1 on tensor cores (HMMA)
    {
        int n = NB*10000*DIN;
        cvt_k<<<(n+255)/256,256>>>(x, xh, xl, n);
        cvtT_k<<<dim3(DIN/32, DD/32), dim3(32,32)>>>(wfc1, wth, wtl, DIN, DD);
        mm_hmma<<<dim3(4,79,NB),256,MMH_SMEM>>>(xh, xl, wth, wtl,
            h+(size_t)(PADF+1)*DD, bfc1, 10000, DIN, DD,
            (long)10000*DIN, (long)NPAD*DD, FB|FR);
    }
    set_cls<<<NB,512>>>(h, clst);

    for (int L=0; L<2; L++){
        ln_k<<<NB*NPAD,256>>>(h, lnh, lnl, lng[L], lnb[L]);
        cvtT_k<<<dim3(DD/32, QKVD/32), dim3(32,32)>>>(qkvw[L], wth, wtl, DD, QKVD);
        mm_hmma<<<dim3(12,160,1),256,MMH_SMEM>>>(lnh, lnl, wth, wtl,
            qkv, bfc1 /*unused*/, NB*NPAD, DD, QKVD, 0L, 0L, 0);
        landmarks_k<<<dim3(BH,MLAND),64>>>(qkv, ql, kl);
        // s2 = ql @ kl^T -> a2, softmax (+ bf16 hi/lo for pinv)
        gemm64(ql, kl, a2, nullptr, nullptr,
               256, 256, 64, 64, 64, 256,
               (long)256*64, 0, (long)256*64, 0, (long)65536, 0,
               1, BH, 1.f, 0.f, 1, FTRB);
        softmax256<<<BH*256,256>>>(a2, pa2h, pa2l);
        // fused s3 -> online softmax -> @v  (split flash + combine)
        f2_k<<<dim3(4,4,BH),256,F2_SMEM>>>(qkv, ql, s1, pm, ps);
        f2comb_k<<<BH*256,64>>>(s1, pm, ps, a3v);
        // Moore-Penrose pinv on tensor cores (hi/lo bf16 end-to-end)
        zerok<<<1,256>>>(mx, 2);
        crmax_k<<<BH,256>>>(a2, mx);
        ztrans_k<<<dim3(BH,8,8),dim3(32,32)>>>(a2, mx, pzah[0],pzal[0], pzbh[0],pzbl[0]);
        int c = 0;
        dim3 pg(2,2,BH);
        for (int it=0; it<6; it++){
            mm_pinv<<<pg,256,MMH_SMEM>>>(pa2h,pa2l, pzbh[c],pzbl[c], nullptr,
                pxzh,pxzl, pwbh,pwbl, 1.f, 7.f, PF_A|PF_BD);
            mm_pinv<<<pg,256,MMH_SMEM>>>(pxzh,pxzl, pwbh,pwbl, nullptr,
                nullptr,nullptr, ptbh,ptbl, 1.f, 15.f, PF_BD);
            mm_pinv<<<pg,256,MMH_SMEM>>>(pxzh,pxzl, ptbh,ptbl, nullptr,
                nullptr,nullptr, pwbh,pwbl, 1.f, 13.f, PF_BD);
            mm_pinv<<<pg,256,MMH_SMEM>>>(pzah[c],pzal[c], pwbh,pwbl, zf,
                pzah[1-c],pzal[1-c], pzbh[1-c],pzbl[1-c], 0.25f, 0.f, PF_F|PF_A|PF_BV);
            c ^= 1;
        }
        // pz = pinv(a2) @ a3v
        gemm64(zf, a3v, pz, nullptr, nullptr,
               256, 64, 256, 256, 64, 64,
               65536,0, 16384,0, 16384,0, 1, BH, 1.f, 0.f, 1, 0);
        // fused s1 -> softmax -> @pz -> mg
        f1_k<<<dim3(160,BH),256,F1_SMEM>>>(qkv, kl, pz, mg);
        resconv_k<<<dim3(NPAD/8,BH),dim3(64,8)>>>(qkv, resw[L], mg);
        // out-proj on tensor cores: h += mg @ w_out + b_out
        {
            int n = NB*NPAD*DD;
            cvt_k<<<(n+255)/256,256>>>(mg, mgh, mgl, n);
            cvtT_k<<<dim3(DD/32, DD/32), dim3(32,32)>>>(outw[L], wth, wtl, DD, DD);
            mm_hmma<<<dim3(4,79,NB),256,MMH_SMEM>>>(
                mgh+(size_t)PADF*DD, mgl+(size_t)PADF*DD, wth, wtl,
                h+(size_t)PADF*DD, outb[L], 10001, DD, DD,
                (long)NPAD*DD, (long)NPAD*DD, FB|FACC);
        }
        if (L==0){
            t2p_k<<<dim3(NB,313,16),dim3(32,32)>>>(h, s1);
            ppeg_conv_k<<<dim3(NB*512,40),256>>>(s1, s3, pw7,pb7, pw5,pb5, pw3,pb3);
            p2h_k<<<dim3(NB,313,16),dim3(32,32)>>>(s3, h);
        }
    }
    lnf_k<<<NB,256>>>(h, a2, lnfg, lnfb);
    head_k<<<NB,256>>>(a2, wfc2, bfc2, (float*)d_out, out_size);
}

// round 15
// speedup vs baseline: 1.9698x; 1.1135x over previous
#include <cuda_runtime.h>
#include <cuda_bf16.h>
#include <cfloat>
#include <cstdint>

#define NB    2
#define DIN   1024
#define DD    512
#define NPAD  10240
#define PADF  239
#define QKVD  1536
#define MLAND 256
#define BH    16

#define FB    1
#define FR    2
#define FACC  4
#define FAT   8
#define FTRB  16
#define FH    32

// pinv epilogue flags
#define PF_F  1
#define PF_A  2
#define PF_BV 4
#define PF_BD 8

#define PSZ 65536
#define PT  (16*PSZ)

// ----------------- device scratch -----------------
__device__ float g_h  [(size_t)NB*NPAD*DD];
__device__ float g_qkv[(size_t)NB*NPAD*QKVD];
__device__ float g_ql [BH*MLAND*64];
__device__ float g_kl [BH*MLAND*64];
__device__ float g_s1 [(size_t)BH*NPAD*MLAND];   // s1 scores; reused: PPEG planar
__device__ float g_s3 [(size_t)BH*MLAND*NPAD];   // s3 scores; reused: PPEG planar
__device__ float g_a2 [BH*MLAND*MLAND];
__device__ float g_z0 [BH*MLAND*MLAND];          // fp32 final pinv (zf)
__device__ float g_a3v[BH*MLAND*64];
__device__ float g_pz [BH*MLAND*64];
__device__ float g_mg [(size_t)NB*NPAD*DD];
__device__ float g_mx [2];

// bf16 hi/lo operands
__device__ __align__(16) __nv_bfloat16 g_xh [(size_t)NB*10000*DIN];
__device__ __align__(16) __nv_bfloat16 g_xl [(size_t)NB*10000*DIN];
__device__ __align__(16) __nv_bfloat16 g_lnh[(size_t)NB*NPAD*DD];
__device__ __align__(16) __nv_bfloat16 g_lnl[(size_t)NB*NPAD*DD];
__device__ __align__(16) __nv_bfloat16 g_mgh[(size_t)NB*NPAD*DD];
__device__ __align__(16) __nv_bfloat16 g_mgl[(size_t)NB*NPAD*DD];
__device__ __align__(16) __nv_bfloat16 g_wth[786432];
__device__ __align__(16) __nv_bfloat16 g_wtl[786432];
__device__ __align__(16) __nv_bfloat16 g_qkvh[(size_t)NB*NPAD*QKVD];
__device__ __align__(16) __nv_bfloat16 g_qkvl[(size_t)NB*NPAD*QKVD];
__device__ __align__(16) __nv_bfloat16 g_a1h[(size_t)BH*NPAD*MLAND];
__device__ __align__(16) __nv_bfloat16 g_a1l[(size_t)BH*NPAD*MLAND];
__device__ __align__(16) __nv_bfloat16 g_a3h[(size_t)BH*MLAND*NPAD];
__device__ __align__(16) __nv_bfloat16 g_a3l[(size_t)BH*MLAND*NPAD];
__device__ __align__(16) __nv_bfloat16 g_vth[(size_t)BH*64*NPAD];
__device__ __align__(16) __nv_bfloat16 g_vtl[(size_t)BH*64*NPAD];
__device__ __align__(16) __nv_bfloat16 g_qlh[BH*MLAND*64], g_qll[BH*MLAND*64];
__device__ __align__(16) __nv_bfloat16 g_klh[BH*MLAND*64], g_kll[BH*MLAND*64];
__device__ __align__(16) __nv_bfloat16 g_pzth[BH*64*MLAND], g_pztl[BH*64*MLAND];

// pinv hi/lo buffers
__device__ __align__(16) __nv_bfloat16 g_pa2h[PT], g_pa2l[PT];
__device__ __align__(16) __nv_bfloat16 g_pxzh[PT], g_pxzl[PT];
__device__ __align__(16) __nv_bfloat16 g_pwbh[PT], g_pwbl[PT];
__device__ __align__(16) __nv_bfloat16 g_ptbh[PT], g_ptbl[PT];
__device__ __align__(16) __nv_bfloat16 g_pzah0[PT], g_pzal0[PT], g_pzbh0[PT], g_pzbl0[PT];
__device__ __align__(16) __nv_bfloat16 g_pzah1[PT], g_pzal1[PT], g_pzbh1[PT], g_pzbl1[PT];

// ----------------- helpers -----------------
__device__ __forceinline__ uint32_t smem_u32(const void* p){
    uint32_t a;
    asm("{ .reg .u64 t; cvta.to.shared.u64 t, %1; cvt.u32.u64 %0, t; }" : "=r"(a) : "l"(p));
    return a;
}
__device__ __forceinline__ void cpasync16(uint32_t d, const void* s, int sz){
    asm volatile("cp.async.cg.shared.global [%0], [%1], 16, %2;"
        :: "r"(d), "l"(s), "r"(sz) : "memory");
}
__device__ __forceinline__ void ldmx4(uint32_t* r, uint32_t a){
    asm volatile("ldmatrix.sync.aligned.m8n8.x4.shared.b16 {%0,%1,%2,%3},[%4];"
        : "=r"(r[0]), "=r"(r[1]), "=r"(r[2]), "=r"(r[3]) : "r"(a));
}
__device__ __forceinline__ void mma_bf16(float* c, const uint32_t* a, uint32_t b0, uint32_t b1){
    asm volatile("mma.sync.aligned.m16n8k16.row.col.f32.bf16.bf16.f32 "
        "{%0,%1,%2,%3},{%4,%5,%6,%7},{%8,%9},{%0,%1,%2,%3};"
        : "+f"(c[0]), "+f"(c[1]), "+f"(c[2]), "+f"(c[3])
        : "r"(a[0]), "r"(a[1]), "r"(a[2]), "r"(a[3]), "r"(b0), "r"(b1));
}
__device__ __forceinline__ void hilo_st(float v, __nv_bfloat16* H, __nv_bfloat16* L, long i){
    __nv_bfloat16 h = __float2bfloat16(v);
    H[i] = h;
    L[i] = __float2bfloat16(v - __bfloat162float(h));
}

// ----------------- block reductions -----------------
__device__ __forceinline__ float bsum(float v, float* sh){
    int lane = threadIdx.x & 31, wid = threadIdx.x >> 5;
    #pragma unroll
    for (int o=16;o;o>>=1) v += __shfl_xor_sync(0xffffffffu, v, o);
    if (lane==0) sh[wid]=v;
    __syncthreads();
    if (wid==0){
        int nw = blockDim.x >> 5;
        float r = (lane<nw) ? sh[lane] : 0.f;
        #pragma unroll
        for (int o=16;o;o>>=1) r += __shfl_xor_sync(0xffffffffu, r, o);
        if (lane==0) sh[0]=r;
    }
    __syncthreads();
    float out = sh[0];
    __syncthreads();
    return out;
}
__device__ __forceinline__ float bmax(float v, float* sh){
    int lane = threadIdx.x & 31, wid = threadIdx.x >> 5;
    #pragma unroll
    for (int o=16;o;o>>=1) v = fmaxf(v, __shfl_xor_sync(0xffffffffu, v, o));
    if (lane==0) sh[wid]=v;
    __syncthreads();
    if (wid==0){
        int nw = blockDim.x >> 5;
        float r = (lane<nw) ? sh[lane] : -FLT_MAX;
        #pragma unroll
        for (int o=16;o;o>>=1) r = fmaxf(r, __shfl_xor_sync(0xffffffffu, r, o));
        if (lane==0) sh[0]=r;
    }
    __syncthreads();
    float out = sh[0];
    __syncthreads();
    return out;
}

// ----------------- HMMA GEMM (proven): C = A @ B^T, simple strides -----------------
#define MMH_TS   (128*72)
#define MMH_BUFB (4*MMH_TS*2)
#define MMH_SMEM (2*MMH_BUFB)
__global__ void __launch_bounds__(256, 1)
mm_hmma(const __nv_bfloat16* __restrict__ Ah, const __nv_bfloat16* __restrict__ Al,
        const __nv_bfloat16* __restrict__ Bh, const __nv_bfloat16* __restrict__ Bl,
        float* __restrict__ C, const float* __restrict__ bias,
        int M, int K, int ldc, long sA, long sC, int flags)
{
    extern __shared__ __nv_bfloat16 smb[];
    uint32_t sbase = smem_u32(smb);
    int tid = threadIdx.x, wid = tid >> 5, lane = tid & 31;
    int col0 = blockIdx.x * 128, row0 = blockIdx.y * 128;
    long bz = blockIdx.z;
    Ah += bz * sA;  Al += bz * sA;
    float* Cb = C + bz * sC;

    int wm = wid & 3, wn = wid >> 2;
    float acc[2][8][4] = {};
    const int S = K >> 6;

    auto issue = [&](int s){
        int b = s & 1;
        uint32_t dst = sbase + (uint32_t)b * MMH_BUFB;
        int k0 = s << 6;
        #pragma unroll
        for (int i = 0; i < 4; i++){
            int ch = tid + i*256;
            int r = ch >> 3, c8 = ch & 7;
            uint32_t off = (uint32_t)(r*144 + c8*16);
            int gm = row0 + r;
            int sz = (gm < M) ? 16 : 0;
            cpasync16(dst + off,              Ah + (long)gm*K + k0 + c8*8, sz);
            cpasync16(dst + MMH_TS*2 + off,   Al + (long)gm*K + k0 + c8*8, sz);
            long gn = col0 + r;
            cpasync16(dst + 2*MMH_TS*2 + off, Bh + gn*K + k0 + c8*8, 16);
            cpasync16(dst + 3*MMH_TS*2 + off, Bl + gn*K + k0 + c8*8, 16);
        }
        asm volatile("cp.async.commit_group;" ::: "memory");
    };

    issue(0);
    for (int s = 0; s < S; s++){
        if (s + 1 < S){
            issue(s + 1);
            asm volatile("cp.async.wait_group 1;" ::: "memory");
        } else {
            asm volatile("cp.async.wait_group 0;" ::: "memory");
        }
        __syncthreads();
        uint32_t buf = sbase + (uint32_t)(s & 1) * MMH_BUFB;
        uint32_t aH = buf, aL = buf + MMH_TS*2;
        uint32_t bHb = buf + 2*MMH_TS*2, bLb = buf + 3*MMH_TS*2;
        #pragma unroll
        for (int ks = 0; ks < 4; ks++){
            int kc = ks * 16;
            uint32_t ah[2][4], al[2][4];
            #pragma unroll
            for (int mi = 0; mi < 2; mi++){
                int rowb = wm*32 + mi*16 + (lane & 15);
                uint32_t o = (uint32_t)(rowb*144 + kc*2 + (lane >> 4)*16);
                ldmx4(ah[mi], aH + o);
                ldmx4(al[mi], aL + o);
            }
            #pragma unroll
            for (int nb = 0; nb < 4; nb++){
                int g = lane >> 3;
                int rown = wn*64 + nb*16 + (g >> 1)*8 + (lane & 7);
                uint32_t bo = (uint32_t)(rown*144 + kc*2 + (g & 1)*16);
                uint32_t bh[4], bl[4];
                ldmx4(bh, bHb + bo);
                ldmx4(bl, bLb + bo);
                #pragma unroll
                for (int mi = 0; mi < 2; mi++){
                    #pragma unroll
                    for (int hf = 0; hf < 2; hf++){
                        float* c = acc[mi][nb*2 + hf];
                        mma_bf16(c, ah[mi], bh[hf*2], bh[hf*2+1]);
                        mma_bf16(c, ah[mi], bl[hf*2], bl[hf*2+1]);
                        mma_bf16(c, al[mi], bh[hf*2], bh[hf*2+1]);
                    }
                }
            }
        }
        __syncthreads();
    }

    int gID = lane >> 2, tig = lane & 3;
    #pragma unroll
    for (int mi = 0; mi < 2; mi++){
        #pragma unroll
        for (int nj = 0; nj < 8; nj++){
            int colb = col0 + wn*64 + nj*8 + tig*2;
            #pragma unroll
            for (int rh = 0; rh < 2; rh++){
                int gm = row0 + wm*32 + mi*16 + rh*8 + gID;
                if (gm >= M) continue;
                float v0 = acc[mi][nj][rh*2+0];
                float v1 = acc[mi][nj][rh*2+1];
                float* cp = Cb + (long)gm*ldc + colb;
                if (flags & FB){ v0 += bias[colb]; v1 += bias[colb+1]; }
                if (flags & FACC){ v0 += cp[0]; v1 += cp[1]; }
                if (flags & FR){ v0 = fmaxf(v0, 0.f); v1 = fmaxf(v1, 0.f); }
                cp[0] = v0; cp[1] = v1;
            }
        }
    }
}

// ----------------- generalized HMMA GEMM: strided batch, split-K, hilo-emit -----------------
// A hi/lo [m][k] lda; B hi/lo [n][k] ldb. batch offset via (bz/nh, bz%nh).
// grid (colTiles, nTM*kSplit, batch).
__global__ void __launch_bounds__(256, 1)
mm_g(const __nv_bfloat16* __restrict__ Ah, const __nv_bfloat16* __restrict__ Al,
     const __nv_bfloat16* __restrict__ Bh, const __nv_bfloat16* __restrict__ Bl,
     float* __restrict__ Cf, __nv_bfloat16* __restrict__ Ch, __nv_bfloat16* __restrict__ Cl,
     int M, int N, int K, int lda, int ldb, int ldc,
     long sA1, long sA2, long sB1, long sB2, long sC1, long sC2,
     int nh, int nTM, float alpha, int kSplit, int flags)
{
    extern __shared__ __nv_bfloat16 smb[];
    uint32_t sbase = smem_u32(smb);
    int tid = threadIdx.x, wid = tid >> 5, lane = tid & 31;
    int col0 = blockIdx.x * 128;
    int row0 = (blockIdx.y % nTM) * 128;
    int kIdx = blockIdx.y / nTM;
    int bz = blockIdx.z;
    long ab = (long)(bz/nh)*sA1 + (long)(bz%nh)*sA2;
    long bb = (long)(bz/nh)*sB1 + (long)(bz%nh)*sB2;
    long cb = (long)(bz/nh)*sC1 + (long)(bz%nh)*sC2;
    int kChunk = K / kSplit;
    int k0 = kIdx * kChunk;
    const int S = kChunk >> 6;

    int wm = wid & 3, wn = wid >> 2;
    float acc[2][8][4] = {};

    auto issue = [&](int s){
        uint32_t dst = sbase + (uint32_t)(s & 1) * MMH_BUFB;
        int kk = k0 + (s << 6);
        #pragma unroll
        for (int i = 0; i < 4; i++){
            int ch = tid + i*256;
            int r = ch >> 3, c8 = ch & 7;
            uint32_t off = (uint32_t)(r*144 + c8*16);
            int gm = row0 + r;
            int sza = (gm < M) ? 16 : 0;
            cpasync16(dst + off,              Ah + ab + (long)gm*lda + kk + c8*8, sza);
            cpasync16(dst + MMH_TS*2 + off,   Al + ab + (long)gm*lda + kk + c8*8, sza);
            int gn = col0 + r;
            int szb = (gn < N) ? 16 : 0;
            cpasync16(dst + 2*MMH_TS*2 + off, Bh + bb + (long)gn*ldb + kk + c8*8, szb);
            cpasync16(dst + 3*MMH_TS*2 + off, Bl + bb + (long)gn*ldb + kk + c8*8, szb);
        }
        asm volatile("cp.async.commit_group;" ::: "memory");
    };

    issue(0);
    for (int s = 0; s < S; s++){
        if (s + 1 < S){
            issue(s + 1);
            asm volatile("cp.async.wait_group 1;" ::: "memory");
        } else {
            asm volatile("cp.async.wait_group 0;" ::: "memory");
        }
        __syncthreads();
        uint32_t buf = sbase + (uint32_t)(s & 1) * MMH_BUFB;
        uint32_t aH = buf, aL = buf + MMH_TS*2;
        uint32_t bHb = buf + 2*MMH_TS*2, bLb = buf + 3*MMH_TS*2;
        #pragma unroll
        for (int ks = 0; ks < 4; ks++){
            int kc = ks * 16;
            uint32_t ah[2][4], al[2][4];
            #pragma unroll
            for (int mi = 0; mi < 2; mi++){
                int rowb = wm*32 + mi*16 + (lane & 15);
                uint32_t o = (uint32_t)(rowb*144 + kc*2 + (lane >> 4)*16);
                ldmx4(ah[mi], aH + o);
                ldmx4(al[mi], aL + o);
            }
            #pragma unroll
            for (int nb = 0; nb < 4; nb++){
                int g = lane >> 3;
                int rown = wn*64 + nb*16 + (g >> 1)*8 + (lane & 7);
                uint32_t bo = (uint32_t)(rown*144 + kc*2 + (g & 1)*16);
                uint32_t bh[4], bl[4];
                ldmx4(bh, bHb + bo);
                ldmx4(bl, bLb + bo);
                #pragma unroll
                for (int mi = 0; mi < 2; mi++){
                    #pragma unroll
                    for (int hf = 0; hf < 2; hf++){
                        float* c = acc[mi][nb*2 + hf];
                        mma_bf16(c, ah[mi], bh[hf*2], bh[hf*2+1]);
                        mma_bf16(c, ah[mi], bl[hf*2], bl[hf*2+1]);
                        mma_bf16(c, al[mi], bh[hf*2], bh[hf*2+1]);
                    }
                }
            }
        }
        __syncthreads();
    }

    int gID = lane >> 2, tig = lane & 3;
    #pragma unroll
    for (int mi = 0; mi < 2; mi++){
        #pragma unroll
        for (int nj = 0; nj < 8; nj++){
            int colb = col0 + wn*64 + nj*8 + tig*2;
            if (colb >= N) continue;
            #pragma unroll
            for (int rh = 0; rh < 2; rh++){
                int gm = row0 + wm*32 + mi*16 + rh*8 + gID;
                if (gm >= M) continue;
                float v0 = acc[mi][nj][rh*2+0]*alpha;
                float v1 = acc[mi][nj][rh*2+1]*alpha;
                long idx = cb + (long)gm*ldc + colb;
                if (flags & FAT){
                    atomicAdd(&Cf[idx], v0);
                    atomicAdd(&Cf[idx+1], v1);
                } else {
                    if (flags & FACC){ v0 += Cf[idx]; v1 += Cf[idx+1]; }
                    if (flags & FR){ v0 = fmaxf(v0,0.f); v1 = fmaxf(v1,0.f); }
                    Cf[idx] = v0; Cf[idx+1] = v1;
                }
                if (flags & FH){
                    hilo_st(v0, Ch, Cl, idx);
                    hilo_st(v1, Ch, Cl, idx+1);
                }
            }
        }
    }
}

// ----------------- HMMA pinv GEMM (proven) -----------------
__global__ void __launch_bounds__(256, 1)
mm_pinv(const __nv_bfloat16* __restrict__ Ah, const __nv_bfloat16* __restrict__ Al,
        const __nv_bfloat16* __restrict__ Bh, const __nv_bfloat16* __restrict__ Bl,
        float* __restrict__ Cf,
        __nv_bfloat16* __restrict__ Xh, __nv_bfloat16* __restrict__ Xl,
        __nv_bfloat16* __restrict__ Yh, __nv_bfloat16* __restrict__ Yl,
        float alpha, float dval, int flags)
{
    extern __shared__ __nv_bfloat16 smb[];
    uint32_t sbase = smem_u32(smb);
    int tid = threadIdx.x, wid = tid >> 5, lane = tid & 31;
    int col0 = blockIdx.x * 128, row0 = blockIdx.y * 128;
    long off = (long)blockIdx.z * PSZ;
    Ah += off; Al += off; Bh += off; Bl += off;

    int wm = wid & 3, wn = wid >> 2;
    float acc[2][8][4] = {};

    auto issue = [&](int s){
        uint32_t dst = sbase + (uint32_t)(s & 1) * MMH_BUFB;
        int k0 = s << 6;
        #pragma unroll
        for (int i = 0; i < 4; i++){
            int ch = tid + i*256;
            int r = ch >> 3, c8 = ch & 7;
            uint32_t o2 = (uint32_t)(r*144 + c8*16);
            cpasync16(dst + o2,              Ah + (long)(row0+r)*256 + k0 + c8*8, 16);
            cpasync16(dst + MMH_TS*2 + o2,   Al + (long)(row0+r)*256 + k0 + c8*8, 16);
            cpasync16(dst + 2*MMH_TS*2 + o2, Bh + (long)(col0+r)*256 + k0 + c8*8, 16);
            cpasync16(dst + 3*MMH_TS*2 + o2, Bl + (long)(col0+r)*256 + k0 + c8*8, 16);
        }
        asm volatile("cp.async.commit_group;" ::: "memory");
    };

    issue(0);
    for (int s = 0; s < 4; s++){
        if (s + 1 < 4){
            issue(s + 1);
            asm volatile("cp.async.wait_group 1;" ::: "memory");
        } else {
            asm volatile("cp.async.wait_group 0;" ::: "memory");
        }
        __syncthreads();
        uint32_t buf = sbase + (uint32_t)(s & 1) * MMH_BUFB;
        uint32_t aH = buf, aL = buf + MMH_TS*2;
        uint32_t bHb = buf + 2*MMH_TS*2, bLb = buf + 3*MMH_TS*2;
        #pragma unroll
        for (int ks = 0; ks < 4; ks++){
            int kc = ks * 16;
            uint32_t ah[2][4], al[2][4];
            #pragma unroll
            for (int mi = 0; mi < 2; mi++){
                int rowb = wm*32 + mi*16 + (lane & 15);
                uint32_t o = (uint32_t)(rowb*144 + kc*2 + (lane >> 4)*16);
                ldmx4(ah[mi], aH + o);
                ldmx4(al[mi], aL + o);
            }
            #pragma unroll
            for (int nb = 0; nb < 4; nb++){
                int g = lane >> 3;
                int rown = wn*64 + nb*16 + (g >> 1)*8 + (lane & 7);
                uint32_t bo = (uint32_t)(rown*144 + kc*2 + (g & 1)*16);
                uint32_t bh[4], bl[4];
                ldmx4(bh, bHb + bo);
                ldmx4(bl, bLb + bo);
                #pragma unroll
                for (int mi = 0; mi < 2; mi++){
                    #pragma unroll
                    for (int hf = 0; hf < 2; hf++){
                        float* c = acc[mi][nb*2 + hf];
                        mma_bf16(c, ah[mi], bh[hf*2], bh[hf*2+1]);
                        mma_bf16(c, ah[mi], bl[hf*2], bl[hf*2+1]);
                        mma_bf16(c, al[mi], bh[hf*2], bh[hf*2+1]);
                    }
                }
            }
        }
        __syncthreads();
    }

    int gID = lane >> 2, tig = lane & 3;
    #pragma unroll
    for (int mi = 0; mi < 2; mi++){
        #pragma unroll
        for (int nj = 0; nj < 8; nj++){
            int cb2 = col0 + wn*64 + nj*8 + tig*2;
            #pragma unroll
            for (int rh = 0; rh < 2; rh++){
                int gm = row0 + wm*32 + mi*16 + rh*8 + gID;
                float v0 = acc[mi][nj][rh*2+0]*alpha;
                float v1 = acc[mi][nj][rh*2+1]*alpha;
                long i0 = off + (long)gm*256 + cb2;
                if (flags & PF_F){ Cf[i0] = v0; Cf[i0+1] = v1; }
                if (flags & PF_A){
                    hilo_st(v0, Xh, Xl, i0);
                    hilo_st(v1, Xh, Xl, i0+1);
                }
                if (flags & (PF_BV|PF_BD)){
                    float w0 = v0, w1 = v1;
                    if (flags & PF_BD){
                        w0 = ((gm==cb2  )?dval:0.f) - v0;
                        w1 = ((gm==cb2+1)?dval:0.f) - v1;
                    }
                    long j0 = off + (long)cb2*256 + gm;
                    hilo_st(w0, Yh, Yl, j0);
                    hilo_st(w1, Yh, Yl, j0+256);
                }
            }
        }
    }
}

// ----------------- conversions -----------------
__global__ void cvt_k(const float* __restrict__ s, __nv_bfloat16* __restrict__ hi,
                      __nv_bfloat16* __restrict__ lo, int n){
    int i = blockIdx.x*256 + threadIdx.x;
    if (i < n){
        float v = s[i];
        __nv_bfloat16 h = __float2bfloat16(v);
        hi[i] = h;
        lo[i] = __float2bfloat16(v - __bfloat162float(h));
    }
}
__global__ void cvtT_k(const float* __restrict__ W, __nv_bfloat16* __restrict__ th,
                       __nv_bfloat16* __restrict__ tl, int K, int N){
    __shared__ float t[32][33];
    int k0 = blockIdx.x*32, n0 = blockIdx.y*32;
    t[threadIdx.y][threadIdx.x] = W[(k0+threadIdx.y)*N + n0+threadIdx.x];
    __syncthreads();
    int n = n0+threadIdx.y, k = k0+threadIdx.x;
    float v = t[threadIdx.x][threadIdx.y];
    __nv_bfloat16 h = __float2bfloat16(v);
    th[(size_t)n*K+k] = h;
    tl[(size_t)n*K+k] = __float2bfloat16(v - __bfloat162float(h));
}
// V^T per bh: vt[bh][d][t] from qkv v-section
__global__ void vtrans_k(const float* __restrict__ qkv, __nv_bfloat16* __restrict__ VH,
                         __nv_bfloat16* __restrict__ VL){
    __shared__ float tile[32][33];
    int bh=blockIdx.x, b=bh>>3, h=bh&7;
    int t0=blockIdx.y*32, d0=blockIdx.z*32;
    tile[threadIdx.y][threadIdx.x] =
        qkv[((size_t)b*NPAD + t0+threadIdx.y)*QKVD + 1024 + h*64 + d0+threadIdx.x];
    __syncthreads();
    long o = ((size_t)bh*64 + d0+threadIdx.y)*NPAD + t0+threadIdx.x;
    hilo_st(tile[threadIdx.x][threadIdx.y], VH, VL, o);
}
// pz^T per bh: pzt[bh][d][land]
__global__ void pzt_k(const float* __restrict__ pz, __nv_bfloat16* __restrict__ H,
                      __nv_bfloat16* __restrict__ L){
    __shared__ float tile[32][33];
    int bh=blockIdx.x;
    int l0=blockIdx.y*32, d0=blockIdx.z*32;
    tile[threadIdx.y][threadIdx.x] = pz[((size_t)bh*256 + l0+threadIdx.y)*64 + d0+threadIdx.x];
    __syncthreads();
    long o = ((size_t)bh*64 + d0+threadIdx.y)*256 + l0+threadIdx.x;
    hilo_st(tile[threadIdx.x][threadIdx.y], H, L, o);
}

// ----------------- fp32 batched GEMM (small paths: s2, pz) -----------------
template<int BM,int BN,int BK,int TM,int TN,int MAXB>
__global__ void __launch_bounds__((BM/TM)*(BN/TN), MAXB)
gemm_k(const float* __restrict__ A, const float* __restrict__ Bp,
       float* C, float* C2, const float* __restrict__ bias,
       int M,int N,int K,int lda,int ldb,int ldc,
       long sA1,long sA2,long sB1,long sB2,long sC1,long sC2,
       int nh,float alpha,float dval,int nTN,int kSplit,int flags)
{
    constexpr int THREADS=(BM/TM)*(BN/TN);
    constexpr int LA = BM*BK/THREADS;
    constexpr int LB = BK*BN/THREADS;
    __shared__ float As[2][BK][BM];
    __shared__ float Bs[2][BK][BN+1];
    int bz=blockIdx.z;
    A  += (long)(bz/nh)*sA1 + (long)(bz%nh)*sA2;
    Bp += (long)(bz/nh)*sB1 + (long)(bz%nh)*sB2;
    long offC = (long)(bz/nh)*sC1 + (long)(bz%nh)*sC2;
    int kIdx=blockIdx.x/nTN;
    int col0=(blockIdx.x%nTN)*BN;
    int row0=blockIdx.y*BM;
    int kChunk=(K+kSplit-1)/kSplit;
    int k0=kIdx*kChunk, k1=min(K,k0+kChunk);
    int tid=threadIdx.x;
    int tm=tid/(BN/TN), tn=tid%(BN/TN);
    bool trb = (flags & FTRB) != 0;
    float acc[TM][TN] = {};
    float pa[LA], pb[LB];

    auto loadT = [&](int kk){
        #pragma unroll
        for (int it=0; it<LA; it++){
            int i=tid+it*THREADS;
            int m=i/BK, k=i%BK;
            int gm=row0+m, gk=kk+k;
            pa[it] = (gm<M && gk<k1) ? A[(long)gm*lda+gk] : 0.f;
        }
        #pragma unroll
        for (int it=0; it<LB; it++){
            int i=tid+it*THREADS;
            int k,n;
            if (trb){ n=i/BK; k=i%BK; } else { k=i/BN; n=i%BN; }
            int gk=kk+k, gn=col0+n;
            pb[it] = (gk<k1 && gn<N) ? (trb ? Bp[(long)gn*ldb+gk] : Bp[(long)gk*ldb+gn]) : 0.f;
        }
    };
    auto storeT = [&](int b){
        #pragma unroll
        for (int it=0; it<LA; it++){
            int i=tid+it*THREADS;
            int m=i/BK, k=i%BK;
            As[b][k][m]=pa[it];
        }
        #pragma unroll
        for (int it=0; it<LB; it++){
            int i=tid+it*THREADS;
            int k,n;
            if (trb){ n=i/BK; k=i%BK; } else { k=i/BN; n=i%BN; }
            Bs[b][k][n]=pb[it];
        }
    };

    loadT(k0);
    storeT(0);
    __syncthreads();
    int buf=0;
    for (int kk=k0; kk<k1; kk+=BK){
        bool hn = (kk+BK) < k1;
        if (hn) loadT(kk+BK);
        #pragma unroll
        for (int k=0;k<BK;k++){
            float ra[TM], rb[TN];
            #pragma unroll
            for (int i=0;i<TM;i++) ra[i]=As[buf][k][tm*TM+i];
            #pragma unroll
            for (int j=0;j<TN;j++) rb[j]=Bs[buf][k][tn*TN+j];
            #pragma unroll
            for (int i=0;i<TM;i++)
                #pragma unroll
                for (int j=0;j<TN;j++) acc[i][j] += ra[i]*rb[j];
        }
        if (hn) storeT(buf^1);
        __syncthreads();
        buf^=1;
    }
    #pragma unroll
    for (int i=0;i<TM;i++){
        int gm=row0+tm*TM+i; if (gm>=M) continue;
        #pragma unroll
        for (int j=0;j<TN;j++){
            int gn=col0+tn*TN+j; if (gn>=N) continue;
            float v = acc[i][j]*alpha;
            if (flags&FB) v += bias[gn];
            long idx = offC + (long)gm*ldc + gn;
            if (C2) C2[idx] = ((gm==gn)?dval:0.f) - v;
            if (C){
                if (flags&FAT) atomicAdd(&C[idx], v);
                else {
                    float o = v;
                    if (flags&FACC) o += C[idx];
                    if (flags&FR)   o = fmaxf(o, 0.f);
                    C[idx] = o;
                }
            }
        }
    }
}

static void gemm64(const float*A,const float*B,float*C,float*C2,const float*bias,
    int M,int N,int K,int lda,int ldb,int ldc,
    long a1,long a2,long b1,long b2,long c1,long c2,int nh,int batch,
    float alpha,float dval,int kSplit,int flags)
{
    int nTN=(N+63)/64, nTM=(M+63)/64;
    dim3 g(nTN*kSplit, nTM, batch);
    gemm_k<64,64,16,4,4,2><<<g,256>>>(A,B,C,C2,bias,M,N,K,lda,ldb,ldc,
        a1,a2,b1,b2,c1,c2,nh,alpha,dval,nTN,kSplit,flags);
}

// ----------------- elementwise / reduction kernels -----------------
__global__ void set_cls(float* h, const float* __restrict__ cls){
    h[((size_t)blockIdx.x*NPAD + PADF)*DD + threadIdx.x] = cls[threadIdx.x];
}

__global__ void ln_k(const float* __restrict__ h, __nv_bfloat16* __restrict__ oh,
                     __nv_bfloat16* __restrict__ ol,
                     const float* __restrict__ g, const float* __restrict__ b){
    __shared__ float sh[32];
    size_t row = blockIdx.x;
    int t = (int)(row % NPAD);
    __nv_bfloat16* ph = oh + row*(size_t)DD;
    __nv_bfloat16* pl = ol + row*(size_t)DD;
    int tx = threadIdx.x;
    __nv_bfloat16 z = __float2bfloat16(0.f);
    if (t < PADF){ ph[tx]=z; ph[tx+256]=z; pl[tx]=z; pl[tx+256]=z; return; }
    const float* p = h + row*(size_t)DD;
    float x0=p[tx], x1=p[tx+256];
    float mu  = bsum(x0+x1, sh) * (1.f/512.f);
    float d0=x0-mu, d1=x1-mu;
    float var = bsum(d0*d0+d1*d1, sh) * (1.f/512.f);
    float rs = rsqrtf(var + 1e-5f);
    float y0 = d0*rs*g[tx]     + b[tx];
    float y1 = d1*rs*g[tx+256] + b[tx+256];
    __nv_bfloat16 h0 = __float2bfloat16(y0);
    __nv_bfloat16 h1 = __float2bfloat16(y1);
    ph[tx]     = h0; pl[tx]     = __float2bfloat16(y0 - __bfloat162float(h0));
    ph[tx+256] = h1; pl[tx+256] = __float2bfloat16(y1 - __bfloat162float(h1));
}

__global__ void lnf_k(const float* __restrict__ h, float* __restrict__ o,
                      const float* __restrict__ g, const float* __restrict__ b){
    __shared__ float sh[32];
    const float* p = h + ((size_t)blockIdx.x*NPAD + PADF)*DD;
    int tx = threadIdx.x;
    float x0=p[tx], x1=p[tx+256];
    float mu  = bsum(x0+x1, sh) * (1.f/512.f);
    float d0=x0-mu, d1=x1-mu;
    float var = bsum(d0*d0+d1*d1, sh) * (1.f/512.f);
    float rs = rsqrtf(var + 1e-5f);
    o[blockIdx.x*DD+tx]     = d0*rs*g[tx]     + b[tx];
    o[blockIdx.x*DD+tx+256] = d1*rs*g[tx+256] + b[tx+256];
}

__global__ void landmarks_k(const float* __restrict__ qkv,
                            float* __restrict__ ql, float* __restrict__ kl,
                            __nv_bfloat16* qlh, __nv_bfloat16* qll,
                            __nv_bfloat16* klh, __nv_bfloat16* kll){
    int bz=blockIdx.x, m=blockIdx.y, d=threadIdx.x;
    int b=bz>>3, hh=bz&7;
    const float* base = qkv + ((size_t)b*NPAD + (size_t)m*40)*QKVD + hh*64 + d;
    float sq=0.f, sk=0.f;
    #pragma unroll 8
    for (int j=0;j<40;j++){ sq += base[(size_t)j*QKVD]; sk += base[(size_t)j*QKVD+512]; }
    long i = ((size_t)bz*MLAND+m)*64+d;
    float vq = sq*0.003125f, vk = sk*0.025f;
    ql[i]=vq; kl[i]=vk;
    hilo_st(vq, qlh, qll, i);
    hilo_st(vk, klh, kll, i);
}

// softmax rows of 256 -> fp32 + bf16 hilo (for pinv input a2)
__global__ void softmax256(float* __restrict__ X, __nv_bfloat16* __restrict__ Xh,
                           __nv_bfloat16* __restrict__ Xl){
    __shared__ float sh[32];
    float* p = X + (size_t)blockIdx.x*256;
    float v = p[threadIdx.x];
    float m = bmax(v, sh);
    float e = __expf(v - m);
    float s = bsum(e, sh);
    float r = e / s;
    p[threadIdx.x] = r;
    long i = (long)blockIdx.x*256 + threadIdx.x;
    hilo_st(r, Xh, Xl, i);
}

// softmax rows of 256 -> bf16 hilo only (a1 probs)
__global__ void softmax256h(const float* __restrict__ X, __nv_bfloat16* __restrict__ H,
                            __nv_bfloat16* __restrict__ L){
    __shared__ float sh[32];
    long i = (size_t)blockIdx.x*256 + threadIdx.x;
    float v = X[i];
    float m = bmax(v, sh);
    float e = __expf(v - m);
    float s = bsum(e, sh);
    hilo_st(e/s, H, L, i);
}

// softmax rows of NPAD -> bf16 hilo only (a3 probs); register-cached
__global__ void softmaxN_h(const float* __restrict__ X, __nv_bfloat16* __restrict__ H,
                           __nv_bfloat16* __restrict__ L){
    __shared__ float sh[32];
    const float* p = X + (size_t)blockIdx.x*NPAD;
    int tx = threadIdx.x;
    float r[40];
    float m = -FLT_MAX;
    #pragma unroll
    for (int i=0;i<40;i++){ r[i]=p[tx+i*256]; m = fmaxf(m, r[i]); }
    m = bmax(m, sh);
    float s = 0.f;
    #pragma unroll
    for (int i=0;i<40;i++){ r[i]=__expf(r[i]-m); s += r[i]; }
    s = bsum(s, sh);
    float inv = 1.f/s;
    size_t base = (size_t)blockIdx.x*NPAD + tx;
    #pragma unroll
    for (int i=0;i<40;i++) hilo_st(r[i]*inv, H, L, base + i*256);
}

__global__ void zerok(float* p, int n){
    int i = blockIdx.x*256 + threadIdx.x;
    if (i<n) p[i]=0.f;
}

__global__ void crmax_k(const float* __restrict__ a2, float* mx){
    __shared__ float sh[32];
    const float* p = a2 + (size_t)blockIdx.x*65536;
    int t = threadIdx.x;
    float cs=0.f, rs=0.f;
    for (int m=0;m<256;m++){ cs += p[m*256+t]; rs += p[t*256+m]; }
    float mc = bmax(cs, sh);
    float mr = bmax(rs, sh);
    if (t==0){
        atomicMax((int*)&mx[0], __float_as_int(mc));
        atomicMax((int*)&mx[1], __float_as_int(mr));
    }
}

__global__ void ztrans_k(const float* __restrict__ a2, const float* __restrict__ mx,
                         __nv_bfloat16* __restrict__ zAh, __nv_bfloat16* __restrict__ zAl,
                         __nv_bfloat16* __restrict__ zBh, __nv_bfloat16* __restrict__ zBl){
    __shared__ float tile[32][33];
    int bz=blockIdx.x;
    const float* p = a2 + (size_t)bz*65536;
    int i0=blockIdx.y*32, j0=blockIdx.z*32;
    tile[threadIdx.y][threadIdx.x] = p[(j0+threadIdx.y)*256 + i0+threadIdx.x];
    __syncthreads();
    float inv = 1.f/(mx[0]*mx[1]);
    long off = (long)bz*PSZ;
    float za = tile[threadIdx.x][threadIdx.y]*inv;
    hilo_st(za, zAh, zAl, off + (long)(i0+threadIdx.y)*256 + (j0+threadIdx.x));
    float zb = tile[threadIdx.y][threadIdx.x]*inv;
    hilo_st(zb, zBh, zBl, off + (long)(j0+threadIdx.y)*256 + (i0+threadIdx.x));
}

__global__ void resconv_k(const float* __restrict__ qkv, const float* __restrict__ rw,
                          float* __restrict__ mg){
    __shared__ float w[33];
    int bz=blockIdx.y; int b=bz>>3, hh=bz&7;
    if (threadIdx.y==0 && threadIdx.x<33) w[threadIdx.x]=rw[hh*33+threadIdx.x];
    __syncthreads();
    int d=threadIdx.x;
    int t=blockIdx.x*8+threadIdx.y;
    const float* vb = qkv + (size_t)b*NPAD*QKVD + 1024 + hh*64 + d;
    float acc=0.f;
    #pragma unroll
    for (int j=0;j<33;j++){
        int ts=t+j-16;
        if (ts>=0 && ts<NPAD) acc += vb[(size_t)ts*QKVD]*w[j];
    }
    mg[((size_t)b*NPAD+t)*DD + hh*64 + d] += acc;
}

__global__ void t2p_k(const float* __restrict__ h, float* __restrict__ pl){
    __shared__ float tile[32][33];
    int b=blockIdx.x, t0=blockIdx.y*32, c0=blockIdx.z*32;
    int t=t0+threadIdx.y, c=c0+threadIdx.x;
    if (t<10000) tile[threadIdx.y][threadIdx.x] = h[((size_t)b*NPAD+PADF+1+t)*DD + c];
    __syncthreads();
    int ch=c0+threadIdx.y, tt=t0+threadIdx.x;
    if (tt<10000) pl[((size_t)b*DD+ch)*10000 + tt] = tile[threadIdx.x][threadIdx.y];
}
__global__ void p2h_k(const float* __restrict__ pl, float* __restrict__ h){
    __shared__ float tile[32][33];
    int b=blockIdx.x, t0=blockIdx.y*32, c0=blockIdx.z*32;
    int ch=c0+threadIdx.y, tt=t0+threadIdx.x;
    if (tt<10000) tile[threadIdx.y][threadIdx.x] = pl[((size_t)b*DD+ch)*10000 + tt];
    __syncthreads();
    int t=t0+threadIdx.y, c=c0+threadIdx.x;
    if (t<10000) h[((size_t)b*NPAD+PADF+1+t)*DD + c] = tile[threadIdx.x][threadIdx.y];
}

__global__ void ppeg_conv_k(const float* __restrict__ pl, float* __restrict__ po,
    const float* __restrict__ w7, const float* __restrict__ b7,
    const float* __restrict__ w5, const float* __restrict__ b5,
    const float* __restrict__ w3, const float* __restrict__ b3){
    __shared__ float sw[86];
    int plane=blockIdx.x; int ch=plane&511;
    int tx=threadIdx.x;
    if      (tx<49) sw[tx]=w7[ch*49+tx];
    else if (tx<74) sw[tx]=w5[ch*25+tx-49];
    else if (tx<83) sw[tx]=w3[ch*9+tx-74];
    else if (tx==83) sw[83]=b7[ch];
    else if (tx==84) sw[84]=b5[ch];
    else if (tx==85) sw[85]=b3[ch];
    __syncthreads();
    int px=blockIdx.y*256+tx;
    if (px>=10000) return;
    int r=px/100, c=px%100;
    const float* in = pl + (size_t)plane*10000;
    float acc = in[px] + sw[83] + sw[84] + sw[85];
    #pragma unroll
    for (int kr=0;kr<7;kr++){
        int rr=r+kr-3; if (rr<0||rr>=100) continue;
        #pragma unroll
        for (int kc=0;kc<7;kc++){
            int cc=c+kc-3; if (cc<0||cc>=100) continue;
            acc += in[rr*100+cc]*sw[kr*7+kc];
        }
    }
    #pragma unroll
    for (int kr=0;kr<5;kr++){
        int rr=r+kr-2; if (rr<0||rr>=100) continue;
        #pragma unroll
        for (int kc=0;kc<5;kc++){
            int cc=c+kc-2; if (cc<0||cc>=100) continue;
            acc += in[rr*100+cc]*sw[49+kr*5+kc];
        }
    }
    #pragma unroll
    for (int kr=0;kr<3;kr++){
        int rr=r+kr-1; if (rr<0||rr>=100) continue;
        #pragma unroll
        for (int kc=0;kc<3;kc++){
            int cc=c+kc-1; if (cc<0||cc>=100) continue;
            acc += in[rr*100+cc]*sw[74+kr*3+kc];
        }
    }
    po[(size_t)plane*10000+px]=acc;
}

__global__ void head_k(const float* __restrict__ cls, const float* __restrict__ w2,
                       const float* __restrict__ b2, float* out, int osz){
    __shared__ float sh[64];
    int b=blockIdx.x;
    float a0=0.f, a1=0.f;
    for (int d=threadIdx.x; d<512; d+=256){
        float x = cls[b*512+d];
        a0 += x*w2[d*2+0]; a1 += x*w2[d*2+1];
    }
    #pragma unroll
    for (int o=16;o;o>>=1){
        a0 += __shfl_xor_sync(0xffffffffu,a0,o);
        a1 += __shfl_xor_sync(0xffffffffu,a1,o);
    }
    int lane=threadIdx.x&31, wid=threadIdx.x>>5;
    if (lane==0){ sh[wid]=a0; sh[wid+32]=a1; }
    __syncthreads();
    if (threadIdx.x==0){
        float l0=b2[0], l1=b2[1];
        for (int w=0;w<8;w++){ l0+=sh[w]; l1+=sh[w+32]; }
        float m=fmaxf(l0,l1);
        float e0=expf(l0-m), e1=expf(l1-m), s=e0+e1;
        if (b*2+1   < osz){ out[b*2]=l0;      out[b*2+1]=l1; }
        if (4+b*2+1 < osz){ out[4+b*2]=e0/s;  out[4+b*2+1]=e1/s; }
        if (8+b     < osz){ out[8+b] = (l1>l0)?1.f:0.f; }
    }
}

// ----------------- driver -----------------
extern "C" void kernel_launch(void* const* d_in, const int* in_sizes, int n_in,
                              void* d_out, int out_size){
    const float* x    =(const float*)d_in[0];
    const float* wfc1 =(const float*)d_in[1];
    const float* bfc1 =(const float*)d_in[2];
    const float* clst =(const float*)d_in[3];
    const float* lng[2]={(const float*)d_in[4],(const float*)d_in[10]};
    const float* lnb[2]={(const float*)d_in[5],(const float*)d_in[11]};
    const float* qkvw[2]={(const float*)d_in[6],(const float*)d_in[12]};
    const float* outw[2]={(const float*)d_in[7],(const float*)d_in[13]};
    const float* outb[2]={(const float*)d_in[8],(const float*)d_in[14]};
    const float* resw[2]={(const float*)d_in[9],(const float*)d_in[15]};
    const float* pw7=(const float*)d_in[16]; const float* pb7=(const float*)d_in[17];
    const float* pw5=(const float*)d_in[18]; const float* pb5=(const float*)d_in[19];
    const float* pw3=(const float*)d_in[20]; const float* pb3=(const float*)d_in[21];
    const float* lnfg=(const float*)d_in[22]; const float* lnfb=(const float*)d_in[23];
    const float* wfc2=(const float*)d_in[24]; const float* bfc2=(const float*)d_in[25];

    float *h,*qkv,*ql,*kl,*s1,*s3,*a2,*zf,*a3v,*pz,*mg,*mx;
    __nv_bfloat16 *xh,*xl,*lnh,*lnl,*mgh,*mgl,*wth,*wtl;
    __nv_bfloat16 *qkvh,*qkvl,*a1h,*a1l,*a3h,*a3l,*vth,*vtl;
    __nv_bfloat16 *qlh,*qll,*klh,*kll,*pzth,*pztl;
    __nv_bfloat16 *pa2h,*pa2l,*pxzh,*pxzl,*pwbh,*pwbl,*ptbh,*ptbl;
    __nv_bfloat16 *pzah[2],*pzal[2],*pzbh[2],*pzbl[2];
    cudaGetSymbolAddress((void**)&h,  g_h);
    cudaGetSymbolAddress((void**)&qkv,g_qkv);
    cudaGetSymbolAddress((void**)&ql, g_ql);
    cudaGetSymbolAddress((void**)&kl, g_kl);
    cudaGetSymbolAddress((void**)&s1, g_s1);
    cudaGetSymbolAddress((void**)&s3, g_s3);
    cudaGetSymbolAddress((void**)&a2, g_a2);
    cudaGetSymbolAddress((void**)&zf, g_z0);
    cudaGetSymbolAddress((void**)&a3v,g_a3v);
    cudaGetSymbolAddress((void**)&pz, g_pz);
    cudaGetSymbolAddress((void**)&mg, g_mg);
    cudaGetSymbolAddress((void**)&mx, g_mx);
    cudaGetSymbolAddress((void**)&xh, g_xh);
    cudaGetSymbolAddress((void**)&xl, g_xl);
    cudaGetSymbolAddress((void**)&lnh,g_lnh);
    cudaGetSymbolAddress((void**)&lnl,g_lnl);
    cudaGetSymbolAddress((void**)&mgh,g_mgh);
    cudaGetSymbolAddress((void**)&mgl,g_mgl);
    cudaGetSymbolAddress((void**)&wth,g_wth);
    cudaGetSymbolAddress((void**)&wtl,g_wtl);
    cudaGetSymbolAddress((void**)&qkvh,g_qkvh);
    cudaGetSymbolAddress((void**)&qkvl,g_qkvl);
    cudaGetSymbolAddress((void**)&a1h,g_a1h);
    cudaGetSymbolAddress((void**)&a1l,g_a1l);
    cudaGetSymbolAddress((void**)&a3h,g_a3h);
    cudaGetSymbolAddress((void**)&a3l,g_a3l);
    cudaGetSymbolAddress((void**)&vth,g_vth);
    cudaGetSymbolAddress((void**)&vtl,g_vtl);
    cudaGetSymbolAddress((void**)&qlh,g_qlh);
    cudaGetSymbolAddress((void**)&qll,g_qll);
    cudaGetSymbolAddress((void**)&klh,g_klh);
    cudaGetSymbolAddress((void**)&kll,g_kll);
    cudaGetSymbolAddress((void**)&pzth,g_pzth);
    cudaGetSymbolAddress((void**)&pztl,g_pztl);
    cudaGetSymbolAddress((void**)&pa2h,g_pa2h);  cudaGetSymbolAddress((void**)&pa2l,g_pa2l);
    cudaGetSymbolAddress((void**)&pxzh,g_pxzh);  cudaGetSymbolAddress((void**)&pxzl,g_pxzl);
    cudaGetSymbolAddress((void**)&pwbh,g_pwbh);  cudaGetSymbolAddress((void**)&pwbl,g_pwbl);
    cudaGetSymbolAddress((void**)&ptbh,g_ptbh);  cudaGetSymbolAddress((void**)&ptbl,g_ptbl);
    cudaGetSymbolAddress((void**)&pzah[0],g_pzah0); cudaGetSymbolAddress((void**)&pzal[0],g_pzal0);
    cudaGetSymbolAddress((void**)&pzbh[0],g_pzbh0); cudaGetSymbolAddress((void**)&pzbl[0],g_pzbl0);
    cudaGetSymbolAddress((void**)&pzah[1],g_pzah1); cudaGetSymbolAddress((void**)&pzal[1],g_pzal1);
    cudaGetSymbolAddress((void**)&pzbh[1],g_pzbh1); cudaGetSymbolAddress((void**)&pzbl[1],g_pzbl1);

    cudaFuncSetAttribute(mm_hmma, cudaFuncAttributeMaxDynamicSharedMemorySize, MMH_SMEM);
    cudaFuncSetAttribute(mm_g,    cudaFuncAttributeMaxDynamicSharedMemorySize, MMH_SMEM);
    cudaFuncSetAttribute(mm_pinv, cudaFuncAttributeMaxDynamicSharedMemorySize, MMH_SMEM);

    // fc1 (HMMA)
    {
        int n = NB*10000*DIN;
        cvt_k<<<(n+255)/256,256>>>(x, xh, xl, n);
        cvtT_k<<<dim3(DIN/32, DD/32), dim3(32,32)>>>(wfc1, wth, wtl, DIN, DD);
        mm_hmma<<<dim3(4,79,NB),256,MMH_SMEM>>>(xh, xl, wth, wtl,
            h+(size_t)(PADF+1)*DD, bfc1, 10000, DIN, DD,
            (long)10000*DIN, (long)NPAD*DD, FB|FR);
    }
    set_cls<<<NB,512>>>(h, clst);

    for (int L=0; L<2; L++){
        ln_k<<<NB*NPAD,256>>>(h, lnh, lnl, lng[L], lnb[L]);
        // qkv (HMMA) + hilo emit
        cvtT_k<<<dim3(DD/32, QKVD/32), dim3(32,32)>>>(qkvw[L], wth, wtl, DD, QKVD);
        mm_g<<<dim3(12,160,1),256,MMH_SMEM>>>(lnh, lnl, wth, wtl,
            qkv, qkvh, qkvl,
            NB*NPAD, QKVD, DD, DD, DD, QKVD,
            0L,0L, 0L,0L, 0L,0L, 1, 160, 1.f, 1, FH);
        landmarks_k<<<dim3(BH,MLAND),64>>>(qkv, ql, kl, qlh,qll, klh,kll);
        // s2 + softmax (pinv input)
        gemm64(ql, kl, a2, nullptr, nullptr,
               256, 256, 64, 64, 64, 256,
               (long)256*64, 0, (long)256*64, 0, (long)65536, 0,
               1, BH, 1.f, 0.f, 1, FTRB);
        softmax256<<<BH*256,256>>>(a2, pa2h, pa2l);
        // s3 = ql @ k^T (HMMA) -> fp32 g_s3
        mm_g<<<dim3(80,2,BH),256,MMH_SMEM>>>(qlh, qll, qkvh+512, qkvl+512,
            s3, nullptr, nullptr,
            256, NPAD, 64, 64, QKVD, NPAD,
            8L*MLAND*64, (long)MLAND*64,
            (long)NPAD*QKVD, 64L,
            8L*MLAND*NPAD, (long)MLAND*NPAD,
            8, 2, 1.f, 1, 0);
        softmaxN_h<<<BH*256,256>>>(s3, a3h, a3l);
        vtrans_k<<<dim3(BH,320,2),dim3(32,32)>>>(qkv, vth, vtl);
        // a3v = a3 @ v (split-K=8 atomic HMMA)
        zerok<<<(BH*256*64+255)/256,256>>>(a3v, BH*256*64);
        mm_g<<<dim3(1,2*8,BH),256,MMH_SMEM>>>(a3h, a3l, vth, vtl,
            a3v, nullptr, nullptr,
            256, 64, NPAD, NPAD, NPAD, 64,
            (long)MLAND*NPAD, 0L, 64L*NPAD, 0L, 16384L, 0L,
            1, 2, 1.f, 8, FAT);
        // pinv chain (HMMA)
        zerok<<<1,256>>>(mx, 2);
        crmax_k<<<BH,256>>>(a2, mx);
        ztrans_k<<<dim3(BH,8,8),dim3(32,32)>>>(a2, mx, pzah[0],pzal[0], pzbh[0],pzbl[0]);
        int c = 0;
        dim3 pg(2,2,BH);
        for (int it=0; it<6; it++){
            mm_pinv<<<pg,256,MMH_SMEM>>>(pa2h,pa2l, pzbh[c],pzbl[c], nullptr,
                pxzh,pxzl, pwbh,pwbl, 1.f, 7.f, PF_A|PF_BD);
            mm_pinv<<<pg,256,MMH_SMEM>>>(pxzh,pxzl, pwbh,pwbl, nullptr,
                nullptr,nullptr, ptbh,ptbl, 1.f, 15.f, PF_BD);
            mm_pinv<<<pg,256,MMH_SMEM>>>(pxzh,pxzl, ptbh,ptbl, nullptr,
                nullptr,nullptr, pwbh,pwbl, 1.f, 13.f, PF_BD);
            mm_pinv<<<pg,256,MMH_SMEM>>>(pzah[c],pzal[c], pwbh,pwbl, zf,
                pzah[1-c],pzal[1-c], pzbh[1-c],pzbl[1-c], 0.25f, 0.f, PF_F|PF_A|PF_BV);
            c ^= 1;
        }
        // pz = pinv(a2) @ a3v ; then transpose to B-layout hilo
        gemm64(zf, a3v, pz, nullptr, nullptr,
               256, 64, 256, 256, 64, 64,
               65536,0, 16384,0, 16384,0, 1, BH, 1.f, 0.f, 1, 0);
        pzt_k<<<dim3(BH,8,2),dim3(32,32)>>>(pz, pzth, pztl);
        // s1 = q @ kl^T (HMMA, alpha=0.125) -> fp32 g_s1
        mm_g<<<dim3(2,80,BH),256,MMH_SMEM>>>(qkvh, qkvl, klh, kll,
            s1, nullptr, nullptr,
            NPAD, 256, 64, QKVD, 64, 256,
            (long)NPAD*QKVD, 64L,
            8L*MLAND*64, (long)MLAND*64,
            8L*NPAD*MLAND, (long)NPAD*MLAND,
            8, 80, 0.125f, 1, 0);
        softmax256h<<<BH*NPAD,256>>>(s1, a1h, a1l);
        // mg = a1 @ pz (HMMA)
        mm_g<<<dim3(1,80,BH),256,MMH_SMEM>>>(a1h, a1l, pzth, pztl,
            mg, nullptr, nullptr,
            NPAD, 64, 256, 256, 256, DD,
            8L*NPAD*MLAND, (long)NPAD*MLAND,
            8L*64*MLAND, 64L*MLAND,
            (long)NPAD*DD, 64L,
            8, 80, 1.f, 1, 0);
        resconv_k<<<dim3(NPAD/8,BH),dim3(64,8)>>>(qkv, resw[L], mg);
        // out-proj (HMMA): h += mg @ w_out + b_out
        {
            int n = NB*NPAD*DD;
            cvt_k<<<(n+255)/256,256>>>(mg, mgh, mgl, n);
            cvtT_k<<<dim3(DD/32, DD/32), dim3(32,32)>>>(outw[L], wth, wtl, DD, DD);
            mm_hmma<<<dim3(4,79,NB),256,MMH_SMEM>>>(
                mgh+(size_t)PADF*DD, mgl+(size_t)PADF*DD, wth, wtl,
                h+(size_t)PADF*DD, outb[L], 10001, DD, DD,
                (long)NPAD*DD, (long)NPAD*DD, FB|FACC);
        }
        if (L==0){
            t2p_k<<<dim3(NB,313,16),dim3(32,32)>>>(h, s1);
            ppeg_conv_k<<<dim3(NB*512,40),256>>>(s1, s3, pw7,pb7, pw5,pb5, pw3,pb3);
            p2h_k<<<dim3(NB,313,16),dim3(32,32)>>>(s3, h);
        }
    }
    lnf_k<<<NB,256>>>(h, a2, lnfg, lnfb);
    head_k<<<NB,256>>>(a2, wfc2, bfc2, (float*)d_out, out_size);
}

// round 16
// speedup vs baseline: 2.0641x; 1.0479x over previous
#include <cuda_runtime.h>
#include <cuda_bf16.h>
#include <cfloat>
#include <cstdint>

#define NB    2
#define DIN   1024
#define DD    512
#define NPAD  10240
#define PADF  239
#define QKVD  1536
#define MLAND 256
#define BH    16

#define FB    1
#define FR    2
#define FACC  4
#define FAT   8
#define FTRB  16
#define FH    32

// pinv epilogue flags
#define PF_F  1
#define PF_A  2
#define PF_BV 4
#define PF_BD 8

#define PSZ 65536
#define PT  (16*PSZ)

// ----------------- device scratch -----------------
__device__ float g_h  [(size_t)NB*NPAD*DD];
__device__ float g_qkv[(size_t)NB*NPAD*QKVD];
__device__ float g_ql [BH*MLAND*64];
__device__ float g_kl [BH*MLAND*64];
__device__ float g_s1 [(size_t)BH*NPAD*MLAND];   // s1 scores; reused: PPEG planar
__device__ float g_s3 [(size_t)BH*MLAND*NPAD];   // s3 scores; reused: PPEG planar
__device__ float g_a2 [BH*MLAND*MLAND];
__device__ float g_z0 [BH*MLAND*MLAND];          // fp32 final pinv (zf)
__device__ float g_a3v[BH*MLAND*64];
__device__ float g_pz [BH*MLAND*64];
__device__ float g_mg [(size_t)NB*NPAD*DD];
__device__ float g_mx [2];

// bf16 hi/lo operands
__device__ __align__(16) __nv_bfloat16 g_xh [(size_t)NB*10000*DIN];
__device__ __align__(16) __nv_bfloat16 g_xl [(size_t)NB*10000*DIN];
__device__ __align__(16) __nv_bfloat16 g_lnh[(size_t)NB*NPAD*DD];
__device__ __align__(16) __nv_bfloat16 g_lnl[(size_t)NB*NPAD*DD];
__device__ __align__(16) __nv_bfloat16 g_mgh[(size_t)NB*NPAD*DD];
__device__ __align__(16) __nv_bfloat16 g_mgl[(size_t)NB*NPAD*DD];
__device__ __align__(16) __nv_bfloat16 g_wth[786432];
__device__ __align__(16) __nv_bfloat16 g_wtl[786432];
__device__ __align__(16) __nv_bfloat16 g_qkvh[(size_t)NB*NPAD*QKVD];
__device__ __align__(16) __nv_bfloat16 g_qkvl[(size_t)NB*NPAD*QKVD];
__device__ __align__(16) __nv_bfloat16 g_a1h[(size_t)BH*NPAD*MLAND];
__device__ __align__(16) __nv_bfloat16 g_a1l[(size_t)BH*NPAD*MLAND];
__device__ __align__(16) __nv_bfloat16 g_a3h[(size_t)BH*MLAND*NPAD];
__device__ __align__(16) __nv_bfloat16 g_a3l[(size_t)BH*MLAND*NPAD];
__device__ __align__(16) __nv_bfloat16 g_vth[(size_t)BH*64*NPAD];
__device__ __align__(16) __nv_bfloat16 g_vtl[(size_t)BH*64*NPAD];
__device__ __align__(16) __nv_bfloat16 g_qlh[BH*MLAND*64], g_qll[BH*MLAND*64];
__device__ __align__(16) __nv_bfloat16 g_klh[BH*MLAND*64], g_kll[BH*MLAND*64];
__device__ __align__(16) __nv_bfloat16 g_pzth[BH*64*MLAND], g_pztl[BH*64*MLAND];

// pinv hi/lo buffers
__device__ __align__(16) __nv_bfloat16 g_pa2h[PT], g_pa2l[PT];
__device__ __align__(16) __nv_bfloat16 g_pxzh[PT], g_pxzl[PT];
__device__ __align__(16) __nv_bfloat16 g_pwbh[PT], g_pwbl[PT];
__device__ __align__(16) __nv_bfloat16 g_ptbh[PT], g_ptbl[PT];
__device__ __align__(16) __nv_bfloat16 g_pzah0[PT], g_pzal0[PT], g_pzbh0[PT], g_pzbl0[PT];
__device__ __align__(16) __nv_bfloat16 g_pzah1[PT], g_pzal1[PT], g_pzbh1[PT], g_pzbl1[PT];

// ----------------- fast exp2 (FFMA-only, rel err ~8e-6) -----------------
__device__ __forceinline__ float fexp2(float y){
    y = fmaxf(y, -120.f);
    float fl = floorf(y);
    float f = y - fl;
    float p = 1.54036e-4f;
    p = fmaf(p, f, 1.33336e-3f);
    p = fmaf(p, f, 9.61813e-3f);
    p = fmaf(p, f, 5.55041e-2f);
    p = fmaf(p, f, 2.40227e-1f);
    p = fmaf(p, f, 6.93147e-1f);
    p = fmaf(p, f, 1.0f);
    return p * __int_as_float(((int)fl + 127) << 23);
}
#define LOG2E 1.44269504f

// ----------------- helpers -----------------
__device__ __forceinline__ uint32_t smem_u32(const void* p){
    uint32_t a;
    asm("{ .reg .u64 t; cvta.to.shared.u64 t, %1; cvt.u32.u64 %0, t; }" : "=r"(a) : "l"(p));
    return a;
}
__device__ __forceinline__ void cpasync16(uint32_t d, const void* s, int sz){
    asm volatile("cp.async.cg.shared.global [%0], [%1], 16, %2;"
        :: "r"(d), "l"(s), "r"(sz) : "memory");
}
__device__ __forceinline__ void ldmx4(uint32_t* r, uint32_t a){
    asm volatile("ldmatrix.sync.aligned.m8n8.x4.shared.b16 {%0,%1,%2,%3},[%4];"
        : "=r"(r[0]), "=r"(r[1]), "=r"(r[2]), "=r"(r[3]) : "r"(a));
}
__device__ __forceinline__ void mma_bf16(float* c, const uint32_t* a, uint32_t b0, uint32_t b1){
    asm volatile("mma.sync.aligned.m16n8k16.row.col.f32.bf16.bf16.f32 "
        "{%0,%1,%2,%3},{%4,%5,%6,%7},{%8,%9},{%0,%1,%2,%3};"
        : "+f"(c[0]), "+f"(c[1]), "+f"(c[2]), "+f"(c[3])
        : "r"(a[0]), "r"(a[1]), "r"(a[2]), "r"(a[3]), "r"(b0), "r"(b1));
}
__device__ __forceinline__ void hilo_st(float v, __nv_bfloat16* H, __nv_bfloat16* L, long i){
    __nv_bfloat16 h = __float2bfloat16(v);
    H[i] = h;
    L[i] = __float2bfloat16(v - __bfloat162float(h));
}

// ----------------- block reductions -----------------
__device__ __forceinline__ float bsum(float v, float* sh){
    int lane = threadIdx.x & 31, wid = threadIdx.x >> 5;
    #pragma unroll
    for (int o=16;o;o>>=1) v += __shfl_xor_sync(0xffffffffu, v, o);
    if (lane==0) sh[wid]=v;
    __syncthreads();
    if (wid==0){
        int nw = blockDim.x >> 5;
        float r = (lane<nw) ? sh[lane] : 0.f;
        #pragma unroll
        for (int o=16;o;o>>=1) r += __shfl_xor_sync(0xffffffffu, r, o);
        if (lane==0) sh[0]=r;
    }
    __syncthreads();
    float out = sh[0];
    __syncthreads();
    return out;
}
__device__ __forceinline__ float bmax(float v, float* sh){
    int lane = threadIdx.x & 31, wid = threadIdx.x >> 5;
    #pragma unroll
    for (int o=16;o;o>>=1) v = fmaxf(v, __shfl_xor_sync(0xffffffffu, v, o));
    if (lane==0) sh[wid]=v;
    __syncthreads();
    if (wid==0){
        int nw = blockDim.x >> 5;
        float r = (lane<nw) ? sh[lane] : -FLT_MAX;
        #pragma unroll
        for (int o=16;o;o>>=1) r = fmaxf(r, __shfl_xor_sync(0xffffffffu, r, o));
        if (lane==0) sh[0]=r;
    }
    __syncthreads();
    float out = sh[0];
    __syncthreads();
    return out;
}

// ----------------- HMMA GEMM (proven): C = A @ B^T, simple strides -----------------
#define MMH_TS   (128*72)
#define MMH_BUFB (4*MMH_TS*2)
#define MMH_SMEM (2*MMH_BUFB)
__global__ void __launch_bounds__(256, 1)
mm_hmma(const __nv_bfloat16* __restrict__ Ah, const __nv_bfloat16* __restrict__ Al,
        const __nv_bfloat16* __restrict__ Bh, const __nv_bfloat16* __restrict__ Bl,
        float* __restrict__ C, const float* __restrict__ bias,
        int M, int K, int ldc, long sA, long sC, int flags)
{
    extern __shared__ __nv_bfloat16 smb[];
    uint32_t sbase = smem_u32(smb);
    int tid = threadIdx.x, wid = tid >> 5, lane = tid & 31;
    int col0 = blockIdx.x * 128, row0 = blockIdx.y * 128;
    long bz = blockIdx.z;
    Ah += bz * sA;  Al += bz * sA;
    float* Cb = C + bz * sC;

    int wm = wid & 3, wn = wid >> 2;
    float acc[2][8][4] = {};
    const int S = K >> 6;

    auto issue = [&](int s){
        int b = s & 1;
        uint32_t dst = sbase + (uint32_t)b * MMH_BUFB;
        int k0 = s << 6;
        #pragma unroll
        for (int i = 0; i < 4; i++){
            int ch = tid + i*256;
            int r = ch >> 3, c8 = ch & 7;
            uint32_t off = (uint32_t)(r*144 + c8*16);
            int gm = row0 + r;
            int sz = (gm < M) ? 16 : 0;
            cpasync16(dst + off,              Ah + (long)gm*K + k0 + c8*8, sz);
            cpasync16(dst + MMH_TS*2 + off,   Al + (long)gm*K + k0 + c8*8, sz);
            long gn = col0 + r;
            cpasync16(dst + 2*MMH_TS*2 + off, Bh + gn*K + k0 + c8*8, 16);
            cpasync16(dst + 3*MMH_TS*2 + off, Bl + gn*K + k0 + c8*8, 16);
        }
        asm volatile("cp.async.commit_group;" ::: "memory");
    };

    issue(0);
    for (int s = 0; s < S; s++){
        if (s + 1 < S){
            issue(s + 1);
            asm volatile("cp.async.wait_group 1;" ::: "memory");
        } else {
            asm volatile("cp.async.wait_group 0;" ::: "memory");
        }
        __syncthreads();
        uint32_t buf = sbase + (uint32_t)(s & 1) * MMH_BUFB;
        uint32_t aH = buf, aL = buf + MMH_TS*2;
        uint32_t bHb = buf + 2*MMH_TS*2, bLb = buf + 3*MMH_TS*2;
        #pragma unroll
        for (int ks = 0; ks < 4; ks++){
            int kc = ks * 16;
            uint32_t ah[2][4], al[2][4];
            #pragma unroll
            for (int mi = 0; mi < 2; mi++){
                int rowb = wm*32 + mi*16 + (lane & 15);
                uint32_t o = (uint32_t)(rowb*144 + kc*2 + (lane >> 4)*16);
                ldmx4(ah[mi], aH + o);
                ldmx4(al[mi], aL + o);
            }
            #pragma unroll
            for (int nb = 0; nb < 4; nb++){
                int g = lane >> 3;
                int rown = wn*64 + nb*16 + (g >> 1)*8 + (lane & 7);
                uint32_t bo = (uint32_t)(rown*144 + kc*2 + (g & 1)*16);
                uint32_t bh[4], bl[4];
                ldmx4(bh, bHb + bo);
                ldmx4(bl, bLb + bo);
                #pragma unroll
                for (int mi = 0; mi < 2; mi++){
                    #pragma unroll
                    for (int hf = 0; hf < 2; hf++){
                        float* c = acc[mi][nb*2 + hf];
                        mma_bf16(c, ah[mi], bh[hf*2], bh[hf*2+1]);
                        mma_bf16(c, ah[mi], bl[hf*2], bl[hf*2+1]);
                        mma_bf16(c, al[mi], bh[hf*2], bh[hf*2+1]);
                    }
                }
            }
        }
        __syncthreads();
    }

    int gID = lane >> 2, tig = lane & 3;
    #pragma unroll
    for (int mi = 0; mi < 2; mi++){
        #pragma unroll
        for (int nj = 0; nj < 8; nj++){
            int colb = col0 + wn*64 + nj*8 + tig*2;
            #pragma unroll
            for (int rh = 0; rh < 2; rh++){
                int gm = row0 + wm*32 + mi*16 + rh*8 + gID;
                if (gm >= M) continue;
                float v0 = acc[mi][nj][rh*2+0];
                float v1 = acc[mi][nj][rh*2+1];
                float* cp = Cb + (long)gm*ldc + colb;
                if (flags & FB){ v0 += bias[colb]; v1 += bias[colb+1]; }
                if (flags & FACC){ v0 += cp[0]; v1 += cp[1]; }
                if (flags & FR){ v0 = fmaxf(v0, 0.f); v1 = fmaxf(v1, 0.f); }
                cp[0] = v0; cp[1] = v1;
            }
        }
    }
}

// ----------------- generalized HMMA GEMM: strided batch, split-K, hilo-emit -----------------
__global__ void __launch_bounds__(256, 1)
mm_g(const __nv_bfloat16* __restrict__ Ah, const __nv_bfloat16* __restrict__ Al,
     const __nv_bfloat16* __restrict__ Bh, const __nv_bfloat16* __restrict__ Bl,
     float* __restrict__ Cf, __nv_bfloat16* __restrict__ Ch, __nv_bfloat16* __restrict__ Cl,
     int M, int N, int K, int lda, int ldb, int ldc,
     long sA1, long sA2, long sB1, long sB2, long sC1, long sC2,
     int nh, int nTM, float alpha, int kSplit, int flags)
{
    extern __shared__ __nv_bfloat16 smb[];
    uint32_t sbase = smem_u32(smb);
    int tid = threadIdx.x, wid = tid >> 5, lane = tid & 31;
    int col0 = blockIdx.x * 128;
    int row0 = (blockIdx.y % nTM) * 128;
    int kIdx = blockIdx.y / nTM;
    int bz = blockIdx.z;
    long ab = (long)(bz/nh)*sA1 + (long)(bz%nh)*sA2;
    long bb = (long)(bz/nh)*sB1 + (long)(bz%nh)*sB2;
    long cb = (long)(bz/nh)*sC1 + (long)(bz%nh)*sC2;
    int kChunk = K / kSplit;
    int k0 = kIdx * kChunk;
    const int S = kChunk >> 6;

    int wm = wid & 3, wn = wid >> 2;
    float acc[2][8][4] = {};

    auto issue = [&](int s){
        uint32_t dst = sbase + (uint32_t)(s & 1) * MMH_BUFB;
        int kk = k0 + (s << 6);
        #pragma unroll
        for (int i = 0; i < 4; i++){
            int ch = tid + i*256;
            int r = ch >> 3, c8 = ch & 7;
            uint32_t off = (uint32_t)(r*144 + c8*16);
            int gm = row0 + r;
            int sza = (gm < M) ? 16 : 0;
            cpasync16(dst + off,              Ah + ab + (long)gm*lda + kk + c8*8, sza);
            cpasync16(dst + MMH_TS*2 + off,   Al + ab + (long)gm*lda + kk + c8*8, sza);
            int gn = col0 + r;
            int szb = (gn < N) ? 16 : 0;
            cpasync16(dst + 2*MMH_TS*2 + off, Bh + bb + (long)gn*ldb + kk + c8*8, szb);
            cpasync16(dst + 3*MMH_TS*2 + off, Bl + bb + (long)gn*ldb + kk + c8*8, szb);
        }
        asm volatile("cp.async.commit_group;" ::: "memory");
    };

    issue(0);
    for (int s = 0; s < S; s++){
        if (s + 1 < S){
            issue(s + 1);
            asm volatile("cp.async.wait_group 1;" ::: "memory");
        } else {
            asm volatile("cp.async.wait_group 0;" ::: "memory");
        }
        __syncthreads();
        uint32_t buf = sbase + (uint32_t)(s & 1) * MMH_BUFB;
        uint32_t aH = buf, aL = buf + MMH_TS*2;
        uint32_t bHb = buf + 2*MMH_TS*2, bLb = buf + 3*MMH_TS*2;
        #pragma unroll
        for (int ks = 0; ks < 4; ks++){
            int kc = ks * 16;
            uint32_t ah[2][4], al[2][4];
            #pragma unroll
            for (int mi = 0; mi < 2; mi++){
                int rowb = wm*32 + mi*16 + (lane & 15);
                uint32_t o = (uint32_t)(rowb*144 + kc*2 + (lane >> 4)*16);
                ldmx4(ah[mi], aH + o);
                ldmx4(al[mi], aL + o);
            }
            #pragma unroll
            for (int nb = 0; nb < 4; nb++){
                int g = lane >> 3;
                int rown = wn*64 + nb*16 + (g >> 1)*8 + (lane & 7);
                uint32_t bo = (uint32_t)(rown*144 + kc*2 + (g & 1)*16);
                uint32_t bh[4], bl[4];
                ldmx4(bh, bHb + bo);
                ldmx4(bl, bLb + bo);
                #pragma unroll
                for (int mi = 0; mi < 2; mi++){
                    #pragma unroll
                    for (int hf = 0; hf < 2; hf++){
                        float* c = acc[mi][nb*2 + hf];
                        mma_bf16(c, ah[mi], bh[hf*2], bh[hf*2+1]);
                        mma_bf16(c, ah[mi], bl[hf*2], bl[hf*2+1]);
                        mma_bf16(c, al[mi], bh[hf*2], bh[hf*2+1]);
                    }
                }
            }
        }
        __syncthreads();
    }

    int gID = lane >> 2, tig = lane & 3;
    #pragma unroll
    for (int mi = 0; mi < 2; mi++){
        #pragma unroll
        for (int nj = 0; nj < 8; nj++){
            int colb = col0 + wn*64 + nj*8 + tig*2;
            if (colb >= N) continue;
            #pragma unroll
            for (int rh = 0; rh < 2; rh++){
                int gm = row0 + wm*32 + mi*16 + rh*8 + gID;
                if (gm >= M) continue;
                float v0 = acc[mi][nj][rh*2+0]*alpha;
                float v1 = acc[mi][nj][rh*2+1]*alpha;
                long idx = cb + (long)gm*ldc + colb;
                if (flags & FAT){
                    atomicAdd(&Cf[idx], v0);
                    atomicAdd(&Cf[idx+1], v1);
                } else {
                    if (flags & FACC){ v0 += Cf[idx]; v1 += Cf[idx+1]; }
                    if (flags & FR){ v0 = fmaxf(v0,0.f); v1 = fmaxf(v1,0.f); }
                    Cf[idx] = v0; Cf[idx+1] = v1;
                }
                if (flags & FH){
                    hilo_st(v0, Ch, Cl, idx);
                    hilo_st(v1, Ch, Cl, idx+1);
                }
            }
        }
    }
}

// ----------------- HMMA pinv GEMM (proven) -----------------
__global__ void __launch_bounds__(256, 1)
mm_pinv(const __nv_bfloat16* __restrict__ Ah, const __nv_bfloat16* __restrict__ Al,
        const __nv_bfloat16* __restrict__ Bh, const __nv_bfloat16* __restrict__ Bl,
        float* __restrict__ Cf,
        __nv_bfloat16* __restrict__ Xh, __nv_bfloat16* __restrict__ Xl,
        __nv_bfloat16* __restrict__ Yh, __nv_bfloat16* __restrict__ Yl,
        float alpha, float dval, int flags)
{
    extern __shared__ __nv_bfloat16 smb[];
    uint32_t sbase = smem_u32(smb);
    int tid = threadIdx.x, wid = tid >> 5, lane = tid & 31;
    int col0 = blockIdx.x * 128, row0 = blockIdx.y * 128;
    long off = (long)blockIdx.z * PSZ;
    Ah += off; Al += off; Bh += off; Bl += off;

    int wm = wid & 3, wn = wid >> 2;
    float acc[2][8][4] = {};

    auto issue = [&](int s){
        uint32_t dst = sbase + (uint32_t)(s & 1) * MMH_BUFB;
        int k0 = s << 6;
        #pragma unroll
        for (int i = 0; i < 4; i++){
            int ch = tid + i*256;
            int r = ch >> 3, c8 = ch & 7;
            uint32_t o2 = (uint32_t)(r*144 + c8*16);
            cpasync16(dst + o2,              Ah + (long)(row0+r)*256 + k0 + c8*8, 16);
            cpasync16(dst + MMH_TS*2 + o2,   Al + (long)(row0+r)*256 + k0 + c8*8, 16);
            cpasync16(dst + 2*MMH_TS*2 + o2, Bh + (long)(col0+r)*256 + k0 + c8*8, 16);
            cpasync16(dst + 3*MMH_TS*2 + o2, Bl + (long)(col0+r)*256 + k0 + c8*8, 16);
        }
        asm volatile("cp.async.commit_group;" ::: "memory");
    };

    issue(0);
    for (int s = 0; s < 4; s++){
        if (s + 1 < 4){
            issue(s + 1);
            asm volatile("cp.async.wait_group 1;" ::: "memory");
        } else {
            asm volatile("cp.async.wait_group 0;" ::: "memory");
        }
        __syncthreads();
        uint32_t buf = sbase + (uint32_t)(s & 1) * MMH_BUFB;
        uint32_t aH = buf, aL = buf + MMH_TS*2;
        uint32_t bHb = buf + 2*MMH_TS*2, bLb = buf + 3*MMH_TS*2;
        #pragma unroll
        for (int ks = 0; ks < 4; ks++){
            int kc = ks * 16;
            uint32_t ah[2][4], al[2][4];
            #pragma unroll
            for (int mi = 0; mi < 2; mi++){
                int rowb = wm*32 + mi*16 + (lane & 15);
                uint32_t o = (uint32_t)(rowb*144 + kc*2 + (lane >> 4)*16);
                ldmx4(ah[mi], aH + o);
                ldmx4(al[mi], aL + o);
            }
            #pragma unroll
            for (int nb = 0; nb < 4; nb++){
                int g = lane >> 3;
                int rown = wn*64 + nb*16 + (g >> 1)*8 + (lane & 7);
                uint32_t bo = (uint32_t)(rown*144 + kc*2 + (g & 1)*16);
                uint32_t bh[4], bl[4];
                ldmx4(bh, bHb + bo);
                ldmx4(bl, bLb + bo);
                #pragma unroll
                for (int mi = 0; mi < 2; mi++){
                    #pragma unroll
                    for (int hf = 0; hf < 2; hf++){
                        float* c = acc[mi][nb*2 + hf];
                        mma_bf16(c, ah[mi], bh[hf*2], bh[hf*2+1]);
                        mma_bf16(c, ah[mi], bl[hf*2], bl[hf*2+1]);
                        mma_bf16(c, al[mi], bh[hf*2], bh[hf*2+1]);
                    }
                }
            }
        }
        __syncthreads();
    }

    int gID = lane >> 2, tig = lane & 3;
    #pragma unroll
    for (int mi = 0; mi < 2; mi++){
        #pragma unroll
        for (int nj = 0; nj < 8; nj++){
            int cb2 = col0 + wn*64 + nj*8 + tig*2;
            #pragma unroll
            for (int rh = 0; rh < 2; rh++){
                int gm = row0 + wm*32 + mi*16 + rh*8 + gID;
                float v0 = acc[mi][nj][rh*2+0]*alpha;
                float v1 = acc[mi][nj][rh*2+1]*alpha;
                long i0 = off + (long)gm*256 + cb2;
                if (flags & PF_F){ Cf[i0] = v0; Cf[i0+1] = v1; }
                if (flags & PF_A){
                    hilo_st(v0, Xh, Xl, i0);
                    hilo_st(v1, Xh, Xl, i0+1);
                }
                if (flags & (PF_BV|PF_BD)){
                    float w0 = v0, w1 = v1;
                    if (flags & PF_BD){
                        w0 = ((gm==cb2  )?dval:0.f) - v0;
                        w1 = ((gm==cb2+1)?dval:0.f) - v1;
                    }
                    long j0 = off + (long)cb2*256 + gm;
                    hilo_st(w0, Yh, Yl, j0);
                    hilo_st(w1, Yh, Yl, j0+256);
                }
            }
        }
    }
}

// ----------------- conversions -----------------
__global__ void cvt_k(const float* __restrict__ s, __nv_bfloat16* __restrict__ hi,
                      __nv_bfloat16* __restrict__ lo, int n){
    int i = blockIdx.x*256 + threadIdx.x;
    if (i < n){
        float v = s[i];
        __nv_bfloat16 h = __float2bfloat16(v);
        hi[i] = h;
        lo[i] = __float2bfloat16(v - __bfloat162float(h));
    }
}
__global__ void cvtT_k(const float* __restrict__ W, __nv_bfloat16* __restrict__ th,
                       __nv_bfloat16* __restrict__ tl, int K, int N){
    __shared__ float t[32][33];
    int k0 = blockIdx.x*32, n0 = blockIdx.y*32;
    t[threadIdx.y][threadIdx.x] = W[(k0+threadIdx.y)*N + n0+threadIdx.x];
    __syncthreads();
    int n = n0+threadIdx.y, k = k0+threadIdx.x;
    float v = t[threadIdx.x][threadIdx.y];
    __nv_bfloat16 h = __float2bfloat16(v);
    th[(size_t)n*K+k] = h;
    tl[(size_t)n*K+k] = __float2bfloat16(v - __bfloat162float(h));
}
__global__ void vtrans_k(const float* __restrict__ qkv, __nv_bfloat16* __restrict__ VH,
                         __nv_bfloat16* __restrict__ VL){
    __shared__ float tile[32][33];
    int bh=blockIdx.x, b=bh>>3, h=bh&7;
    int t0=blockIdx.y*32, d0=blockIdx.z*32;
    tile[threadIdx.y][threadIdx.x] =
        qkv[((size_t)b*NPAD + t0+threadIdx.y)*QKVD + 1024 + h*64 + d0+threadIdx.x];
    __syncthreads();
    long o = ((size_t)bh*64 + d0+threadIdx.y)*NPAD + t0+threadIdx.x;
    hilo_st(tile[threadIdx.x][threadIdx.y], VH, VL, o);
}
__global__ void pzt_k(const float* __restrict__ pz, __nv_bfloat16* __restrict__ H,
                      __nv_bfloat16* __restrict__ L){
    __shared__ float tile[32][33];
    int bh=blockIdx.x;
    int l0=blockIdx.y*32, d0=blockIdx.z*32;
    tile[threadIdx.y][threadIdx.x] = pz[((size_t)bh*256 + l0+threadIdx.y)*64 + d0+threadIdx.x];
    __syncthreads();
    long o = ((size_t)bh*64 + d0+threadIdx.y)*256 + l0+threadIdx.x;
    hilo_st(tile[threadIdx.x][threadIdx.y], H, L, o);
}

// ----------------- fp32 batched GEMM (pz only) -----------------
template<int BM,int BN,int BK,int TM,int TN,int MAXB>
__global__ void __launch_bounds__((BM/TM)*(BN/TN), MAXB)
gemm_k(const float* __restrict__ A, const float* __restrict__ Bp,
       float* C, float* C2, const float* __restrict__ bias,
       int M,int N,int K,int lda,int ldb,int ldc,
       long sA1,long sA2,long sB1,long sB2,long sC1,long sC2,
       int nh,float alpha,float dval,int nTN,int kSplit,int flags)
{
    constexpr int THREADS=(BM/TM)*(BN/TN);
    constexpr int LA = BM*BK/THREADS;
    constexpr int LB = BK*BN/THREADS;
    __shared__ float As[2][BK][BM];
    __shared__ float Bs[2][BK][BN+1];
    int bz=blockIdx.z;
    A  += (long)(bz/nh)*sA1 + (long)(bz%nh)*sA2;
    Bp += (long)(bz/nh)*sB1 + (long)(bz%nh)*sB2;
    long offC = (long)(bz/nh)*sC1 + (long)(bz%nh)*sC2;
    int kIdx=blockIdx.x/nTN;
    int col0=(blockIdx.x%nTN)*BN;
    int row0=blockIdx.y*BM;
    int kChunk=(K+kSplit-1)/kSplit;
    int k0=kIdx*kChunk, k1=min(K,k0+kChunk);
    int tid=threadIdx.x;
    int tm=tid/(BN/TN), tn=tid%(BN/TN);
    bool trb = (flags & FTRB) != 0;
    float acc[TM][TN] = {};
    float pa[LA], pb[LB];

    auto loadT = [&](int kk){
        #pragma unroll
        for (int it=0; it<LA; it++){
            int i=tid+it*THREADS;
            int m=i/BK, k=i%BK;
            int gm=row0+m, gk=kk+k;
            pa[it] = (gm<M && gk<k1) ? A[(long)gm*lda+gk] : 0.f;
        }
        #pragma unroll
        for (int it=0; it<LB; it++){
            int i=tid+it*THREADS;
            int k,n;
            if (trb){ n=i/BK; k=i%BK; } else { k=i/BN; n=i%BN; }
            int gk=kk+k, gn=col0+n;
            pb[it] = (gk<k1 && gn<N) ? (trb ? Bp[(long)gn*ldb+gk] : Bp[(long)gk*ldb+gn]) : 0.f;
        }
    };
    auto storeT = [&](int b){
        #pragma unroll
        for (int it=0; it<LA; it++){
            int i=tid+it*THREADS;
            int m=i/BK, k=i%BK;
            As[b][k][m]=pa[it];
        }
        #pragma unroll
        for (int it=0; it<LB; it++){
            int i=tid+it*THREADS;
            int k,n;
            if (trb){ n=i/BK; k=i%BK; } else { k=i/BN; n=i%BN; }
            Bs[b][k][n]=pb[it];
        }
    };

    loadT(k0);
    storeT(0);
    __syncthreads();
    int buf=0;
    for (int kk=k0; kk<k1; kk+=BK){
        bool hn = (kk+BK) < k1;
        if (hn) loadT(kk+BK);
        #pragma unroll
        for (int k=0;k<BK;k++){
            float ra[TM], rb[TN];
            #pragma unroll
            for (int i=0;i<TM;i++) ra[i]=As[buf][k][tm*TM+i];
            #pragma unroll
            for (int j=0;j<TN;j++) rb[j]=Bs[buf][k][tn*TN+j];
            #pragma unroll
            for (int i=0;i<TM;i++)
                #pragma unroll
                for (int j=0;j<TN;j++) acc[i][j] += ra[i]*rb[j];
        }
        if (hn) storeT(buf^1);
        __syncthreads();
        buf^=1;
    }
    #pragma unroll
    for (int i=0;i<TM;i++){
        int gm=row0+tm*TM+i; if (gm>=M) continue;
        #pragma unroll
        for (int j=0;j<TN;j++){
            int gn=col0+tn*TN+j; if (gn>=N) continue;
            float v = acc[i][j]*alpha;
            if (flags&FB) v += bias[gn];
            long idx = offC + (long)gm*ldc + gn;
            if (C2) C2[idx] = ((gm==gn)?dval:0.f) - v;
            if (C){
                if (flags&FAT) atomicAdd(&C[idx], v);
                else {
                    float o = v;
                    if (flags&FACC) o += C[idx];
                    if (flags&FR)   o = fmaxf(o, 0.f);
                    C[idx] = o;
                }
            }
        }
    }
}

static void gemm64(const float*A,const float*B,float*C,float*C2,const float*bias,
    int M,int N,int K,int lda,int ldb,int ldc,
    long a1,long a2,long b1,long b2,long c1,long c2,int nh,int batch,
    float alpha,float dval,int kSplit,int flags)
{
    int nTN=(N+63)/64, nTM=(M+63)/64;
    dim3 g(nTN*kSplit, nTM, batch);
    gemm_k<64,64,16,4,4,2><<<g,256>>>(A,B,C,C2,bias,M,N,K,lda,ldb,ldc,
        a1,a2,b1,b2,c1,c2,nh,alpha,dval,nTN,kSplit,flags);
}

// ----------------- elementwise / reduction kernels -----------------
__global__ void set_cls(float* h, const float* __restrict__ cls){
    h[((size_t)blockIdx.x*NPAD + PADF)*DD + threadIdx.x] = cls[threadIdx.x];
}

__global__ void ln_k(const float* __restrict__ h, __nv_bfloat16* __restrict__ oh,
                     __nv_bfloat16* __restrict__ ol,
                     const float* __restrict__ g, const float* __restrict__ b){
    __shared__ float sh[32];
    size_t row = blockIdx.x;
    int t = (int)(row % NPAD);
    __nv_bfloat16* ph = oh + row*(size_t)DD;
    __nv_bfloat16* pl = ol + row*(size_t)DD;
    int tx = threadIdx.x;
    __nv_bfloat16 z = __float2bfloat16(0.f);
    if (t < PADF){ ph[tx]=z; ph[tx+256]=z; pl[tx]=z; pl[tx+256]=z; return; }
    const float* p = h + row*(size_t)DD;
    float x0=p[tx], x1=p[tx+256];
    float mu  = bsum(x0+x1, sh) * (1.f/512.f);
    float d0=x0-mu, d1=x1-mu;
    float var = bsum(d0*d0+d1*d1, sh) * (1.f/512.f);
    float rs = rsqrtf(var + 1e-5f);
    float y0 = d0*rs*g[tx]     + b[tx];
    float y1 = d1*rs*g[tx+256] + b[tx+256];
    __nv_bfloat16 h0 = __float2bfloat16(y0);
    __nv_bfloat16 h1 = __float2bfloat16(y1);
    ph[tx]     = h0; pl[tx]     = __float2bfloat16(y0 - __bfloat162float(h0));
    ph[tx+256] = h1; pl[tx+256] = __float2bfloat16(y1 - __bfloat162float(h1));
}

__global__ void lnf_k(const float* __restrict__ h, float* __restrict__ o,
                      const float* __restrict__ g, const float* __restrict__ b){
    __shared__ float sh[32];
    const float* p = h + ((size_t)blockIdx.x*NPAD + PADF)*DD;
    int tx = threadIdx.x;
    float x0=p[tx], x1=p[tx+256];
    float mu  = bsum(x0+x1, sh) * (1.f/512.f);
    float d0=x0-mu, d1=x1-mu;
    float var = bsum(d0*d0+d1*d1, sh) * (1.f/512.f);
    float rs = rsqrtf(var + 1e-5f);
    o[blockIdx.x*DD+tx]     = d0*rs*g[tx]     + b[tx];
    o[blockIdx.x*DD+tx+256] = d1*rs*g[tx+256] + b[tx+256];
}

__global__ void landmarks_k(const float* __restrict__ qkv,
                            float* __restrict__ ql, float* __restrict__ kl,
                            __nv_bfloat16* qlh, __nv_bfloat16* qll,
                            __nv_bfloat16* klh, __nv_bfloat16* kll){
    int bz=blockIdx.x, m=blockIdx.y, d=threadIdx.x;
    int b=bz>>3, hh=bz&7;
    const float* base = qkv + ((size_t)b*NPAD + (size_t)m*40)*QKVD + hh*64 + d;
    float sq=0.f, sk=0.f;
    #pragma unroll 8
    for (int j=0;j<40;j++){ sq += base[(size_t)j*QKVD]; sk += base[(size_t)j*QKVD+512]; }
    long i = ((size_t)bz*MLAND+m)*64+d;
    float vq = sq*0.003125f, vk = sk*0.025f;
    ql[i]=vq; kl[i]=vk;
    hilo_st(vq, qlh, qll, i);
    hilo_st(vk, klh, kll, i);
}

// softmax rows of 256 -> fp32 + bf16 hilo (for pinv input a2)
__global__ void softmax256(float* __restrict__ X, __nv_bfloat16* __restrict__ Xh,
                           __nv_bfloat16* __restrict__ Xl){
    __shared__ float sh[32];
    float* p = X + (size_t)blockIdx.x*256;
    float v = p[threadIdx.x];
    float m = bmax(v, sh);
    float e = fexp2((v - m)*LOG2E);
    float s = bsum(e, sh);
    float r = e / s;
    p[threadIdx.x] = r;
    long i = (long)blockIdx.x*256 + threadIdx.x;
    hilo_st(r, Xh, Xl, i);
}

// warp-per-row softmax of 256-wide rows -> bf16 hilo only (a1 probs); 8 rows/block
__global__ void softmax256h(const float* __restrict__ X, __nv_bfloat16* __restrict__ H,
                            __nv_bfloat16* __restrict__ L){
    long row = (long)blockIdx.x*8 + (threadIdx.x >> 5);
    int lane = threadIdx.x & 31;
    const float4* p = (const float4*)(X + row*256);
    float4 v0 = p[lane], v1 = p[lane+32];
    float m = fmaxf(fmaxf(fmaxf(v0.x,v0.y), fmaxf(v0.z,v0.w)),
                    fmaxf(fmaxf(v1.x,v1.y), fmaxf(v1.z,v1.w)));
    #pragma unroll
    for (int o=16;o;o>>=1) m = fmaxf(m, __shfl_xor_sync(0xffffffffu, m, o));
    float e[8];
    e[0]=fexp2((v0.x-m)*LOG2E); e[1]=fexp2((v0.y-m)*LOG2E);
    e[2]=fexp2((v0.z-m)*LOG2E); e[3]=fexp2((v0.w-m)*LOG2E);
    e[4]=fexp2((v1.x-m)*LOG2E); e[5]=fexp2((v1.y-m)*LOG2E);
    e[6]=fexp2((v1.z-m)*LOG2E); e[7]=fexp2((v1.w-m)*LOG2E);
    float s = (e[0]+e[1])+(e[2]+e[3])+(e[4]+e[5])+(e[6]+e[7]);
    #pragma unroll
    for (int o=16;o;o>>=1) s += __shfl_xor_sync(0xffffffffu, s, o);
    float inv = 1.f/s;
    long b0 = row*256 + lane*4;
    #pragma unroll
    for (int j=0;j<4;j++) hilo_st(e[j]*inv,   H, L, b0+j);
    #pragma unroll
    for (int j=0;j<4;j++) hilo_st(e[4+j]*inv, H, L, b0+128+j);
}

// softmax rows of NPAD -> bf16 hilo only (a3 probs); register-cached
__global__ void softmaxN_h(const float* __restrict__ X, __nv_bfloat16* __restrict__ H,
                           __nv_bfloat16* __restrict__ L){
    __shared__ float sh[32];
    const float* p = X + (size_t)blockIdx.x*NPAD;
    int tx = threadIdx.x;
    float r[40];
    float m = -FLT_MAX;
    #pragma unroll
    for (int i=0;i<40;i++){ r[i]=p[tx+i*256]; m = fmaxf(m, r[i]); }
    m = bmax(m, sh);
    float s = 0.f;
    #pragma unroll
    for (int i=0;i<40;i++){ r[i]=fexp2((r[i]-m)*LOG2E); s += r[i]; }
    s = bsum(s, sh);
    float inv = 1.f/s;
    size_t base = (size_t)blockIdx.x*NPAD + tx;
    #pragma unroll
    for (int i=0;i<40;i++) hilo_st(r[i]*inv, H, L, base + i*256);
}

__global__ void zerok(float* p, int n){
    int i = blockIdx.x*256 + threadIdx.x;
    if (i<n) p[i]=0.f;
}

__global__ void crmax_k(const float* __restrict__ a2, float* mx){
    __shared__ float sh[32];
    const float* p = a2 + (size_t)blockIdx.x*65536;
    int t = threadIdx.x;
    float cs=0.f, rs=0.f;
    for (int m=0;m<256;m++){ cs += p[m*256+t]; rs += p[t*256+m]; }
    float mc = bmax(cs, sh);
    float mr = bmax(rs, sh);
    if (t==0){
        atomicMax((int*)&mx[0], __float_as_int(mc));
        atomicMax((int*)&mx[1], __float_as_int(mr));
    }
}

__global__ void ztrans_k(const float* __restrict__ a2, const float* __restrict__ mx,
                         __nv_bfloat16* __restrict__ zAh, __nv_bfloat16* __restrict__ zAl,
                         __nv_bfloat16* __restrict__ zBh, __nv_bfloat16* __restrict__ zBl){
    __shared__ float tile[32][33];
    int bz=blockIdx.x;
    const float* p = a2 + (size_t)bz*65536;
    int i0=blockIdx.y*32, j0=blockIdx.z*32;
    tile[threadIdx.y][threadIdx.x] = p[(j0+threadIdx.y)*256 + i0+threadIdx.x];
    __syncthreads();
    float inv = 1.f/(mx[0]*mx[1]);
    long off = (long)bz*PSZ;
    float za = tile[threadIdx.x][threadIdx.y]*inv;
    hilo_st(za, zAh, zAl, off + (long)(i0+threadIdx.y)*256 + (j0+threadIdx.x));
    float zb = tile[threadIdx.y][threadIdx.x]*inv;
    hilo_st(zb, zBh, zBl, off + (long)(j0+threadIdx.y)*256 + (i0+threadIdx.x));
}

__global__ void resconv_k(const float* __restrict__ qkv, const float* __restrict__ rw,
                          float* __restrict__ mg){
    __shared__ float w[33];
    int bz=blockIdx.y; int b=bz>>3, hh=bz&7;
    if (threadIdx.y==0 && threadIdx.x<33) w[threadIdx.x]=rw[hh*33+threadIdx.x];
    __syncthreads();
    int d=threadIdx.x;
    int t=blockIdx.x*8+threadIdx.y;
    const float* vb = qkv + (size_t)b*NPAD*QKVD + 1024 + hh*64 + d;
    float acc=0.f;
    #pragma unroll
    for (int j=0;j<33;j++){
        int ts=t+j-16;
        if (ts>=0 && ts<NPAD) acc += vb[(size_t)ts*QKVD]*w[j];
    }
    mg[((size_t)b*NPAD+t)*DD + hh*64 + d] += acc;
}

__global__ void t2p_k(const float* __restrict__ h, float* __restrict__ pl){
    __shared__ float tile[32][33];
    int b=blockIdx.x, t0=blockIdx.y*32, c0=blockIdx.z*32;
    int t=t0+threadIdx.y, c=c0+threadIdx.x;
    if (t<10000) tile[threadIdx.y][threadIdx.x] = h[((size_t)b*NPAD+PADF+1+t)*DD + c];
    __syncthreads();
    int ch=c0+threadIdx.y, tt=t0+threadIdx.x;
    if (tt<10000) pl[((size_t)b*DD+ch)*10000 + tt] = tile[threadIdx.x][threadIdx.y];
}
__global__ void p2h_k(const float* __restrict__ pl, float* __restrict__ h){
    __shared__ float tile[32][33];
    int b=blockIdx.x, t0=blockIdx.y*32, c0=blockIdx.z*32;
    int ch=c0+threadIdx.y, tt=t0+threadIdx.x;
    if (tt<10000) tile[threadIdx.y][threadIdx.x] = pl[((size_t)b*DD+ch)*10000 + tt];
    __syncthreads();
    int t=t0+threadIdx.y, c=c0+threadIdx.x;
    if (t<10000) h[((size_t)b*NPAD+PADF+1+t)*DD + c] = tile[threadIdx.x][threadIdx.y];
}

__global__ void ppeg_conv_k(const float* __restrict__ pl, float* __restrict__ po,
    const float* __restrict__ w7, const float* __restrict__ b7,
    const float* __restrict__ w5, const float* __restrict__ b5,
    const float* __restrict__ w3, const float* __restrict__ b3){
    __shared__ float sw[86];
    int plane=blockIdx.x; int ch=plane&511;
    int tx=threadIdx.x;
    if      (tx<49) sw[tx]=w7[ch*49+tx];
    else if (tx<74) sw[tx]=w5[ch*25+tx-49];
    else if (tx<83) sw[tx]=w3[ch*9+tx-74];
    else if (tx==83) sw[83]=b7[ch];
    else if (tx==84) sw[84]=b5[ch];
    else if (tx==85) sw[85]=b3[ch];
    __syncthreads();
    int px=blockIdx.y*256+tx;
    if (px>=10000) return;
    int r=px/100, c=px%100;
    const float* in = pl + (size_t)plane*10000;
    float acc = in[px] + sw[83] + sw[84] + sw[85];
    #pragma unroll
    for (int kr=0;kr<7;kr++){
        int rr=r+kr-3; if (rr<0||rr>=100) continue;
        #pragma unroll
        for (int kc=0;kc<7;kc++){
            int cc=c+kc-3; if (cc<0||cc>=100) continue;
            acc += in[rr*100+cc]*sw[kr*7+kc];
        }
    }
    #pragma unroll
    for (int kr=0;kr<5;kr++){
        int rr=r+kr-2; if (rr<0||rr>=100) continue;
        #pragma unroll
        for (int kc=0;kc<5;kc++){
            int cc=c+kc-2; if (cc<0||cc>=100) continue;
            acc += in[rr*100+cc]*sw[49+kr*5+kc];
        }
    }
    #pragma unroll
    for (int kr=0;kr<3;kr++){
        int rr=r+kr-1; if (rr<0||rr>=100) continue;
        #pragma unroll
        for (int kc=0;kc<3;kc++){
            int cc=c+kc-1; if (cc<0||cc>=100) continue;
            acc += in[rr*100+cc]*sw[74+kr*3+kc];
        }
    }
    po[(size_t)plane*10000+px]=acc;
}

__global__ void head_k(const float* __restrict__ cls, const float* __restrict__ w2,
                       const float* __restrict__ b2, float* out, int osz){
    __shared__ float sh[64];
    int b=blockIdx.x;
    float a0=0.f, a1=0.f;
    for (int d=threadIdx.x; d<512; d+=256){
        float x = cls[b*512+d];
        a0 += x*w2[d*2+0]; a1 += x*w2[d*2+1];
    }
    #pragma unroll
    for (int o=16;o;o>>=1){
        a0 += __shfl_xor_sync(0xffffffffu,a0,o);
        a1 += __shfl_xor_sync(0xffffffffu,a1,o);
    }
    int lane=threadIdx.x&31, wid=threadIdx.x>>5;
    if (lane==0){ sh[wid]=a0; sh[wid+32]=a1; }
    __syncthreads();
    if (threadIdx.x==0){
        float l0=b2[0], l1=b2[1];
        for (int w=0;w<8;w++){ l0+=sh[w]; l1+=sh[w+32]; }
        float m=fmaxf(l0,l1);
        float e0=expf(l0-m), e1=expf(l1-m), s=e0+e1;
        if (b*2+1   < osz){ out[b*2]=l0;      out[b*2+1]=l1; }
        if (4+b*2+1 < osz){ out[4+b*2]=e0/s;  out[4+b*2+1]=e1/s; }
        if (8+b     < osz){ out[8+b] = (l1>l0)?1.f:0.f; }
    }
}

// ----------------- driver -----------------
extern "C" void kernel_launch(void* const* d_in, const int* in_sizes, int n_in,
                              void* d_out, int out_size){
    const float* x    =(const float*)d_in[0];
    const float* wfc1 =(const float*)d_in[1];
    const float* bfc1 =(const float*)d_in[2];
    const float* clst =(const float*)d_in[3];
    const float* lng[2]={(const float*)d_in[4],(const float*)d_in[10]};
    const float* lnb[2]={(const float*)d_in[5],(const float*)d_in[11]};
    const float* qkvw[2]={(const float*)d_in[6],(const float*)d_in[12]};
    const float* outw[2]={(const float*)d_in[7],(const float*)d_in[13]};
    const float* outb[2]={(const float*)d_in[8],(const float*)d_in[14]};
    const float* resw[2]={(const float*)d_in[9],(const float*)d_in[15]};
    const float* pw7=(const float*)d_in[16]; const float* pb7=(const float*)d_in[17];
    const float* pw5=(const float*)d_in[18]; const float* pb5=(const float*)d_in[19];
    const float* pw3=(const float*)d_in[20]; const float* pb3=(const float*)d_in[21];
    const float* lnfg=(const float*)d_in[22]; const float* lnfb=(const float*)d_in[23];
    const float* wfc2=(const float*)d_in[24]; const float* bfc2=(const float*)d_in[25];

    float *h,*qkv,*ql,*kl,*s1,*s3,*a2,*zf,*a3v,*pz,*mg,*mx;
    __nv_bfloat16 *xh,*xl,*lnh,*lnl,*mgh,*mgl,*wth,*wtl;
    __nv_bfloat16 *qkvh,*qkvl,*a1h,*a1l,*a3h,*a3l,*vth,*vtl;
    __nv_bfloat16 *qlh,*qll,*klh,*kll,*pzth,*pztl;
    __nv_bfloat16 *pa2h,*pa2l,*pxzh,*pxzl,*pwbh,*pwbl,*ptbh,*ptbl;
    __nv_bfloat16 *pzah[2],*pzal[2],*pzbh[2],*pzbl[2];
    cudaGetSymbolAddress((void**)&h,  g_h);
    cudaGetSymbolAddress((void**)&qkv,g_qkv);
    cudaGetSymbolAddress((void**)&ql, g_ql);
    cudaGetSymbolAddress((void**)&kl, g_kl);
    cudaGetSymbolAddress((void**)&s1, g_s1);
    cudaGetSymbolAddress((void**)&s3, g_s3);
    cudaGetSymbolAddress((void**)&a2, g_a2);
    cudaGetSymbolAddress((void**)&zf, g_z0);
    cudaGetSymbolAddress((void**)&a3v,g_a3v);
    cudaGetSymbolAddress((void**)&pz, g_pz);
    cudaGetSymbolAddress((void**)&mg, g_mg);
    cudaGetSymbolAddress((void**)&mx, g_mx);
    cudaGetSymbolAddress((void**)&xh, g_xh);
    cudaGetSymbolAddress((void**)&xl, g_xl);
    cudaGetSymbolAddress((void**)&lnh,g_lnh);
    cudaGetSymbolAddress((void**)&lnl,g_lnl);
    cudaGetSymbolAddress((void**)&mgh,g_mgh);
    cudaGetSymbolAddress((void**)&mgl,g_mgl);
    cudaGetSymbolAddress((void**)&wth,g_wth);
    cudaGetSymbolAddress((void**)&wtl,g_wtl);
    cudaGetSymbolAddress((void**)&qkvh,g_qkvh);
    cudaGetSymbolAddress((void**)&qkvl,g_qkvl);
    cudaGetSymbolAddress((void**)&a1h,g_a1h);
    cudaGetSymbolAddress((void**)&a1l,g_a1l);
    cudaGetSymbolAddress((void**)&a3h,g_a3h);
    cudaGetSymbolAddress((void**)&a3l,g_a3l);
    cudaGetSymbolAddress((void**)&vth,g_vth);
    cudaGetSymbolAddress((void**)&vtl,g_vtl);
    cudaGetSymbolAddress((void**)&qlh,g_qlh);
    cudaGetSymbolAddress((void**)&qll,g_qll);
    cudaGetSymbolAddress((void**)&klh,g_klh);
    cudaGetSymbolAddress((void**)&kll,g_kll);
    cudaGetSymbolAddress((void**)&pzth,g_pzth);
    cudaGetSymbolAddress((void**)&pztl,g_pztl);
    cudaGetSymbolAddress((void**)&pa2h,g_pa2h);  cudaGetSymbolAddress((void**)&pa2l,g_pa2l);
    cudaGetSymbolAddress((void**)&pxzh,g_pxzh);  cudaGetSymbolAddress((void**)&pxzl,g_pxzl);
    cudaGetSymbolAddress((void**)&pwbh,g_pwbh);  cudaGetSymbolAddress((void**)&pwbl,g_pwbl);
    cudaGetSymbolAddress((void**)&ptbh,g_ptbh);  cudaGetSymbolAddress((void**)&ptbl,g_ptbl);
    cudaGetSymbolAddress((void**)&pzah[0],g_pzah0); cudaGetSymbolAddress((void**)&pzal[0],g_pzal0);
    cudaGetSymbolAddress((void**)&pzbh[0],g_pzbh0); cudaGetSymbolAddress((void**)&pzbl[0],g_pzbl0);
    cudaGetSymbolAddress((void**)&pzah[1],g_pzah1); cudaGetSymbolAddress((void**)&pzal[1],g_pzal1);
    cudaGetSymbolAddress((void**)&pzbh[1],g_pzbh1); cudaGetSymbolAddress((void**)&pzbl[1],g_pzbl1);

    cudaFuncSetAttribute(mm_hmma, cudaFuncAttributeMaxDynamicSharedMemorySize, MMH_SMEM);
    cudaFuncSetAttribute(mm_g,    cudaFuncAttributeMaxDynamicSharedMemorySize, MMH_SMEM);
    cudaFuncSetAttribute(mm_pinv, cudaFuncAttributeMaxDynamicSharedMemorySize, MMH_SMEM);

    // fc1 (HMMA)
    {
        int n = NB*10000*DIN;
        cvt_k<<<(n+255)/256,256>>>(x, xh, xl, n);
        cvtT_k<<<dim3(DIN/32, DD/32), dim3(32,32)>>>(wfc1, wth, wtl, DIN, DD);
        mm_hmma<<<dim3(4,79,NB),256,MMH_SMEM>>>(xh, xl, wth, wtl,
            h+(size_t)(PADF+1)*DD, bfc1, 10000, DIN, DD,
            (long)10000*DIN, (long)NPAD*DD, FB|FR);
    }
    set_cls<<<NB,512>>>(h, clst);

    for (int L=0; L<2; L++){
        ln_k<<<NB*NPAD,256>>>(h, lnh, lnl, lng[L], lnb[L]);
        // qkv (HMMA) + hilo emit
        cvtT_k<<<dim3(DD/32, QKVD/32), dim3(32,32)>>>(qkvw[L], wth, wtl, DD, QKVD);
        mm_g<<<dim3(12,160,1),256,MMH_SMEM>>>(lnh, lnl, wth, wtl,
            qkv, qkvh, qkvl,
            NB*NPAD, QKVD, DD, DD, DD, QKVD,
            0L,0L, 0L,0L, 0L,0L, 1, 160, 1.f, 1, FH);
        landmarks_k<<<dim3(BH,MLAND),64>>>(qkv, ql, kl, qlh,qll, klh,kll);
        // s2 = ql @ kl^T (HMMA, S=1, small smem) -> a2 fp32, then softmax + hilo
        mm_g<<<dim3(2,2,BH),256,MMH_BUFB>>>(qlh, qll, klh, kll,
            a2, nullptr, nullptr,
            256, 256, 64, 64, 64, 256,
            (long)MLAND*64, 0L, (long)MLAND*64, 0L, (long)PSZ, 0L,
            1, 2, 1.f, 1, 0);
        softmax256<<<BH*256,256>>>(a2, pa2h, pa2l);
        // s3 = ql @ k^T (HMMA, S=1, small smem)
        mm_g<<<dim3(80,2,BH),256,MMH_BUFB>>>(qlh, qll, qkvh+512, qkvl+512,
            s3, nullptr, nullptr,
            256, NPAD, 64, 64, QKVD, NPAD,
            8L*MLAND*64, (long)MLAND*64,
            (long)NPAD*QKVD, 64L,
            8L*MLAND*NPAD, (long)MLAND*NPAD,
            8, 2, 1.f, 1, 0);
        softmaxN_h<<<BH*256,256>>>(s3, a3h, a3l);
        vtrans_k<<<dim3(BH,320,2),dim3(32,32)>>>(qkv, vth, vtl);
        // a3v = a3 @ v (split-K=8 atomic HMMA)
        zerok<<<(BH*256*64+255)/256,256>>>(a3v, BH*256*64);
        mm_g<<<dim3(1,2*8,BH),256,MMH_SMEM>>>(a3h, a3l, vth, vtl,
            a3v, nullptr, nullptr,
            256, 64, NPAD, NPAD, NPAD, 64,
            (long)MLAND*NPAD, 0L, 64L*NPAD, 0L, 16384L, 0L,
            1, 2, 1.f, 8, FAT);
        // pinv chain (HMMA)
        zerok<<<1,256>>>(mx, 2);
        crmax_k<<<BH,256>>>(a2, mx);
        ztrans_k<<<dim3(BH,8,8),dim3(32,32)>>>(a2, mx, pzah[0],pzal[0], pzbh[0],pzbl[0]);
        int c = 0;
        dim3 pg(2,2,BH);
        for (int it=0; it<6; it++){
            mm_pinv<<<pg,256,MMH_SMEM>>>(pa2h,pa2l, pzbh[c],pzbl[c], nullptr,
                pxzh,pxzl, pwbh,pwbl, 1.f, 7.f, PF_A|PF_BD);
            mm_pinv<<<pg,256,MMH_SMEM>>>(pxzh,pxzl, pwbh,pwbl, nullptr,
                nullptr,nullptr, ptbh,ptbl, 1.f, 15.f, PF_BD);
            mm_pinv<<<pg,256,MMH_SMEM>>>(pxzh,pxzl, ptbh,ptbl, nullptr,
                nullptr,nullptr, pwbh,pwbl, 1.f, 13.f, PF_BD);
            mm_pinv<<<pg,256,MMH_SMEM>>>(pzah[c],pzal[c], pwbh,pwbl, zf,
                pzah[1-c],pzal[1-c], pzbh[1-c],pzbl[1-c], 0.25f, 0.f, PF_F|PF_A|PF_BV);
            c ^= 1;
        }
        // pz = pinv(a2) @ a3v ; then transpose to B-layout hilo
        gemm64(zf, a3v, pz, nullptr, nullptr,
               256, 64, 256, 256, 64, 64,
               65536,0, 16384,0, 16384,0, 1, BH, 1.f, 0.f, 1, 0);
        pzt_k<<<dim3(BH,8,2),dim3(32,32)>>>(pz, pzth, pztl);
        // s1 = q @ kl^T (HMMA, alpha=0.125, S=1, small smem)
        mm_g<<<dim3(2,80,BH),256,MMH_BUFB>>>(qkvh, qkvl, klh, kll,
            s1, nullptr, nullptr,
            NPAD, 256, 64, QKVD, 64, 256,
            (long)NPAD*QKVD, 64L,
            8L*MLAND*64, (long)MLAND*64,
            8L*NPAD*MLAND, (long)NPAD*MLAND,
            8, 80, 0.125f, 1, 0);
        softmax256h<<<BH*NPAD/8,256>>>(s1, a1h, a1l);
        // mg = a1 @ pz (HMMA)
        mm_g<<<dim3(1,80,BH),256,MMH_SMEM>>>(a1h, a1l, pzth, pztl,
            mg, nullptr, nullptr,
            NPAD, 64, 256, 256, 256, DD,
            8L*NPAD*MLAND, (long)NPAD*MLAND,
            8L*64*MLAND, 64L*MLAND,
            (long)NPAD*DD, 64L,
            8, 80, 1.f, 1, 0);
        resconv_k<<<dim3(NPAD/8,BH),dim3(64,8)>>>(qkv, resw[L], mg);
        // out-proj (HMMA): h += mg @ w_out + b_out
        {
            int n = NB*NPAD*DD;
            cvt_k<<<(n+255)/256,256>>>(mg, mgh, mgl, n);
            cvtT_k<<<dim3(DD/32, DD/32), dim3(32,32)>>>(outw[L], wth, wtl, DD, DD);
            mm_hmma<<<dim3(4,79,NB),256,MMH_SMEM>>>(
                mgh+(size_t)PADF*DD, mgl+(size_t)PADF*DD, wth, wtl,
                h+(size_t)PADF*DD, outb[L], 10001, DD, DD,
                (long)NPAD*DD, (long)NPAD*DD, FB|FACC);
        }
        if (L==0){
            t2p_k<<<dim3(NB,313,16),dim3(32,32)>>>(h, s1);
            ppeg_conv_k<<<dim3(NB*512,40),256>>>(s1, s3, pw7,pb7, pw5,pb5, pw3,pb3);
            p2h_k<<<dim3(NB,313,16),dim3(32,32)>>>(s3, h);
        }
    }
    lnf_k<<<NB,256>>>(h, a2, lnfg, lnfb);
    head_k<<<NB,256>>>(a2, wfc2, bfc2, (float*)d_out, out_size);
}

// round 17
// speedup vs baseline: 2.1303x; 1.0321x over previous
#include <cuda_runtime.h>
#include <cuda_bf16.h>
#include <cfloat>
#include <cstdint>

#define NB    2
#define DIN   1024
#define DD    512
#define NPAD  10240
#define PADF  239
#define QKVD  1536
#define MLAND 256
#define BH    16

#define FB    1
#define FR    2
#define FACC  4
#define FAT   8
#define FTRB  16
#define FH    32

// pinv epilogue flags
#define PF_F  1
#define PF_A  2
#define PF_BV 4
#define PF_BD 8

#define PSZ 65536
#define PT  (16*PSZ)

// ----------------- device scratch -----------------
__device__ float g_h  [(size_t)NB*NPAD*DD];
__device__ float g_qkv[(size_t)NB*NPAD*QKVD];
__device__ float g_ql [BH*MLAND*64];
__device__ float g_kl [BH*MLAND*64];
__device__ float g_s1 [(size_t)BH*NPAD*MLAND];   // s1 scores; reused: PPEG planar
__device__ float g_s3 [(size_t)BH*MLAND*NPAD];   // s3 scores; reused: PPEG planar
__device__ float g_a2 [BH*MLAND*MLAND];
__device__ float g_z0 [BH*MLAND*MLAND];          // fp32 final pinv (zf)
__device__ float g_a3v[BH*MLAND*64];
__device__ float g_pz [BH*MLAND*64];
__device__ float g_mg [(size_t)NB*NPAD*DD];
__device__ float g_mx [2];

// bf16 hi/lo operands
__device__ __align__(16) __nv_bfloat16 g_xh [(size_t)NB*10000*DIN];
__device__ __align__(16) __nv_bfloat16 g_xl [(size_t)NB*10000*DIN];
__device__ __align__(16) __nv_bfloat16 g_lnh[(size_t)NB*NPAD*DD];
__device__ __align__(16) __nv_bfloat16 g_lnl[(size_t)NB*NPAD*DD];
__device__ __align__(16) __nv_bfloat16 g_mgh[(size_t)NB*NPAD*DD];
__device__ __align__(16) __nv_bfloat16 g_mgl[(size_t)NB*NPAD*DD];
__device__ __align__(16) __nv_bfloat16 g_wth[786432];
__device__ __align__(16) __nv_bfloat16 g_wtl[786432];
__device__ __align__(16) __nv_bfloat16 g_qkvh[(size_t)NB*NPAD*QKVD];
__device__ __align__(16) __nv_bfloat16 g_qkvl[(size_t)NB*NPAD*QKVD];
__device__ __align__(16) __nv_bfloat16 g_a1h[(size_t)BH*NPAD*MLAND];
__device__ __align__(16) __nv_bfloat16 g_a3h[(size_t)BH*MLAND*NPAD];
__device__ __align__(16) __nv_bfloat16 g_vth[(size_t)BH*64*NPAD];
__device__ __align__(16) __nv_bfloat16 g_vtl[(size_t)BH*64*NPAD];
__device__ __align__(16) __nv_bfloat16 g_qlh[BH*MLAND*64], g_qll[BH*MLAND*64];
__device__ __align__(16) __nv_bfloat16 g_klh[BH*MLAND*64], g_kll[BH*MLAND*64];
__device__ __align__(16) __nv_bfloat16 g_pzth[BH*64*MLAND], g_pztl[BH*64*MLAND];

// pinv hi/lo buffers
__device__ __align__(16) __nv_bfloat16 g_pa2h[PT], g_pa2l[PT];
__device__ __align__(16) __nv_bfloat16 g_pxzh[PT], g_pxzl[PT];
__device__ __align__(16) __nv_bfloat16 g_pwbh[PT], g_pwbl[PT];
__device__ __align__(16) __nv_bfloat16 g_ptbh[PT], g_ptbl[PT];
__device__ __align__(16) __nv_bfloat16 g_pzah0[PT], g_pzal0[PT], g_pzbh0[PT], g_pzbl0[PT];
__device__ __align__(16) __nv_bfloat16 g_pzah1[PT], g_pzal1[PT], g_pzbh1[PT], g_pzbl1[PT];

// ----------------- fast exp2 (FFMA-only, rel err ~8e-6) -----------------
__device__ __forceinline__ float fexp2(float y){
    y = fmaxf(y, -120.f);
    float fl = floorf(y);
    float f = y - fl;
    float p = 1.54036e-4f;
    p = fmaf(p, f, 1.33336e-3f);
    p = fmaf(p, f, 9.61813e-3f);
    p = fmaf(p, f, 5.55041e-2f);
    p = fmaf(p, f, 2.40227e-1f);
    p = fmaf(p, f, 6.93147e-1f);
    p = fmaf(p, f, 1.0f);
    return p * __int_as_float(((int)fl + 127) << 23);
}
#define LOG2E 1.44269504f

// ----------------- helpers -----------------
__device__ __forceinline__ uint32_t smem_u32(const void* p){
    uint32_t a;
    asm("{ .reg .u64 t; cvta.to.shared.u64 t, %1; cvt.u32.u64 %0, t; }" : "=r"(a) : "l"(p));
    return a;
}
__device__ __forceinline__ void cpasync16(uint32_t d, const void* s, int sz){
    asm volatile("cp.async.cg.shared.global [%0], [%1], 16, %2;"
        :: "r"(d), "l"(s), "r"(sz) : "memory");
}
__device__ __forceinline__ void ldmx4(uint32_t* r, uint32_t a){
    asm volatile("ldmatrix.sync.aligned.m8n8.x4.shared.b16 {%0,%1,%2,%3},[%4];"
        : "=r"(r[0]), "=r"(r[1]), "=r"(r[2]), "=r"(r[3]) : "r"(a));
}
__device__ __forceinline__ void mma_bf16(float* c, const uint32_t* a, uint32_t b0, uint32_t b1){
    asm volatile("mma.sync.aligned.m16n8k16.row.col.f32.bf16.bf16.f32 "
        "{%0,%1,%2,%3},{%4,%5,%6,%7},{%8,%9},{%0,%1,%2,%3};"
        : "+f"(c[0]), "+f"(c[1]), "+f"(c[2]), "+f"(c[3])
        : "r"(a[0]), "r"(a[1]), "r"(a[2]), "r"(a[3]), "r"(b0), "r"(b1));
}
__device__ __forceinline__ void hilo_st(float v, __nv_bfloat16* H, __nv_bfloat16* L, long i){
    __nv_bfloat16 h = __float2bfloat16(v);
    H[i] = h;
    L[i] = __float2bfloat16(v - __bfloat162float(h));
}
__device__ __forceinline__ void prob_st(float v, __nv_bfloat16* H, __nv_bfloat16* L, long i){
    __nv_bfloat16 h = __float2bfloat16(v);
    H[i] = h;
    if (L) L[i] = __float2bfloat16(v - __bfloat162float(h));
}

// ----------------- block reductions -----------------
__device__ __forceinline__ float bsum(float v, float* sh){
    int lane = threadIdx.x & 31, wid = threadIdx.x >> 5;
    #pragma unroll
    for (int o=16;o;o>>=1) v += __shfl_xor_sync(0xffffffffu, v, o);
    if (lane==0) sh[wid]=v;
    __syncthreads();
    if (wid==0){
        int nw = blockDim.x >> 5;
        float r = (lane<nw) ? sh[lane] : 0.f;
        #pragma unroll
        for (int o=16;o;o>>=1) r += __shfl_xor_sync(0xffffffffu, r, o);
        if (lane==0) sh[0]=r;
    }
    __syncthreads();
    float out = sh[0];
    __syncthreads();
    return out;
}
__device__ __forceinline__ float bmax(float v, float* sh){
    int lane = threadIdx.x & 31, wid = threadIdx.x >> 5;
    #pragma unroll
    for (int o=16;o;o>>=1) v = fmaxf(v, __shfl_xor_sync(0xffffffffu, v, o));
    if (lane==0) sh[wid]=v;
    __syncthreads();
    if (wid==0){
        int nw = blockDim.x >> 5;
        float r = (lane<nw) ? sh[lane] : -FLT_MAX;
        #pragma unroll
        for (int o=16;o;o>>=1) r = fmaxf(r, __shfl_xor_sync(0xffffffffu, r, o));
        if (lane==0) sh[0]=r;
    }
    __syncthreads();
    float out = sh[0];
    __syncthreads();
    return out;
}

// ----------------- HMMA GEMM (proven): C = A @ B^T, simple strides -----------------
#define MMH_TS   (128*72)
#define MMH_BUFB (4*MMH_TS*2)
#define MMH_SMEM (2*MMH_BUFB)
__global__ void __launch_bounds__(256, 1)
mm_hmma(const __nv_bfloat16* __restrict__ Ah, const __nv_bfloat16* __restrict__ Al,
        const __nv_bfloat16* __restrict__ Bh, const __nv_bfloat16* __restrict__ Bl,
        float* __restrict__ C, const float* __restrict__ bias,
        int M, int K, int ldc, long sA, long sC, int flags)
{
    extern __shared__ __nv_bfloat16 smb[];
    uint32_t sbase = smem_u32(smb);
    int tid = threadIdx.x, wid = tid >> 5, lane = tid & 31;
    int col0 = blockIdx.x * 128, row0 = blockIdx.y * 128;
    long bz = blockIdx.z;
    Ah += bz * sA;  Al += bz * sA;
    float* Cb = C + bz * sC;

    int wm = wid & 3, wn = wid >> 2;
    float acc[2][8][4] = {};
    const int S = K >> 6;

    auto issue = [&](int s){
        int b = s & 1;
        uint32_t dst = sbase + (uint32_t)b * MMH_BUFB;
        int k0 = s << 6;
        #pragma unroll
        for (int i = 0; i < 4; i++){
            int ch = tid + i*256;
            int r = ch >> 3, c8 = ch & 7;
            uint32_t off = (uint32_t)(r*144 + c8*16);
            int gm = row0 + r;
            int sz = (gm < M) ? 16 : 0;
            cpasync16(dst + off,              Ah + (long)gm*K + k0 + c8*8, sz);
            cpasync16(dst + MMH_TS*2 + off,   Al + (long)gm*K + k0 + c8*8, sz);
            long gn = col0 + r;
            cpasync16(dst + 2*MMH_TS*2 + off, Bh + gn*K + k0 + c8*8, 16);
            cpasync16(dst + 3*MMH_TS*2 + off, Bl + gn*K + k0 + c8*8, 16);
        }
        asm volatile("cp.async.commit_group;" ::: "memory");
    };

    issue(0);
    for (int s = 0; s < S; s++){
        if (s + 1 < S){
            issue(s + 1);
            asm volatile("cp.async.wait_group 1;" ::: "memory");
        } else {
            asm volatile("cp.async.wait_group 0;" ::: "memory");
        }
        __syncthreads();
        uint32_t buf = sbase + (uint32_t)(s & 1) * MMH_BUFB;
        uint32_t aH = buf, aL = buf + MMH_TS*2;
        uint32_t bHb = buf + 2*MMH_TS*2, bLb = buf + 3*MMH_TS*2;
        #pragma unroll
        for (int ks = 0; ks < 4; ks++){
            int kc = ks * 16;
            uint32_t ah[2][4], al[2][4];
            #pragma unroll
            for (int mi = 0; mi < 2; mi++){
                int rowb = wm*32 + mi*16 + (lane & 15);
                uint32_t o = (uint32_t)(rowb*144 + kc*2 + (lane >> 4)*16);
                ldmx4(ah[mi], aH + o);
                ldmx4(al[mi], aL + o);
            }
            #pragma unroll
            for (int nb = 0; nb < 4; nb++){
                int g = lane >> 3;
                int rown = wn*64 + nb*16 + (g >> 1)*8 + (lane & 7);
                uint32_t bo = (uint32_t)(rown*144 + kc*2 + (g & 1)*16);
                uint32_t bh[4], bl[4];
                ldmx4(bh, bHb + bo);
                ldmx4(bl, bLb + bo);
                #pragma unroll
                for (int mi = 0; mi < 2; mi++){
                    #pragma unroll
                    for (int hf = 0; hf < 2; hf++){
                        float* c = acc[mi][nb*2 + hf];
                        mma_bf16(c, ah[mi], bh[hf*2], bh[hf*2+1]);
                        mma_bf16(c, ah[mi], bl[hf*2], bl[hf*2+1]);
                        mma_bf16(c, al[mi], bh[hf*2], bh[hf*2+1]);
                    }
                }
            }
        }
        __syncthreads();
    }

    int gID = lane >> 2, tig = lane & 3;
    #pragma unroll
    for (int mi = 0; mi < 2; mi++){
        #pragma unroll
        for (int nj = 0; nj < 8; nj++){
            int colb = col0 + wn*64 + nj*8 + tig*2;
            #pragma unroll
            for (int rh = 0; rh < 2; rh++){
                int gm = row0 + wm*32 + mi*16 + rh*8 + gID;
                if (gm >= M) continue;
                float v0 = acc[mi][nj][rh*2+0];
                float v1 = acc[mi][nj][rh*2+1];
                float* cp = Cb + (long)gm*ldc + colb;
                if (flags & FB){ v0 += bias[colb]; v1 += bias[colb+1]; }
                if (flags & FACC){ v0 += cp[0]; v1 += cp[1]; }
                if (flags & FR){ v0 = fmaxf(v0, 0.f); v1 = fmaxf(v1, 0.f); }
                cp[0] = v0; cp[1] = v1;
            }
        }
    }
}

// ----------------- generalized HMMA GEMM: strided batch, split-K, hilo-emit, A-only -----------------
__global__ void __launch_bounds__(256, 1)
mm_g(const __nv_bfloat16* __restrict__ Ah, const __nv_bfloat16* __restrict__ Al,
     const __nv_bfloat16* __restrict__ Bh, const __nv_bfloat16* __restrict__ Bl,
     float* __restrict__ Cf, __nv_bfloat16* __restrict__ Ch, __nv_bfloat16* __restrict__ Cl,
     int M, int N, int K, int lda, int ldb, int ldc,
     long sA1, long sA2, long sB1, long sB2, long sC1, long sC2,
     int nh, int nTM, float alpha, int kSplit, int flags)
{
    extern __shared__ __nv_bfloat16 smb[];
    uint32_t sbase = smem_u32(smb);
    int tid = threadIdx.x, wid = tid >> 5, lane = tid & 31;
    int col0 = blockIdx.x * 128;
    int row0 = (blockIdx.y % nTM) * 128;
    int kIdx = blockIdx.y / nTM;
    int bz = blockIdx.z;
    const bool aonly = (Al == nullptr);
    long ab = (long)(bz/nh)*sA1 + (long)(bz%nh)*sA2;
    long bb = (long)(bz/nh)*sB1 + (long)(bz%nh)*sB2;
    long cb = (long)(bz/nh)*sC1 + (long)(bz%nh)*sC2;
    int kChunk = K / kSplit;
    int k0 = kIdx * kChunk;
    const int S = kChunk >> 6;

    int wm = wid & 3, wn = wid >> 2;
    float acc[2][8][4] = {};

    auto issue = [&](int s){
        uint32_t dst = sbase + (uint32_t)(s & 1) * MMH_BUFB;
        int kk = k0 + (s << 6);
        #pragma unroll
        for (int i = 0; i < 4; i++){
            int ch = tid + i*256;
            int r = ch >> 3, c8 = ch & 7;
            uint32_t off = (uint32_t)(r*144 + c8*16);
            int gm = row0 + r;
            int sza = (gm < M) ? 16 : 0;
            cpasync16(dst + off, Ah + ab + (long)gm*lda + kk + c8*8, sza);
            if (!aonly)
                cpasync16(dst + MMH_TS*2 + off, Al + ab + (long)gm*lda + kk + c8*8, sza);
            int gn = col0 + r;
            int szb = (gn < N) ? 16 : 0;
            cpasync16(dst + 2*MMH_TS*2 + off, Bh + bb + (long)gn*ldb + kk + c8*8, szb);
            cpasync16(dst + 3*MMH_TS*2 + off, Bl + bb + (long)gn*ldb + kk + c8*8, szb);
        }
        asm volatile("cp.async.commit_group;" ::: "memory");
    };

    issue(0);
    for (int s = 0; s < S; s++){
        if (s + 1 < S){
            issue(s + 1);
            asm volatile("cp.async.wait_group 1;" ::: "memory");
        } else {
            asm volatile("cp.async.wait_group 0;" ::: "memory");
        }
        __syncthreads();
        uint32_t buf = sbase + (uint32_t)(s & 1) * MMH_BUFB;
        uint32_t aH = buf, aL = buf + MMH_TS*2;
        uint32_t bHb = buf + 2*MMH_TS*2, bLb = buf + 3*MMH_TS*2;
        #pragma unroll
        for (int ks = 0; ks < 4; ks++){
            int kc = ks * 16;
            uint32_t ah[2][4], al[2][4];
            #pragma unroll
            for (int mi = 0; mi < 2; mi++){
                int rowb = wm*32 + mi*16 + (lane & 15);
                uint32_t o = (uint32_t)(rowb*144 + kc*2 + (lane >> 4)*16);
                ldmx4(ah[mi], aH + o);
                if (!aonly) ldmx4(al[mi], aL + o);
            }
            #pragma unroll
            for (int nb = 0; nb < 4; nb++){
                int g = lane >> 3;
                int rown = wn*64 + nb*16 + (g >> 1)*8 + (lane & 7);
                uint32_t bo = (uint32_t)(rown*144 + kc*2 + (g & 1)*16);
                uint32_t bh[4], bl[4];
                ldmx4(bh, bHb + bo);
                ldmx4(bl, bLb + bo);
                #pragma unroll
                for (int mi = 0; mi < 2; mi++){
                    #pragma unroll
                    for (int hf = 0; hf < 2; hf++){
                        float* c = acc[mi][nb*2 + hf];
                        mma_bf16(c, ah[mi], bh[hf*2], bh[hf*2+1]);
                        mma_bf16(c, ah[mi], bl[hf*2], bl[hf*2+1]);
                        if (!aonly) mma_bf16(c, al[mi], bh[hf*2], bh[hf*2+1]);
                    }
                }
            }
        }
        __syncthreads();
    }

    int gID = lane >> 2, tig = lane & 3;
    #pragma unroll
    for (int mi = 0; mi < 2; mi++){
        #pragma unroll
        for (int nj = 0; nj < 8; nj++){
            int colb = col0 + wn*64 + nj*8 + tig*2;
            if (colb >= N) continue;
            #pragma unroll
            for (int rh = 0; rh < 2; rh++){
                int gm = row0 + wm*32 + mi*16 + rh*8 + gID;
                if (gm >= M) continue;
                float v0 = acc[mi][nj][rh*2+0]*alpha;
                float v1 = acc[mi][nj][rh*2+1]*alpha;
                long idx = cb + (long)gm*ldc + colb;
                if (flags & FAT){
                    atomicAdd(&Cf[idx], v0);
                    atomicAdd(&Cf[idx+1], v1);
                } else {
                    if (flags & FACC){ v0 += Cf[idx]; v1 += Cf[idx+1]; }
                    if (flags & FR){ v0 = fmaxf(v0,0.f); v1 = fmaxf(v1,0.f); }
                    Cf[idx] = v0; Cf[idx+1] = v1;
                }
                if (flags & FH){
                    hilo_st(v0, Ch, Cl, idx);
                    hilo_st(v1, Ch, Cl, idx+1);
                }
            }
        }
    }
}

// ----------------- HMMA pinv GEMM (proven) -----------------
__global__ void __launch_bounds__(256, 1)
mm_pinv(const __nv_bfloat16* __restrict__ Ah, const __nv_bfloat16* __restrict__ Al,
        const __nv_bfloat16* __restrict__ Bh, const __nv_bfloat16* __restrict__ Bl,
        float* __restrict__ Cf,
        __nv_bfloat16* __restrict__ Xh, __nv_bfloat16* __restrict__ Xl,
        __nv_bfloat16* __restrict__ Yh, __nv_bfloat16* __restrict__ Yl,
        float alpha, float dval, int flags)
{
    extern __shared__ __nv_bfloat16 smb[];
    uint32_t sbase = smem_u32(smb);
    int tid = threadIdx.x, wid = tid >> 5, lane = tid & 31;
    int col0 = blockIdx.x * 128, row0 = blockIdx.y * 128;
    long off = (long)blockIdx.z * PSZ;
    Ah += off; Al += off; Bh += off; Bl += off;

    int wm = wid & 3, wn = wid >> 2;
    float acc[2][8][4] = {};

    auto issue = [&](int s){
        uint32_t dst = sbase + (uint32_t)(s & 1) * MMH_BUFB;
        int k0 = s << 6;
        #pragma unroll
        for (int i = 0; i < 4; i++){
            int ch = tid + i*256;
            int r = ch >> 3, c8 = ch & 7;
            uint32_t o2 = (uint32_t)(r*144 + c8*16);
            cpasync16(dst + o2,              Ah + (long)(row0+r)*256 + k0 + c8*8, 16);
            cpasync16(dst + MMH_TS*2 + o2,   Al + (long)(row0+r)*256 + k0 + c8*8, 16);
            cpasync16(dst + 2*MMH_TS*2 + o2, Bh + (long)(col0+r)*256 + k0 + c8*8, 16);
            cpasync16(dst + 3*MMH_TS*2 + o2, Bl + (long)(col0+r)*256 + k0 + c8*8, 16);
        }
        asm volatile("cp.async.commit_group;" ::: "memory");
    };

    issue(0);
    for (int s = 0; s < 4; s++){
        if (s + 1 < 4){
            issue(s + 1);
            asm volatile("cp.async.wait_group 1;" ::: "memory");
        } else {
            asm volatile("cp.async.wait_group 0;" ::: "memory");
        }
        __syncthreads();
        uint32_t buf = sbase + (uint32_t)(s & 1) * MMH_BUFB;
        uint32_t aH = buf, aL = buf + MMH_TS*2;
        uint32_t bHb = buf + 2*MMH_TS*2, bLb = buf + 3*MMH_TS*2;
        #pragma unroll
        for (int ks = 0; ks < 4; ks++){
            int kc = ks * 16;
            uint32_t ah[2][4], al[2][4];
            #pragma unroll
            for (int mi = 0; mi < 2; mi++){
                int rowb = wm*32 + mi*16 + (lane & 15);
                uint32_t o = (uint32_t)(rowb*144 + kc*2 + (lane >> 4)*16);
                ldmx4(ah[mi], aH + o);
                ldmx4(al[mi], aL + o);
            }
            #pragma unroll
            for (int nb = 0; nb < 4; nb++){
                int g = lane >> 3;
                int rown = wn*64 + nb*16 + (g >> 1)*8 + (lane & 7);
                uint32_t bo = (uint32_t)(rown*144 + kc*2 + (g & 1)*16);
                uint32_t bh[4], bl[4];
                ldmx4(bh, bHb + bo);
                ldmx4(bl, bLb + bo);
                #pragma unroll
                for (int mi = 0; mi < 2; mi++){
                    #pragma unroll
                    for (int hf = 0; hf < 2; hf++){
                        float* c = acc[mi][nb*2 + hf];
                        mma_bf16(c, ah[mi], bh[hf*2], bh[hf*2+1]);
                        mma_bf16(c, ah[mi], bl[hf*2], bl[hf*2+1]);
                        mma_bf16(c, al[mi], bh[hf*2], bh[hf*2+1]);
                    }
                }
            }
        }
        __syncthreads();
    }

    int gID = lane >> 2, tig = lane & 3;
    #pragma unroll
    for (int mi = 0; mi < 2; mi++){
        #pragma unroll
        for (int nj = 0; nj < 8; nj++){
            int cb2 = col0 + wn*64 + nj*8 + tig*2;
            #pragma unroll
            for (int rh = 0; rh < 2; rh++){
                int gm = row0 + wm*32 + mi*16 + rh*8 + gID;
                float v0 = acc[mi][nj][rh*2+0]*alpha;
                float v1 = acc[mi][nj][rh*2+1]*alpha;
                long i0 = off + (long)gm*256 + cb2;
                if (flags & PF_F){ Cf[i0] = v0; Cf[i0+1] = v1; }
                if (flags & PF_A){
                    hilo_st(v0, Xh, Xl, i0);
                    hilo_st(v1, Xh, Xl, i0+1);
                }
                if (flags & (PF_BV|PF_BD)){
                    float w0 = v0, w1 = v1;
                    if (flags & PF_BD){
                        w0 = ((gm==cb2  )?dval:0.f) - v0;
                        w1 = ((gm==cb2+1)?dval:0.f) - v1;
                    }
                    long j0 = off + (long)cb2*256 + gm;
                    hilo_st(w0, Yh, Yl, j0);
                    hilo_st(w1, Yh, Yl, j0+256);
                }
            }
        }
    }
}

// ----------------- conversions -----------------
__global__ void cvt_k(const float* __restrict__ s, __nv_bfloat16* __restrict__ hi,
                      __nv_bfloat16* __restrict__ lo, int n){
    int i = blockIdx.x*256 + threadIdx.x;
    if (i < n){
        float v = s[i];
        __nv_bfloat16 h = __float2bfloat16(v);
        hi[i] = h;
        lo[i] = __float2bfloat16(v - __bfloat162float(h));
    }
}
__global__ void cvtT_k(const float* __restrict__ W, __nv_bfloat16* __restrict__ th,
                       __nv_bfloat16* __restrict__ tl, int K, int N){
    __shared__ float t[32][33];
    int k0 = blockIdx.x*32, n0 = blockIdx.y*32;
    t[threadIdx.y][threadIdx.x] = W[(k0+threadIdx.y)*N + n0+threadIdx.x];
    __syncthreads();
    int n = n0+threadIdx.y, k = k0+threadIdx.x;
    float v = t[threadIdx.x][threadIdx.y];
    __nv_bfloat16 h = __float2bfloat16(v);
    th[(size_t)n*K+k] = h;
    tl[(size_t)n*K+k] = __float2bfloat16(v - __bfloat162float(h));
}
__global__ void vtrans_k(const float* __restrict__ qkv, __nv_bfloat16* __restrict__ VH,
                         __nv_bfloat16* __restrict__ VL){
    __shared__ float tile[32][33];
    int bh=blockIdx.x, b=bh>>3, h=bh&7;
    int t0=blockIdx.y*32, d0=blockIdx.z*32;
    tile[threadIdx.y][threadIdx.x] =
        qkv[((size_t)b*NPAD + t0+threadIdx.y)*QKVD + 1024 + h*64 + d0+threadIdx.x];
    __syncthreads();
    long o = ((size_t)bh*64 + d0+threadIdx.y)*NPAD + t0+threadIdx.x;
    hilo_st(tile[threadIdx.x][threadIdx.y], VH, VL, o);
}
__global__ void pzt_k(const float* __restrict__ pz, __nv_bfloat16* __restrict__ H,
                      __nv_bfloat16* __restrict__ L){
    __shared__ float tile[32][33];
    int bh=blockIdx.x;
    int l0=blockIdx.y*32, d0=blockIdx.z*32;
    tile[threadIdx.y][threadIdx.x] = pz[((size_t)bh*256 + l0+threadIdx.y)*64 + d0+threadIdx.x];
    __syncthreads();
    long o = ((size_t)bh*64 + d0+threadIdx.y)*256 + l0+threadIdx.x;
    hilo_st(tile[threadIdx.x][threadIdx.y], H, L, o);
}

// ----------------- fp32 batched GEMM (pz only) -----------------
template<int BM,int BN,int BK,int TM,int TN,int MAXB>
__global__ void __launch_bounds__((BM/TM)*(BN/TN), MAXB)
gemm_k(const float* __restrict__ A, const float* __restrict__ Bp,
       float* C, float* C2, const float* __restrict__ bias,
       int M,int N,int K,int lda,int ldb,int ldc,
       long sA1,long sA2,long sB1,long sB2,long sC1,long sC2,
       int nh,float alpha,float dval,int nTN,int kSplit,int flags)
{
    constexpr int THREADS=(BM/TM)*(BN/TN);
    constexpr int LA = BM*BK/THREADS;
    constexpr int LB = BK*BN/THREADS;
    __shared__ float As[2][BK][BM];
    __shared__ float Bs[2][BK][BN+1];
    int bz=blockIdx.z;
    A  += (long)(bz/nh)*sA1 + (long)(bz%nh)*sA2;
    Bp += (long)(bz/nh)*sB1 + (long)(bz%nh)*sB2;
    long offC = (long)(bz/nh)*sC1 + (long)(bz%nh)*sC2;
    int kIdx=blockIdx.x/nTN;
    int col0=(blockIdx.x%nTN)*BN;
    int row0=blockIdx.y*BM;
    int kChunk=(K+kSplit-1)/kSplit;
    int k0=kIdx*kChunk, k1=min(K,k0+kChunk);
    int tid=threadIdx.x;
    int tm=tid/(BN/TN), tn=tid%(BN/TN);
    bool trb = (flags & FTRB) != 0;
    float acc[TM][TN] = {};
    float pa[LA], pb[LB];

    auto loadT = [&](int kk){
        #pragma unroll
        for (int it=0; it<LA; it++){
            int i=tid+it*THREADS;
            int m=i/BK, k=i%BK;
            int gm=row0+m, gk=kk+k;
            pa[it] = (gm<M && gk<k1) ? A[(long)gm*lda+gk] : 0.f;
        }
        #pragma unroll
        for (int it=0; it<LB; it++){
            int i=tid+it*THREADS;
            int k,n;
            if (trb){ n=i/BK; k=i%BK; } else { k=i/BN; n=i%BN; }
            int gk=kk+k, gn=col0+n;
            pb[it] = (gk<k1 && gn<N) ? (trb ? Bp[(long)gn*ldb+gk] : Bp[(long)gk*ldb+gn]) : 0.f;
        }
    };
    auto storeT = [&](int b){
        #pragma unroll
        for (int it=0; it<LA; it++){
            int i=tid+it*THREADS;
            int m=i/BK, k=i%BK;
            As[b][k][m]=pa[it];
        }
        #pragma unroll
        for (int it=0; it<LB; it++){
            int i=tid+it*THREADS;
            int k,n;
            if (trb){ n=i/BK; k=i%BK; } else { k=i/BN; n=i%BN; }
            Bs[b][k][n]=pb[it];
        }
    };

    loadT(k0);
    storeT(0);
    __syncthreads();
    int buf=0;
    for (int kk=k0; kk<k1; kk+=BK){
        bool hn = (kk+BK) < k1;
        if (hn) loadT(kk+BK);
        #pragma unroll
        for (int k=0;k<BK;k++){
            float ra[TM], rb[TN];
            #pragma unroll
            for (int i=0;i<TM;i++) ra[i]=As[buf][k][tm*TM+i];
            #pragma unroll
            for (int j=0;j<TN;j++) rb[j]=Bs[buf][k][tn*TN+j];
            #pragma unroll
            for (int i=0;i<TM;i++)
                #pragma unroll
                for (int j=0;j<TN;j++) acc[i][j] += ra[i]*rb[j];
        }
        if (hn) storeT(buf^1);
        __syncthreads();
        buf^=1;
    }
    #pragma unroll
    for (int i=0;i<TM;i++){
        int gm=row0+tm*TM+i; if (gm>=M) continue;
        #pragma unroll
        for (int j=0;j<TN;j++){
            int gn=col0+tn*TN+j; if (gn>=N) continue;
            float v = acc[i][j]*alpha;
            if (flags&FB) v += bias[gn];
            long idx = offC + (long)gm*ldc + gn;
            if (C2) C2[idx] = ((gm==gn)?dval:0.f) - v;
            if (C){
                if (flags&FAT) atomicAdd(&C[idx], v);
                else {
                    float o = v;
                    if (flags&FACC) o += C[idx];
                    if (flags&FR)   o = fmaxf(o, 0.f);
                    C[idx] = o;
                }
            }
        }
    }
}

static void gemm64(const float*A,const float*B,float*C,float*C2,const float*bias,
    int M,int N,int K,int lda,int ldb,int ldc,
    long a1,long a2,long b1,long b2,long c1,long c2,int nh,int batch,
    float alpha,float dval,int kSplit,int flags)
{
    int nTN=(N+63)/64, nTM=(M+63)/64;
    dim3 g(nTN*kSplit, nTM, batch);
    gemm_k<64,64,16,4,4,2><<<g,256>>>(A,B,C,C2,bias,M,N,K,lda,ldb,ldc,
        a1,a2,b1,b2,c1,c2,nh,alpha,dval,nTN,kSplit,flags);
}

// ----------------- elementwise / reduction kernels -----------------
__global__ void set_cls(float* h, const float* __restrict__ cls){
    h[((size_t)blockIdx.x*NPAD + PADF)*DD + threadIdx.x] = cls[threadIdx.x];
}

__global__ void ln_k(const float* __restrict__ h, __nv_bfloat16* __restrict__ oh,
                     __nv_bfloat16* __restrict__ ol,
                     const float* __restrict__ g, const float* __restrict__ b){
    __shared__ float sh[32];
    size_t row = blockIdx.x;
    int t = (int)(row % NPAD);
    __nv_bfloat16* ph = oh + row*(size_t)DD;
    __nv_bfloat16* pl = ol + row*(size_t)DD;
    int tx = threadIdx.x;
    __nv_bfloat16 z = __float2bfloat16(0.f);
    if (t < PADF){ ph[tx]=z; ph[tx+256]=z; pl[tx]=z; pl[tx+256]=z; return; }
    const float* p = h + row*(size_t)DD;
    float x0=p[tx], x1=p[tx+256];
    float mu  = bsum(x0+x1, sh) * (1.f/512.f);
    float d0=x0-mu, d1=x1-mu;
    float var = bsum(d0*d0+d1*d1, sh) * (1.f/512.f);
    float rs = rsqrtf(var + 1e-5f);
    float y0 = d0*rs*g[tx]     + b[tx];
    float y1 = d1*rs*g[tx+256] + b[tx+256];
    __nv_bfloat16 h0 = __float2bfloat16(y0);
    __nv_bfloat16 h1 = __float2bfloat16(y1);
    ph[tx]     = h0; pl[tx]     = __float2bfloat16(y0 - __bfloat162float(h0));
    ph[tx+256] = h1; pl[tx+256] = __float2bfloat16(y1 - __bfloat162float(h1));
}

__global__ void lnf_k(const float* __restrict__ h, float* __restrict__ o,
                      const float* __restrict__ g, const float* __restrict__ b){
    __shared__ float sh[32];
    const float* p = h + ((size_t)blockIdx.x*NPAD + PADF)*DD;
    int tx = threadIdx.x;
    float x0=p[tx], x1=p[tx+256];
    float mu  = bsum(x0+x1, sh) * (1.f/512.f);
    float d0=x0-mu, d1=x1-mu;
    float var = bsum(d0*d0+d1*d1, sh) * (1.f/512.f);
    float rs = rsqrtf(var + 1e-5f);
    o[blockIdx.x*DD+tx]     = d0*rs*g[tx]     + b[tx];
    o[blockIdx.x*DD+tx+256] = d1*rs*g[tx+256] + b[tx+256];
}

__global__ void landmarks_k(const float* __restrict__ qkv,
                            float* __restrict__ ql, float* __restrict__ kl,
                            __nv_bfloat16* qlh, __nv_bfloat16* qll,
                            __nv_bfloat16* klh, __nv_bfloat16* kll){
    int bz=blockIdx.x, m=blockIdx.y, d=threadIdx.x;
    int b=bz>>3, hh=bz&7;
    const float* base = qkv + ((size_t)b*NPAD + (size_t)m*40)*QKVD + hh*64 + d;
    float sq=0.f, sk=0.f;
    #pragma unroll 8
    for (int j=0;j<40;j++){ sq += base[(size_t)j*QKVD]; sk += base[(size_t)j*QKVD+512]; }
    long i = ((size_t)bz*MLAND+m)*64+d;
    float vq = sq*0.003125f, vk = sk*0.025f;
    ql[i]=vq; kl[i]=vk;
    hilo_st(vq, qlh, qll, i);
    hilo_st(vk, klh, kll, i);
}

// softmax rows of 256 -> fp32 + bf16 hilo (for pinv input a2)
__global__ void softmax256(float* __restrict__ X, __nv_bfloat16* __restrict__ Xh,
                           __nv_bfloat16* __restrict__ Xl){
    __shared__ float sh[32];
    float* p = X + (size_t)blockIdx.x*256;
    float v = p[threadIdx.x];
    float m = bmax(v, sh);
    float e = fexp2((v - m)*LOG2E);
    float s = bsum(e, sh);
    float r = e / s;
    p[threadIdx.x] = r;
    long i = (long)blockIdx.x*256 + threadIdx.x;
    hilo_st(r, Xh, Xl, i);
}

// warp-per-row softmax of 256-wide rows -> bf16 probs (lo optional); 8 rows/block
__global__ void softmax256h(const float* __restrict__ X, __nv_bfloat16* __restrict__ H,
                            __nv_bfloat16* __restrict__ L){
    long row = (long)blockIdx.x*8 + (threadIdx.x >> 5);
    int lane = threadIdx.x & 31;
    const float4* p = (const float4*)(X + row*256);
    float4 v0 = p[lane], v1 = p[lane+32];
    float m = fmaxf(fmaxf(fmaxf(v0.x,v0.y), fmaxf(v0.z,v0.w)),
                    fmaxf(fmaxf(v1.x,v1.y), fmaxf(v1.z,v1.w)));
    #pragma unroll
    for (int o=16;o;o>>=1) m = fmaxf(m, __shfl_xor_sync(0xffffffffu, m, o));
    float e[8];
    e[0]=fexp2((v0.x-m)*LOG2E); e[1]=fexp2((v0.y-m)*LOG2E);
    e[2]=fexp2((v0.z-m)*LOG2E); e[3]=fexp2((v0.w-m)*LOG2E);
    e[4]=fexp2((v1.x-m)*LOG2E); e[5]=fexp2((v1.y-m)*LOG2E);
    e[6]=fexp2((v1.z-m)*LOG2E); e[7]=fexp2((v1.w-m)*LOG2E);
    float s = (e[0]+e[1])+(e[2]+e[3])+(e[4]+e[5])+(e[6]+e[7]);
    #pragma unroll
    for (int o=16;o;o>>=1) s += __shfl_xor_sync(0xffffffffu, s, o);
    float inv = 1.f/s;
    long b0 = row*256 + lane*4;
    #pragma unroll
    for (int j=0;j<4;j++) prob_st(e[j]*inv,   H, L, b0+j);
    #pragma unroll
    for (int j=0;j<4;j++) prob_st(e[4+j]*inv, H, L, b0+128+j);
}

// softmax rows of NPAD -> bf16 probs (lo optional); register-cached
__global__ void softmaxN_h(const float* __restrict__ X, __nv_bfloat16* __restrict__ H,
                           __nv_bfloat16* __restrict__ L){
    __shared__ float sh[32];
    const float* p = X + (size_t)blockIdx.x*NPAD;
    int tx = threadIdx.x;
    float r[40];
    float m = -FLT_MAX;
    #pragma unroll
    for (int i=0;i<40;i++){ r[i]=p[tx+i*256]; m = fmaxf(m, r[i]); }
    m = bmax(m, sh);
    float s = 0.f;
    #pragma unroll
    for (int i=0;i<40;i++){ r[i]=fexp2((r[i]-m)*LOG2E); s += r[i]; }
    s = bsum(s, sh);
    float inv = 1.f/s;
    size_t base = (size_t)blockIdx.x*NPAD + tx;
    #pragma unroll
    for (int i=0;i<40;i++) prob_st(r[i]*inv, H, L, base + i*256);
}

__global__ void zerok(float* p, int n){
    int i = blockIdx.x*256 + threadIdx.x;
    if (i<n) p[i]=0.f;
}

__global__ void crmax_k(const float* __restrict__ a2, float* mx){
    __shared__ float sh[32];
    const float* p = a2 + (size_t)blockIdx.x*65536;
    int t = threadIdx.x;
    float cs=0.f, rs=0.f;
    for (int m=0;m<256;m++){ cs += p[m*256+t]; rs += p[t*256+m]; }
    float mc = bmax(cs, sh);
    float mr = bmax(rs, sh);
    if (t==0){
        atomicMax((int*)&mx[0], __float_as_int(mc));
        atomicMax((int*)&mx[1], __float_as_int(mr));
    }
}

__global__ void ztrans_k(const float* __restrict__ a2, const float* __restrict__ mx,
                         __nv_bfloat16* __restrict__ zAh, __nv_bfloat16* __restrict__ zAl,
                         __nv_bfloat16* __restrict__ zBh, __nv_bfloat16* __restrict__ zBl){
    __shared__ float tile[32][33];
    int bz=blockIdx.x;
    const float* p = a2 + (size_t)bz*65536;
    int i0=blockIdx.y*32, j0=blockIdx.z*32;
    tile[threadIdx.y][threadIdx.x] = p[(j0+threadIdx.y)*256 + i0+threadIdx.x];
    __syncthreads();
    float inv = 1.f/(mx[0]*mx[1]);
    long off = (long)bz*PSZ;
    float za = tile[threadIdx.x][threadIdx.y]*inv;
    hilo_st(za, zAh, zAl, off + (long)(i0+threadIdx.y)*256 + (j0+threadIdx.x));
    float zb = tile[threadIdx.y][threadIdx.x]*inv;
    hilo_st(zb, zBh, zBl, off + (long)(j0+threadIdx.y)*256 + (i0+threadIdx.x));
}

__global__ void resconv_k(const float* __restrict__ qkv, const float* __restrict__ rw,
                          float* __restrict__ mg){
    __shared__ float w[33];
    int bz=blockIdx.y; int b=bz>>3, hh=bz&7;
    if (threadIdx.y==0 && threadIdx.x<33) w[threadIdx.x]=rw[hh*33+threadIdx.x];
    __syncthreads();
    int d=threadIdx.x;
    int t=blockIdx.x*8+threadIdx.y;
    const float* vb = qkv + (size_t)b*NPAD*QKVD + 1024 + hh*64 + d;
    float acc=0.f;
    #pragma unroll
    for (int j=0;j<33;j++){
        int ts=t+j-16;
        if (ts>=0 && ts<NPAD) acc += vb[(size_t)ts*QKVD]*w[j];
    }
    mg[((size_t)b*NPAD+t)*DD + hh*64 + d] += acc;
}

__global__ void t2p_k(const float* __restrict__ h, float* __restrict__ pl){
    __shared__ float tile[32][33];
    int b=blockIdx.x, t0=blockIdx.y*32, c0=blockIdx.z*32;
    int t=t0+threadIdx.y, c=c0+threadIdx.x;
    if (t<10000) tile[threadIdx.y][threadIdx.x] = h[((size_t)b*NPAD+PADF+1+t)*DD + c];
    __syncthreads();
    int ch=c0+threadIdx.y, tt=t0+threadIdx.x;
    if (tt<10000) pl[((size_t)b*DD+ch)*10000 + tt] = tile[threadIdx.x][threadIdx.y];
}
__global__ void p2h_k(const float* __restrict__ pl, float* __restrict__ h){
    __shared__ float tile[32][33];
    int b=blockIdx.x, t0=blockIdx.y*32, c0=blockIdx.z*32;
    int ch=c0+threadIdx.y, tt=t0+threadIdx.x;
    if (tt<10000) tile[threadIdx.y][threadIdx.x] = pl[((size_t)b*DD+ch)*10000 + tt];
    __syncthreads();
    int t=t0+threadIdx.y, c=c0+threadIdx.x;
    if (t<10000) h[((size_t)b*NPAD+PADF+1+t)*DD + c] = tile[threadIdx.x][threadIdx.y];
}

__global__ void ppeg_conv_k(const float* __restrict__ pl, float* __restrict__ po,
    const float* __restrict__ w7, const float* __restrict__ b7,
    const float* __restrict__ w5, const float* __restrict__ b5,
    const float* __restrict__ w3, const float* __restrict__ b3){
    __shared__ float sw[86];
    int plane=blockIdx.x; int ch=plane&511;
    int tx=threadIdx.x;
    if      (tx<49) sw[tx]=w7[ch*49+tx];
    else if (tx<74) sw[tx]=w5[ch*25+tx-49];
    else if (tx<83) sw[tx]=w3[ch*9+tx-74];
    else if (tx==83) sw[83]=b7[ch];
    else if (tx==84) sw[84]=b5[ch];
    else if (tx==85) sw[85]=b3[ch];
    __syncthreads();
    int px=blockIdx.y*256+tx;
    if (px>=10000) return;
    int r=px/100, c=px%100;
    const float* in = pl + (size_t)plane*10000;
    float acc = in[px] + sw[83] + sw[84] + sw[85];
    #pragma unroll
    for (int kr=0;kr<7;kr++){
        int rr=r+kr-3; if (rr<0||rr>=100) continue;
        #pragma unroll
        for (int kc=0;kc<7;kc++){
            int cc=c+kc-3; if (cc<0||cc>=100) continue;
            acc += in[rr*100+cc]*sw[kr*7+kc];
        }
    }
    #pragma unroll
    for (int kr=0;kr<5;kr++){
        int rr=r+kr-2; if (rr<0||rr>=100) continue;
        #pragma unroll
        for (int kc=0;kc<5;kc++){
            int cc=c+kc-2; if (cc<0||cc>=100) continue;
            acc += in[rr*100+cc]*sw[49+kr*5+kc];
        }
    }
    #pragma unroll
    for (int kr=0;kr<3;kr++){
        int rr=r+kr-1; if (rr<0||rr>=100) continue;
        #pragma unroll
        for (int kc=0;kc<3;kc++){
            int cc=c+kc-1; if (cc<0||cc>=100) continue;
            acc += in[rr*100+cc]*sw[74+kr*3+kc];
        }
    }
    po[(size_t)plane*10000+px]=acc;
}

__global__ void head_k(const float* __restrict__ cls, const float* __restrict__ w2,
                       const float* __restrict__ b2, float* out, int osz){
    __shared__ float sh[64];
    int b=blockIdx.x;
    float a0=0.f, a1=0.f;
    for (int d=threadIdx.x; d<512; d+=256){
        float x = cls[b*512+d];
        a0 += x*w2[d*2+0]; a1 += x*w2[d*2+1];
    }
    #pragma unroll
    for (int o=16;o;o>>=1){
        a0 += __shfl_xor_sync(0xffffffffu,a0,o);
        a1 += __shfl_xor_sync(0xffffffffu,a1,o);
    }
    int lane=threadIdx.x&31, wid=threadIdx.x>>5;
    if (lane==0){ sh[wid]=a0; sh[wid+32]=a1; }
    __syncthreads();
    if (threadIdx.x==0){
        float l0=b2[0], l1=b2[1];
        for (int w=0;w<8;w++){ l0+=sh[w]; l1+=sh[w+32]; }
        float m=fmaxf(l0,l1);
        float e0=expf(l0-m), e1=expf(l1-m), s=e0+e1;
        if (b*2+1   < osz){ out[b*2]=l0;      out[b*2+1]=l1; }
        if (4+b*2+1 < osz){ out[4+b*2]=e0/s;  out[4+b*2+1]=e1/s; }
        if (8+b     < osz){ out[8+b] = (l1>l0)?1.f:0.f; }
    }
}

// ----------------- driver -----------------
extern "C" void kernel_launch(void* const* d_in, const int* in_sizes, int n_in,
                              void* d_out, int out_size){
    const float* x    =(const float*)d_in[0];
    const float* wfc1 =(const float*)d_in[1];
    const float* bfc1 =(const float*)d_in[2];
    const float* clst =(const float*)d_in[3];
    const float* lng[2]={(const float*)d_in[4],(const float*)d_in[10]};
    const float* lnb[2]={(const float*)d_in[5],(const float*)d_in[11]};
    const float* qkvw[2]={(const float*)d_in[6],(const float*)d_in[12]};
    const float* outw[2]={(const float*)d_in[7],(const float*)d_in[13]};
    const float* outb[2]={(const float*)d_in[8],(const float*)d_in[14]};
    const float* resw[2]={(const float*)d_in[9],(const float*)d_in[15]};
    const float* pw7=(const float*)d_in[16]; const float* pb7=(const float*)d_in[17];
    const float* pw5=(const float*)d_in[18]; const float* pb5=(const float*)d_in[19];
    const float* pw3=(const float*)d_in[20]; const float* pb3=(const float*)d_in[21];
    const float* lnfg=(const float*)d_in[22]; const float* lnfb=(const float*)d_in[23];
    const float* wfc2=(const float*)d_in[24]; const float* bfc2=(const float*)d_in[25];

    float *h,*qkv,*ql,*kl,*s1,*s3,*a2,*zf,*a3v,*pz,*mg,*mx;
    __nv_bfloat16 *xh,*xl,*lnh,*lnl,*mgh,*mgl,*wth,*wtl;
    __nv_bfloat16 *qkvh,*qkvl,*a1h,*a3h,*vth,*vtl;
    __nv_bfloat16 *qlh,*qll,*klh,*kll,*pzth,*pztl;
    __nv_bfloat16 *pa2h,*pa2l,*pxzh,*pxzl,*pwbh,*pwbl,*ptbh,*ptbl;
    __nv_bfloat16 *pzah[2],*pzal[2],*pzbh[2],*pzbl[2];
    cudaGetSymbolAddress((void**)&h,  g_h);
    cudaGetSymbolAddress((void**)&qkv,g_qkv);
    cudaGetSymbolAddress((void**)&ql, g_ql);
    cudaGetSymbolAddress((void**)&kl, g_kl);
    cudaGetSymbolAddress((void**)&s1, g_s1);
    cudaGetSymbolAddress((void**)&s3, g_s3);
    cudaGetSymbolAddress((void**)&a2, g_a2);
    cudaGetSymbolAddress((void**)&zf, g_z0);
    cudaGetSymbolAddress((void**)&a3v,g_a3v);
    cudaGetSymbolAddress((void**)&pz, g_pz);
    cudaGetSymbolAddress((void**)&mg, g_mg);
    cudaGetSymbolAddress((void**)&mx, g_mx);
    cudaGetSymbolAddress((void**)&xh, g_xh);
    cudaGetSymbolAddress((void**)&xl, g_xl);
    cudaGetSymbolAddress((void**)&lnh,g_lnh);
    cudaGetSymbolAddress((void**)&lnl,g_lnl);
    cudaGetSymbolAddress((void**)&mgh,g_mgh);
    cudaGetSymbolAddress((void**)&mgl,g_mgl);
    cudaGetSymbolAddress((void**)&wth,g_wth);
    cudaGetSymbolAddress((void**)&wtl,g_wtl);
    cudaGetSymbolAddress((void**)&qkvh,g_qkvh);
    cudaGetSymbolAddress((void**)&qkvl,g_qkvl);
    cudaGetSymbolAddress((void**)&a1h,g_a1h);
    cudaGetSymbolAddress((void**)&a3h,g_a3h);
    cudaGetSymbolAddress((void**)&vth,g_vth);
    cudaGetSymbolAddress((void**)&vtl,g_vtl);
    cudaGetSymbolAddress((void**)&qlh,g_qlh);
    cudaGetSymbolAddress((void**)&qll,g_qll);
    cudaGetSymbolAddress((void**)&klh,g_klh);
    cudaGetSymbolAddress((void**)&kll,g_kll);
    cudaGetSymbolAddress((void**)&pzth,g_pzth);
    cudaGetSymbolAddress((void**)&pztl,g_pztl);
    cudaGetSymbolAddress((void**)&pa2h,g_pa2h);  cudaGetSymbolAddress((void**)&pa2l,g_pa2l);
    cudaGetSymbolAddress((void**)&pxzh,g_pxzh);  cudaGetSymbolAddress((void**)&pxzl,g_pxzl);
    cudaGetSymbolAddress((void**)&pwbh,g_pwbh);  cudaGetSymbolAddress((void**)&pwbl,g_pwbl);
    cudaGetSymbolAddress((void**)&ptbh,g_ptbh);  cudaGetSymbolAddress((void**)&ptbl,g_ptbl);
    cudaGetSymbolAddress((void**)&pzah[0],g_pzah0); cudaGetSymbolAddress((void**)&pzal[0],g_pzal0);
    cudaGetSymbolAddress((void**)&pzbh[0],g_pzbh0); cudaGetSymbolAddress((void**)&pzbl[0],g_pzbl0);
    cudaGetSymbolAddress((void**)&pzah[1],g_pzah1); cudaGetSymbolAddress((void**)&pzal[1],g_pzal1);
    cudaGetSymbolAddress((void**)&pzbh[1],g_pzbh1); cudaGetSymbolAddress((void**)&pzbl[1],g_pzbl1);

    cudaFuncSetAttribute(mm_hmma, cudaFuncAttributeMaxDynamicSharedMemorySize, MMH_SMEM);
    cudaFuncSetAttribute(mm_g,    cudaFuncAttributeMaxDynamicSharedMemorySize, MMH_SMEM);
    cudaFuncSetAttribute(mm_pinv, cudaFuncAttributeMaxDynamicSharedMemorySize, MMH_SMEM);

    // fc1 (HMMA)
    {
        int n = NB*10000*DIN;
        cvt_k<<<(n+255)/256,256>>>(x, xh, xl, n);
        cvtT_k<<<dim3(DIN/32, DD/32), dim3(32,32)>>>(wfc1, wth, wtl, DIN, DD);
        mm_hmma<<<dim3(4,79,NB),256,MMH_SMEM>>>(xh, xl, wth, wtl,
            h+(size_t)(PADF+1)*DD, bfc1, 10000, DIN, DD,
            (long)10000*DIN, (long)NPAD*DD, FB|FR);
    }
    set_cls<<<NB,512>>>(h, clst);

    for (int L=0; L<2; L++){
        ln_k<<<NB*NPAD,256>>>(h, lnh, lnl, lng[L], lnb[L]);
        // qkv (HMMA) + hilo emit
        cvtT_k<<<dim3(DD/32, QKVD/32), dim3(32,32)>>>(qkvw[L], wth, wtl, DD, QKVD);
        mm_g<<<dim3(12,160,1),256,MMH_SMEM>>>(lnh, lnl, wth, wtl,
            qkv, qkvh, qkvl,
            NB*NPAD, QKVD, DD, DD, DD, QKVD,
            0L,0L, 0L,0L, 0L,0L, 1, 160, 1.f, 1, FH);
        landmarks_k<<<dim3(BH,MLAND),64>>>(qkv, ql, kl, qlh,qll, klh,kll);
        // s2 = ql @ kl^T (HMMA, S=1, small smem) -> a2 fp32, then softmax + hilo
        mm_g<<<dim3(2,2,BH),256,MMH_BUFB>>>(qlh, qll, klh, kll,
            a2, nullptr, nullptr,
            256, 256, 64, 64, 64, 256,
            (long)MLAND*64, 0L, (long)MLAND*64, 0L, (long)PSZ, 0L,
            1, 2, 1.f, 1, 0);
        softmax256<<<BH*256,256>>>(a2, pa2h, pa2l);
        // s3 = ql @ k^T (HMMA, S=1, small smem)
        mm_g<<<dim3(80,2,BH),256,MMH_BUFB>>>(qlh, qll, qkvh+512, qkvl+512,
            s3, nullptr, nullptr,
            256, NPAD, 64, 64, QKVD, NPAD,
            8L*MLAND*64, (long)MLAND*64,
            (long)NPAD*QKVD, 64L,
            8L*MLAND*NPAD, (long)MLAND*NPAD,
            8, 2, 1.f, 1, 0);
        softmaxN_h<<<BH*256,256>>>(s3, a3h, nullptr);
        vtrans_k<<<dim3(BH,320,2),dim3(32,32)>>>(qkv, vth, vtl);
        // a3v = a3 @ v (split-K=8 atomic HMMA, A bf16-only)
        zerok<<<(BH*256*64+255)/256,256>>>(a3v, BH*256*64);
        mm_g<<<dim3(1,2*8,BH),256,MMH_SMEM>>>(a3h, nullptr, vth, vtl,
            a3v, nullptr, nullptr,
            256, 64, NPAD, NPAD, NPAD, 64,
            (long)MLAND*NPAD, 0L, 64L*NPAD, 0L, 16384L, 0L,
            1, 2, 1.f, 8, FAT);
        // pinv chain (HMMA)
        zerok<<<1,256>>>(mx, 2);
        crmax_k<<<BH,256>>>(a2, mx);
        ztrans_k<<<dim3(BH,8,8),dim3(32,32)>>>(a2, mx, pzah[0],pzal[0], pzbh[0],pzbl[0]);
        int c = 0;
        dim3 pg(2,2,BH);
        for (int it=0; it<6; it++){
            mm_pinv<<<pg,256,MMH_SMEM>>>(pa2h,pa2l, pzbh[c],pzbl[c], nullptr,
                pxzh,pxzl, pwbh,pwbl, 1.f, 7.f, PF_A|PF_BD);
            mm_pinv<<<pg,256,MMH_SMEM>>>(pxzh,pxzl, pwbh,pwbl, nullptr,
                nullptr,nullptr, ptbh,ptbl, 1.f, 15.f, PF_BD);
            mm_pinv<<<pg,256,MMH_SMEM>>>(pxzh,pxzl, ptbh,ptbl, nullptr,
                nullptr,nullptr, pwbh,pwbl, 1.f, 13.f, PF_BD);
            mm_pinv<<<pg,256,MMH_SMEM>>>(pzah[c],pzal[c], pwbh,pwbl, zf,
                pzah[1-c],pzal[1-c], pzbh[1-c],pzbl[1-c], 0.25f, 0.f, PF_F|PF_A|PF_BV);
            c ^= 1;
        }
        // pz = pinv(a2) @ a3v ; then transpose to B-layout hilo
        gemm64(zf, a3v, pz, nullptr, nullptr,
               256, 64, 256, 256, 64, 64,
               65536,0, 16384,0, 16384,0, 1, BH, 1.f, 0.f, 1, 0);
        pzt_k<<<dim3(BH,8,2),dim3(32,32)>>>(pz, pzth, pztl);
        // s1 = q @ kl^T (HMMA, alpha=0.125, S=1, small smem)
        mm_g<<<dim3(2,80,BH),256,MMH_BUFB>>>(qkvh, qkvl, klh, kll,
            s1, nullptr, nullptr,
            NPAD, 256, 64, QKVD, 64, 256,
            (long)NPAD*QKVD, 64L,
            8L*MLAND*64, (long)MLAND*64,
            8L*NPAD*MLAND, (long)NPAD*MLAND,
            8, 80, 0.125f, 1, 0);
        softmax256h<<<BH*NPAD/8,256>>>(s1, a1h, nullptr);
        // mg = a1 @ pz (HMMA, A bf16-only)
        mm_g<<<dim3(1,80,BH),256,MMH_SMEM>>>(a1h, nullptr, pzth, pztl,
            mg, nullptr, nullptr,
            NPAD, 64, 256, 256, 256, DD,
            8L*NPAD*MLAND, (long)NPAD*MLAND,
            8L*64*MLAND, 64L*MLAND,
            (long)NPAD*DD, 64L,
            8, 80, 1.f, 1, 0);
        resconv_k<<<dim3(NPAD/8,BH),dim3(64,8)>>>(qkv, resw[L], mg);
        // out-proj (HMMA): h += mg @ w_out + b_out
        {
            int n = NB*NPAD*DD;
            cvt_k<<<(n+255)/256,256>>>(mg, mgh, mgl, n);
            cvtT_k<<<dim3(DD/32, DD/32), dim3(32,32)>>>(outw[L], wth, wtl, DD, DD);
            mm_hmma<<<dim3(4,79,NB),256,MMH_SMEM>>>(
                mgh+(size_t)PADF*DD, mgl+(size_t)PADF*DD, wth, wtl,
                h+(size_t)PADF*DD, outb[L], 10001, DD, DD,
                (long)NPAD*DD, (long)NPAD*DD, FB|FACC);
        }
        if (L==0){
            t2p_k<<<dim3(NB,313,16),dim3(32,32)>>>(h, s1);
            ppeg_conv_k<<<dim3(NB*512,40),256>>>(s1, s3, pw7,pb7, pw5,pb5, pw3,pb3);
            p2h_k<<<dim3(NB,313,16),dim3(32,32)>>>(s3, h);
        }
    }
    lnf_k<<<NB,256>>>(h, a2, lnfg, lnfb);
    head_k<<<NB,256>>>(a2, wfc2, bfc2, (float*)d_out, out_size);
}